// round 1
// baseline (speedup 1.0000x reference)
#include <cuda_runtime.h>
#include <math.h>

#define BQ  4
#define SEQ 1024
#define DM  1024
#define NH  16
#define HD  64

// ---- scratch (no allocations allowed) ----
__device__ float g_qp[BQ * SEQ * DM];
__device__ float g_kp[BQ * SEQ * DM];
__device__ float g_vp[BQ * SEQ * DM];
__device__ float g_ctx[BQ * SEQ * DM];
__device__ float g_attn[BQ * NH * SEQ * SEQ];  // fallback if attn not an output

__device__ __forceinline__ float* sel_buf(int s, float* ext) {
    switch (s) {
        case 0: return g_qp;
        case 1: return g_kp;
        case 2: return g_vp;
        case 3: return g_ctx;
        default: return ext;
    }
}

// C[m][n] = sum_k A[m][k] * W[n][k]  (+bias), M=4096, N=K=1024
__global__ __launch_bounds__(256) void gemm_xwt(
    const float* __restrict__ Aext, int a_sel,
    const float* __restrict__ W,
    const float* __restrict__ bias,
    float* __restrict__ Cext, int c_sel)
{
    const int K = DM, N = DM;
    const float* A = (a_sel < 4) ? sel_buf(a_sel, nullptr) : Aext;
    float* C = sel_buf(c_sel, Cext);

    __shared__ float As[16][64];
    __shared__ float Ws[16][64];

    int tid = threadIdx.x;
    int tx = tid & 15, ty = tid >> 4;
    int m0 = blockIdx.y * 64, n0 = blockIdx.x * 64;

    int lrow = tid >> 2;
    int lk = (tid & 3) * 4;
    const float* Ap = A + (size_t)(m0 + lrow) * K + lk;
    const float* Wp = W + (size_t)(n0 + lrow) * K + lk;

    float acc[4][4] = {};

    for (int k0 = 0; k0 < K; k0 += 16) {
        float4 av = *(const float4*)(Ap + k0);
        float4 wv = *(const float4*)(Wp + k0);
        As[lk + 0][lrow] = av.x; As[lk + 1][lrow] = av.y;
        As[lk + 2][lrow] = av.z; As[lk + 3][lrow] = av.w;
        Ws[lk + 0][lrow] = wv.x; Ws[lk + 1][lrow] = wv.y;
        Ws[lk + 2][lrow] = wv.z; Ws[lk + 3][lrow] = wv.w;
        __syncthreads();
        #pragma unroll
        for (int kk = 0; kk < 16; kk++) {
            float a[4], w[4];
            #pragma unroll
            for (int i = 0; i < 4; i++) a[i] = As[kk][ty * 4 + i];
            #pragma unroll
            for (int j = 0; j < 4; j++) w[j] = Ws[kk][tx * 4 + j];
            #pragma unroll
            for (int i = 0; i < 4; i++)
                #pragma unroll
                for (int j = 0; j < 4; j++)
                    acc[i][j] = fmaf(a[i], w[j], acc[i][j]);
        }
        __syncthreads();
    }

    #pragma unroll
    for (int i = 0; i < 4; i++) {
        int gm = m0 + ty * 4 + i;
        #pragma unroll
        for (int j = 0; j < 4; j++) {
            int gn = n0 + tx * 4 + j;
            float v = acc[i][j];
            if (bias) v += bias[gn];
            C[(size_t)gm * N + gn] = v;
        }
    }
}

// scores[bh][m][n] = (Q_h[m,:] . K_h[n,:]) / 32 + mask*(-1e9)
__global__ __launch_bounds__(256) void scores_kernel(
    const int* __restrict__ mask, float* __restrict__ attn_ext)
{
    float* attn = attn_ext ? attn_ext : g_attn;
    __shared__ float Qs[HD][64];
    __shared__ float Ks[HD][64];

    int bh = blockIdx.z, b = bh >> 4, h = bh & 15;
    int m0 = blockIdx.y * 64, n0 = blockIdx.x * 64;
    const float* Q  = g_qp + (size_t)b * SEQ * DM + h * HD;
    const float* Kp = g_kp + (size_t)b * SEQ * DM + h * HD;

    int tid = threadIdx.x;
    int tx = tid & 15, ty = tid >> 4;

    #pragma unroll
    for (int it = 0; it < 4; it++) {
        int e = tid + it * 256;
        int row = e >> 4, c4 = (e & 15) * 4;
        float4 qv = *(const float4*)(Q + (size_t)(m0 + row) * DM + c4);
        Qs[c4 + 0][row] = qv.x; Qs[c4 + 1][row] = qv.y;
        Qs[c4 + 2][row] = qv.z; Qs[c4 + 3][row] = qv.w;
        float4 kv = *(const float4*)(Kp + (size_t)(n0 + row) * DM + c4);
        Ks[c4 + 0][row] = kv.x; Ks[c4 + 1][row] = kv.y;
        Ks[c4 + 2][row] = kv.z; Ks[c4 + 3][row] = kv.w;
    }
    __syncthreads();

    float acc[4][4] = {};
    #pragma unroll
    for (int kk = 0; kk < HD; kk++) {
        float a[4], w[4];
        #pragma unroll
        for (int i = 0; i < 4; i++) a[i] = Qs[kk][ty * 4 + i];
        #pragma unroll
        for (int j = 0; j < 4; j++) w[j] = Ks[kk][tx * 4 + j];
        #pragma unroll
        for (int i = 0; i < 4; i++)
            #pragma unroll
            for (int j = 0; j < 4; j++)
                acc[i][j] = fmaf(a[i], w[j], acc[i][j]);
    }

    const float scale = 0.03125f;  // 1/sqrt(1024)
    #pragma unroll
    for (int i = 0; i < 4; i++) {
        int gm = m0 + ty * 4 + i;
        #pragma unroll
        for (int j = 0; j < 4; j++) {
            int gn = n0 + tx * 4 + j;
            float s = acc[i][j] * scale
                    + (float)mask[(size_t)b * SEQ * SEQ + (size_t)gm * SEQ + gn] * -1e9f;
            attn[((size_t)bh * SEQ + gm) * SEQ + gn] = s;
        }
    }
}

// in-place row softmax, one block per row (length 1024)
__global__ __launch_bounds__(256) void softmax_kernel(float* __restrict__ attn_ext)
{
    float* attn = attn_ext ? attn_ext : g_attn;
    float* p = attn + (size_t)blockIdx.x * SEQ;
    int tid = threadIdx.x;

    float4 x = ((const float4*)p)[tid];
    float m = fmaxf(fmaxf(x.x, x.y), fmaxf(x.z, x.w));

    __shared__ float red[8];
    #pragma unroll
    for (int o = 16; o; o >>= 1) m = fmaxf(m, __shfl_xor_sync(0xffffffffu, m, o));
    if ((tid & 31) == 0) red[tid >> 5] = m;
    __syncthreads();
    m = red[0];
    #pragma unroll
    for (int i = 1; i < 8; i++) m = fmaxf(m, red[i]);

    float4 e;
    e.x = __expf(x.x - m); e.y = __expf(x.y - m);
    e.z = __expf(x.z - m); e.w = __expf(x.w - m);
    float s = (e.x + e.y) + (e.z + e.w);

    __syncthreads();
    #pragma unroll
    for (int o = 16; o; o >>= 1) s += __shfl_xor_sync(0xffffffffu, s, o);
    if ((tid & 31) == 0) red[tid >> 5] = s;
    __syncthreads();
    s = 0.0f;
    #pragma unroll
    for (int i = 0; i < 8; i++) s += red[i];

    float inv = __frcp_rn(s);
    e.x *= inv; e.y *= inv; e.z *= inv; e.w *= inv;
    ((float4*)p)[tid] = e;
}

// ctx_h[m][n] = sum_k attn[bh][m][k] * V_h[k][n], N=64
__global__ __launch_bounds__(256) void ctx_kernel(const float* __restrict__ attn_ext)
{
    const float* attn = attn_ext ? attn_ext : g_attn;
    __shared__ float As[32][64];
    __shared__ float Vs[32][64];

    int bh = blockIdx.y, b = bh >> 4, h = bh & 15;
    int m0 = blockIdx.x * 64;
    int tid = threadIdx.x;
    int tx = tid & 15, ty = tid >> 4;

    const float* Ab = attn + ((size_t)bh * SEQ + m0) * SEQ;
    const float* Vb = g_vp + (size_t)b * SEQ * DM + h * HD;

    float acc[4][4] = {};

    for (int k0 = 0; k0 < SEQ; k0 += 32) {
        #pragma unroll
        for (int it = 0; it < 2; it++) {
            int e = tid + it * 256;
            int row = e >> 3, c4 = (e & 7) * 4;
            float4 av = *(const float4*)(Ab + (size_t)row * SEQ + k0 + c4);
            As[c4 + 0][row] = av.x; As[c4 + 1][row] = av.y;
            As[c4 + 2][row] = av.z; As[c4 + 3][row] = av.w;
            int vrow = e >> 4, vc4 = (e & 15) * 4;
            float4 vv = *(const float4*)(Vb + (size_t)(k0 + vrow) * DM + vc4);
            *(float4*)&Vs[vrow][vc4] = vv;
        }
        __syncthreads();
        #pragma unroll
        for (int kk = 0; kk < 32; kk++) {
            float a[4], w[4];
            #pragma unroll
            for (int i = 0; i < 4; i++) a[i] = As[kk][ty * 4 + i];
            #pragma unroll
            for (int j = 0; j < 4; j++) w[j] = Vs[kk][tx * 4 + j];
            #pragma unroll
            for (int i = 0; i < 4; i++)
                #pragma unroll
                for (int j = 0; j < 4; j++)
                    acc[i][j] = fmaf(a[i], w[j], acc[i][j]);
        }
        __syncthreads();
    }

    float* Cb = g_ctx + (size_t)b * SEQ * DM + h * HD;
    #pragma unroll
    for (int i = 0; i < 4; i++)
        #pragma unroll
        for (int j = 0; j < 4; j++)
            Cb[(size_t)(m0 + ty * 4 + i) * DM + tx * 4 + j] = acc[i][j];
}

extern "C" void kernel_launch(void* const* d_in, const int* in_sizes, int n_in,
                              void* d_out, int out_size)
{
    const float* q   = (const float*)d_in[0];
    const float* k   = (const float*)d_in[1];
    const float* v   = (const float*)d_in[2];
    const int*  mask = (const int*)d_in[3];
    const float* Wq  = (const float*)d_in[4];
    const float* Wk  = (const float*)d_in[5];
    const float* Wv  = (const float*)d_in[6];
    const float* Wd  = (const float*)d_in[7];
    const float* bd  = (const float*)d_in[8];
    float* out = (float*)d_out;

    const long long out_elems  = (long long)BQ * SEQ * DM;           // 4M
    const long long attn_elems = (long long)BQ * NH * SEQ * SEQ;     // 64M
    float* attn_ext = ((long long)out_size >= out_elems + attn_elems)
                          ? out + out_elems : nullptr;

    dim3 gg(DM / 64, (BQ * SEQ) / 64);                  // 16 x 64
    gemm_xwt<<<gg, 256>>>(q, 4, Wq, nullptr, nullptr, 0);
    gemm_xwt<<<gg, 256>>>(k, 4, Wk, nullptr, nullptr, 1);
    gemm_xwt<<<gg, 256>>>(v, 4, Wv, nullptr, nullptr, 2);

    dim3 gs(SEQ / 64, SEQ / 64, BQ * NH);               // 16 x 16 x 64
    scores_kernel<<<gs, 256>>>(mask, attn_ext);
    softmax_kernel<<<BQ * NH * SEQ, 256>>>(attn_ext);
    ctx_kernel<<<dim3(SEQ / 64, BQ * NH), 256>>>(attn_ext);

    gemm_xwt<<<gg, 256>>>(nullptr, 3, Wd, bd, out, 4);
}

// round 2
// speedup vs baseline: 1.3212x; 1.3212x over previous
#include <cuda_runtime.h>
#include <math.h>

#define BQ  4
#define SEQ 1024
#define DM  1024
#define NH  16
#define HD  64

// ---- scratch (no allocations allowed) ----
__device__ float g_qp[BQ * SEQ * DM];
__device__ float g_kp[BQ * SEQ * DM];
__device__ float g_vp[BQ * SEQ * DM];
__device__ float g_ctx[BQ * SEQ * DM];
__device__ float g_attn[BQ * NH * SEQ * SEQ];  // fallback if attn not an output

__device__ __forceinline__ float* sel_buf(int s, float* ext) {
    switch (s) {
        case 0: return g_qp;
        case 1: return g_kp;
        case 2: return g_vp;
        case 3: return g_ctx;
        default: return ext;
    }
}

// ---------------------------------------------------------------------------
// C[m][n] = sum_k A[m][k] * W[n][k]  (+bias). M=4096, N=K=1024.
// 128x128 tile, 256 threads, 8x8 per thread, BK=16, LDS.128 inner loop.
// ---------------------------------------------------------------------------
__global__ __launch_bounds__(256) void gemm_xwt(
    const float* __restrict__ Aext, int a_sel,
    const float* __restrict__ W,
    const float* __restrict__ bias,
    float* __restrict__ Cext, int c_sel)
{
    const int K = DM, N = DM;
    const float* A = (a_sel < 4) ? sel_buf(a_sel, nullptr) : Aext;
    float* C = sel_buf(c_sel, Cext);

    __shared__ float As[16][128];
    __shared__ float Ws[16][128];

    int tid = threadIdx.x;
    int tx = tid & 15, ty = tid >> 4;
    int m0 = blockIdx.y * 128, n0 = blockIdx.x * 128;

    int lr = tid >> 2;          // 0..63
    int lk = (tid & 3) * 4;     // 0,4,8,12
    const float* Ap0 = A + (size_t)(m0 + lr) * K + lk;
    const float* Ap1 = Ap0 + (size_t)64 * K;
    const float* Wp0 = W + (size_t)(n0 + lr) * K + lk;
    const float* Wp1 = Wp0 + (size_t)64 * K;

    float acc[8][8] = {};

    for (int k0 = 0; k0 < K; k0 += 16) {
        float4 a0 = *(const float4*)(Ap0 + k0);
        float4 a1 = *(const float4*)(Ap1 + k0);
        float4 w0 = *(const float4*)(Wp0 + k0);
        float4 w1 = *(const float4*)(Wp1 + k0);
        __syncthreads();
        As[lk + 0][lr] = a0.x; As[lk + 1][lr] = a0.y;
        As[lk + 2][lr] = a0.z; As[lk + 3][lr] = a0.w;
        As[lk + 0][lr + 64] = a1.x; As[lk + 1][lr + 64] = a1.y;
        As[lk + 2][lr + 64] = a1.z; As[lk + 3][lr + 64] = a1.w;
        Ws[lk + 0][lr] = w0.x; Ws[lk + 1][lr] = w0.y;
        Ws[lk + 2][lr] = w0.z; Ws[lk + 3][lr] = w0.w;
        Ws[lk + 0][lr + 64] = w1.x; Ws[lk + 1][lr + 64] = w1.y;
        Ws[lk + 2][lr + 64] = w1.z; Ws[lk + 3][lr + 64] = w1.w;
        __syncthreads();
        #pragma unroll
        for (int kk = 0; kk < 16; kk++) {
            float a[8], b[8];
            *(float4*)&a[0] = *(const float4*)&As[kk][ty * 8];
            *(float4*)&a[4] = *(const float4*)&As[kk][ty * 8 + 4];
            *(float4*)&b[0] = *(const float4*)&Ws[kk][tx * 8];
            *(float4*)&b[4] = *(const float4*)&Ws[kk][tx * 8 + 4];
            #pragma unroll
            for (int i = 0; i < 8; i++)
                #pragma unroll
                for (int j = 0; j < 8; j++)
                    acc[i][j] = fmaf(a[i], b[j], acc[i][j]);
        }
    }

    float bb[8];
    #pragma unroll
    for (int j = 0; j < 8; j++) bb[j] = bias ? bias[n0 + tx * 8 + j] : 0.0f;

    #pragma unroll
    for (int i = 0; i < 8; i++) {
        int gm = m0 + ty * 8 + i;
        float4 v0, v1;
        v0.x = acc[i][0] + bb[0]; v0.y = acc[i][1] + bb[1];
        v0.z = acc[i][2] + bb[2]; v0.w = acc[i][3] + bb[3];
        v1.x = acc[i][4] + bb[4]; v1.y = acc[i][5] + bb[5];
        v1.z = acc[i][6] + bb[6]; v1.w = acc[i][7] + bb[7];
        *(float4*)&C[(size_t)gm * N + n0 + tx * 8]     = v0;
        *(float4*)&C[(size_t)gm * N + n0 + tx * 8 + 4] = v1;
    }
}

// ---------------------------------------------------------------------------
// scores[bh][m][n] = (Q_h[m,:] . K_h[n,:]) * (1/32) + mask*(-1e9)
// 128x128 tile, K=64 in 4 chunks of 16, 8x8 per thread.
// ---------------------------------------------------------------------------
__global__ __launch_bounds__(256) void scores_kernel(
    const int* __restrict__ mask, float* __restrict__ attn_ext)
{
    float* attn = attn_ext ? attn_ext : g_attn;
    __shared__ float Qs[16][128];
    __shared__ float Ks[16][128];

    int bh = blockIdx.z, b = bh >> 4, h = bh & 15;
    int m0 = blockIdx.y * 128, n0 = blockIdx.x * 128;
    const float* Q  = g_qp + (size_t)b * SEQ * DM + h * HD;
    const float* Kp = g_kp + (size_t)b * SEQ * DM + h * HD;

    int tid = threadIdx.x;
    int tx = tid & 15, ty = tid >> 4;
    int lr = tid >> 2;
    int lk = (tid & 3) * 4;

    const float* Qp0 = Q + (size_t)(m0 + lr) * DM + lk;
    const float* Qp1 = Qp0 + (size_t)64 * DM;
    const float* Kp0 = Kp + (size_t)(n0 + lr) * DM + lk;
    const float* Kp1 = Kp0 + (size_t)64 * DM;

    float acc[8][8] = {};

    for (int k0 = 0; k0 < HD; k0 += 16) {
        float4 a0 = *(const float4*)(Qp0 + k0);
        float4 a1 = *(const float4*)(Qp1 + k0);
        float4 w0 = *(const float4*)(Kp0 + k0);
        float4 w1 = *(const float4*)(Kp1 + k0);
        __syncthreads();
        Qs[lk + 0][lr] = a0.x; Qs[lk + 1][lr] = a0.y;
        Qs[lk + 2][lr] = a0.z; Qs[lk + 3][lr] = a0.w;
        Qs[lk + 0][lr + 64] = a1.x; Qs[lk + 1][lr + 64] = a1.y;
        Qs[lk + 2][lr + 64] = a1.z; Qs[lk + 3][lr + 64] = a1.w;
        Ks[lk + 0][lr] = w0.x; Ks[lk + 1][lr] = w0.y;
        Ks[lk + 2][lr] = w0.z; Ks[lk + 3][lr] = w0.w;
        Ks[lk + 0][lr + 64] = w1.x; Ks[lk + 1][lr + 64] = w1.y;
        Ks[lk + 2][lr + 64] = w1.z; Ks[lk + 3][lr + 64] = w1.w;
        __syncthreads();
        #pragma unroll
        for (int kk = 0; kk < 16; kk++) {
            float a[8], b2[8];
            *(float4*)&a[0]  = *(const float4*)&Qs[kk][ty * 8];
            *(float4*)&a[4]  = *(const float4*)&Qs[kk][ty * 8 + 4];
            *(float4*)&b2[0] = *(const float4*)&Ks[kk][tx * 8];
            *(float4*)&b2[4] = *(const float4*)&Ks[kk][tx * 8 + 4];
            #pragma unroll
            for (int i = 0; i < 8; i++)
                #pragma unroll
                for (int j = 0; j < 8; j++)
                    acc[i][j] = fmaf(a[i], b2[j], acc[i][j]);
        }
    }

    const float scale = 0.03125f;  // 1/sqrt(1024)
    #pragma unroll
    for (int i = 0; i < 8; i++) {
        int gm = m0 + ty * 8 + i;
        const int* mrow = mask + (size_t)b * SEQ * SEQ + (size_t)gm * SEQ + n0 + tx * 8;
        int4 mi0 = *(const int4*)mrow;
        int4 mi1 = *(const int4*)(mrow + 4);
        float4 v0, v1;
        v0.x = acc[i][0] * scale + (float)mi0.x * -1e9f;
        v0.y = acc[i][1] * scale + (float)mi0.y * -1e9f;
        v0.z = acc[i][2] * scale + (float)mi0.z * -1e9f;
        v0.w = acc[i][3] * scale + (float)mi0.w * -1e9f;
        v1.x = acc[i][4] * scale + (float)mi1.x * -1e9f;
        v1.y = acc[i][5] * scale + (float)mi1.y * -1e9f;
        v1.z = acc[i][6] * scale + (float)mi1.z * -1e9f;
        v1.w = acc[i][7] * scale + (float)mi1.w * -1e9f;
        float* arow = attn + ((size_t)bh * SEQ + gm) * SEQ + n0 + tx * 8;
        *(float4*)arow       = v0;
        *(float4*)(arow + 4) = v1;
    }
}

// in-place row softmax, one block per row (length 1024)
__global__ __launch_bounds__(256) void softmax_kernel(float* __restrict__ attn_ext)
{
    float* attn = attn_ext ? attn_ext : g_attn;
    float* p = attn + (size_t)blockIdx.x * SEQ;
    int tid = threadIdx.x;

    float4 x = ((const float4*)p)[tid];
    float m = fmaxf(fmaxf(x.x, x.y), fmaxf(x.z, x.w));

    __shared__ float red[8];
    #pragma unroll
    for (int o = 16; o; o >>= 1) m = fmaxf(m, __shfl_xor_sync(0xffffffffu, m, o));
    if ((tid & 31) == 0) red[tid >> 5] = m;
    __syncthreads();
    m = red[0];
    #pragma unroll
    for (int i = 1; i < 8; i++) m = fmaxf(m, red[i]);

    float4 e;
    e.x = __expf(x.x - m); e.y = __expf(x.y - m);
    e.z = __expf(x.z - m); e.w = __expf(x.w - m);
    float s = (e.x + e.y) + (e.z + e.w);

    __syncthreads();
    #pragma unroll
    for (int o = 16; o; o >>= 1) s += __shfl_xor_sync(0xffffffffu, s, o);
    if ((tid & 31) == 0) red[tid >> 5] = s;
    __syncthreads();
    s = 0.0f;
    #pragma unroll
    for (int i = 0; i < 8; i++) s += red[i];

    float inv = __frcp_rn(s);
    e.x *= inv; e.y *= inv; e.z *= inv; e.w *= inv;
    ((float4*)p)[tid] = e;
}

// ---------------------------------------------------------------------------
// ctx_h[m][n] = sum_k attn[bh][m][k] * V_h[k][n]. M-tile 128, N=64, BK=32.
// 256 threads (16x16), 8x4 per thread.
// ---------------------------------------------------------------------------
__global__ __launch_bounds__(256) void ctx_kernel(const float* __restrict__ attn_ext)
{
    const float* attn = attn_ext ? attn_ext : g_attn;
    __shared__ float As2[32][128];
    __shared__ float Vs[32][64];

    int bh = blockIdx.y, b = bh >> 4, h = bh & 15;
    int m0 = blockIdx.x * 128;
    int tid = threadIdx.x;
    int tx = tid & 15, ty = tid >> 4;

    const float* Ab = attn + ((size_t)bh * SEQ + m0) * SEQ;
    const float* Vb = g_vp + (size_t)b * SEQ * DM + h * HD;

    int lr8 = tid >> 3;         // 0..31
    int lk8 = (tid & 7) * 4;    // 0..28
    int vrow = tid >> 4;        // 0..15
    int vc4 = (tid & 15) * 4;   // 0..60

    float acc[8][4] = {};

    for (int k0 = 0; k0 < SEQ; k0 += 32) {
        float4 av[4];
        #pragma unroll
        for (int it = 0; it < 4; it++)
            av[it] = *(const float4*)(Ab + (size_t)(lr8 + 32 * it) * SEQ + k0 + lk8);
        float4 vv0 = *(const float4*)(Vb + (size_t)(k0 + vrow) * DM + vc4);
        float4 vv1 = *(const float4*)(Vb + (size_t)(k0 + vrow + 16) * DM + vc4);
        __syncthreads();
        #pragma unroll
        for (int it = 0; it < 4; it++) {
            int r = lr8 + 32 * it;
            As2[lk8 + 0][r] = av[it].x; As2[lk8 + 1][r] = av[it].y;
            As2[lk8 + 2][r] = av[it].z; As2[lk8 + 3][r] = av[it].w;
        }
        *(float4*)&Vs[vrow][vc4]      = vv0;
        *(float4*)&Vs[vrow + 16][vc4] = vv1;
        __syncthreads();
        #pragma unroll
        for (int kk = 0; kk < 32; kk++) {
            float a[8], b2[4];
            *(float4*)&a[0]  = *(const float4*)&As2[kk][ty * 8];
            *(float4*)&a[4]  = *(const float4*)&As2[kk][ty * 8 + 4];
            *(float4*)&b2[0] = *(const float4*)&Vs[kk][tx * 4];
            #pragma unroll
            for (int i = 0; i < 8; i++)
                #pragma unroll
                for (int j = 0; j < 4; j++)
                    acc[i][j] = fmaf(a[i], b2[j], acc[i][j]);
        }
    }

    float* Cb = g_ctx + (size_t)b * SEQ * DM + h * HD;
    #pragma unroll
    for (int i = 0; i < 8; i++) {
        float4 v;
        v.x = acc[i][0]; v.y = acc[i][1]; v.z = acc[i][2]; v.w = acc[i][3];
        *(float4*)&Cb[(size_t)(m0 + ty * 8 + i) * DM + tx * 4] = v;
    }
}

extern "C" void kernel_launch(void* const* d_in, const int* in_sizes, int n_in,
                              void* d_out, int out_size)
{
    const float* q   = (const float*)d_in[0];
    const float* k   = (const float*)d_in[1];
    const float* v   = (const float*)d_in[2];
    const int*  mask = (const int*)d_in[3];
    const float* Wq  = (const float*)d_in[4];
    const float* Wk  = (const float*)d_in[5];
    const float* Wv  = (const float*)d_in[6];
    const float* Wd  = (const float*)d_in[7];
    const float* bd  = (const float*)d_in[8];
    float* out = (float*)d_out;

    const long long out_elems  = (long long)BQ * SEQ * DM;           // 4M
    const long long attn_elems = (long long)BQ * NH * SEQ * SEQ;     // 64M
    float* attn_ext = ((long long)out_size >= out_elems + attn_elems)
                          ? out + out_elems : nullptr;

    dim3 gg(DM / 128, (BQ * SEQ) / 128);                // 8 x 32
    gemm_xwt<<<gg, 256>>>(q, 4, Wq, nullptr, nullptr, 0);
    gemm_xwt<<<gg, 256>>>(k, 4, Wk, nullptr, nullptr, 1);
    gemm_xwt<<<gg, 256>>>(v, 4, Wv, nullptr, nullptr, 2);

    dim3 gs(SEQ / 128, SEQ / 128, BQ * NH);             // 8 x 8 x 64
    scores_kernel<<<gs, 256>>>(mask, attn_ext);
    softmax_kernel<<<BQ * NH * SEQ, 256>>>(attn_ext);
    ctx_kernel<<<dim3(SEQ / 128, BQ * NH), 256>>>(attn_ext);

    gemm_xwt<<<gg, 256>>>(nullptr, 3, Wd, bd, out, 4);
}

// round 4
// speedup vs baseline: 1.6837x; 1.2744x over previous
#include <cuda_runtime.h>
#include <cuda_bf16.h>
#include <stdint.h>
#include <math.h>

#define BQ  4
#define SEQ 1024
#define DM  1024
#define NH  16
#define HD  64

// ---------------- scratch (no allocations allowed) ----------------
__device__ float g_qp[BQ * SEQ * DM];
__device__ float g_kp[BQ * SEQ * DM];
__device__ float g_vp[BQ * SEQ * DM];
__device__ float g_ctx[BQ * SEQ * DM];
__device__ float g_attn[BQ * NH * SEQ * SEQ];  // fallback if attn not an output

// bf16 split copies
__device__ __nv_bfloat16 g_q_hi[BQ * SEQ * DM],  g_q_lo[BQ * SEQ * DM];
__device__ __nv_bfloat16 g_k_hi[BQ * SEQ * DM],  g_k_lo[BQ * SEQ * DM];
__device__ __nv_bfloat16 g_v_hi[BQ * SEQ * DM],  g_v_lo[BQ * SEQ * DM];
__device__ __nv_bfloat16 g_c_hi[BQ * SEQ * DM],  g_c_lo[BQ * SEQ * DM];
__device__ __nv_bfloat16 g_wq_hi[DM * DM], g_wq_lo[DM * DM];
__device__ __nv_bfloat16 g_wk_hi[DM * DM], g_wk_lo[DM * DM];
__device__ __nv_bfloat16 g_wv_hi[DM * DM], g_wv_lo[DM * DM];
__device__ __nv_bfloat16 g_wd_hi[DM * DM], g_wd_lo[DM * DM];

#define SMEM_SWIZZLE_128B(o) ((o) ^ (((o) >> 3) & 0x70))

__device__ __forceinline__ uint32_t smem_u32(const void* p) {
    uint32_t a;
    asm("{ .reg .u64 t; cvta.to.shared.u64 t, %1; cvt.u32.u64 %0, t; }" : "=r"(a) : "l"(p));
    return a;
}
__device__ __forceinline__ void ldm_x4(uint32_t* r, uint32_t addr) {
    asm volatile("ldmatrix.sync.aligned.m8n8.x4.shared.b16 {%0,%1,%2,%3}, [%4];"
        : "=r"(r[0]), "=r"(r[1]), "=r"(r[2]), "=r"(r[3]) : "r"(addr));
}
__device__ __forceinline__ void mma_bf16(float* d, const uint32_t* a, const uint32_t* b) {
    asm volatile(
        "mma.sync.aligned.m16n8k16.row.col.f32.bf16.bf16.f32 "
        "{%0,%1,%2,%3}, {%4,%5,%6,%7}, {%8,%9}, {%0,%1,%2,%3};"
        : "+f"(d[0]), "+f"(d[1]), "+f"(d[2]), "+f"(d[3])
        : "r"(a[0]), "r"(a[1]), "r"(a[2]), "r"(a[3]), "r"(b[0]), "r"(b[1]));
}

// ---------------------------------------------------------------------------
// fp32 -> (bf16 hi, bf16 lo) split. grid*256*4 == n.
// ---------------------------------------------------------------------------
__global__ __launch_bounds__(256) void convert_split(
    const float* __restrict__ x,
    __nv_bfloat16* __restrict__ hi, __nv_bfloat16* __restrict__ lo)
{
    int i = blockIdx.x * 256 + threadIdx.x;
    float4 v = ((const float4*)x)[i];
    __nv_bfloat16 h0 = __float2bfloat16_rn(v.x);
    __nv_bfloat16 h1 = __float2bfloat16_rn(v.y);
    __nv_bfloat16 h2 = __float2bfloat16_rn(v.z);
    __nv_bfloat16 h3 = __float2bfloat16_rn(v.w);
    __nv_bfloat16 l0 = __float2bfloat16_rn(v.x - __bfloat162float(h0));
    __nv_bfloat16 l1 = __float2bfloat16_rn(v.y - __bfloat162float(h1));
    __nv_bfloat16 l2 = __float2bfloat16_rn(v.z - __bfloat162float(h2));
    __nv_bfloat16 l3 = __float2bfloat16_rn(v.w - __bfloat162float(h3));
    __nv_bfloat162* hp = (__nv_bfloat162*)(hi + (size_t)i * 4);
    __nv_bfloat162* lp = (__nv_bfloat162*)(lo + (size_t)i * 4);
    hp[0] = __nv_bfloat162(h0, h1); hp[1] = __nv_bfloat162(h2, h3);
    lp[0] = __nv_bfloat162(l0, l1); lp[1] = __nv_bfloat162(l2, l3);
}

// ---------------------------------------------------------------------------
// mma.sync bf16 GEMM: C[m][n] = sum_k A[m][k]*W[n][k] (+bias), fp32 out.
// 3-term split: Ahi*Whi + Alo*Whi + Ahi*Wlo.
// CTA 128x128, 8 warps (warp tile 64x32), BK=64, SW128 smem.
// ---------------------------------------------------------------------------
#define MMA_SMEM_BYTES (4 * 16384)

__global__ __launch_bounds__(256) void mma_gemm(
    const __nv_bfloat16* __restrict__ Ahi, const __nv_bfloat16* __restrict__ Alo,
    const __nv_bfloat16* __restrict__ Whi, const __nv_bfloat16* __restrict__ Wlo,
    const float* __restrict__ bias, float* __restrict__ C)
{
    extern __shared__ char sm[];
    const int K = DM, N = DM;
    const uint32_t O_AHI = 0, O_ALO = 16384, O_WHI = 32768, O_WLO = 49152;

    int tid = threadIdx.x, w = tid >> 5, l = tid & 31;
    int m0 = blockIdx.y * 128, n0 = blockIdx.x * 128;
    int wm = w & 1, wn = w >> 1;            // warp tile: (wm*64, wn*32)

    uint32_t sb = smem_u32(sm);

    // ldmatrix lane addressing (within buffer; byte units)
    int a_row = wm * 64 + (l & 15);
    int a_k2  = ((l >> 4) * 8) * 2;          // byte offset of k within row
    int b_row = wn * 32 + (l & 7) + ((l >> 4) * 8);
    int b_k2  = (((l >> 3) & 1) * 8) * 2;

    float acc[4][4][4] = {};

    int lrow = tid >> 3;       // 0..31 (advances 32 per iteration)
    int lc   = tid & 7;        // 16B chunk in row

    for (int kc = 0; kc < K; kc += 64) {
        __syncthreads();
        #pragma unroll
        for (int it = 0; it < 4; it++) {
            int row = lrow + it * 32;
            size_t ga = (size_t)(m0 + row) * K + kc + lc * 8;
            size_t gw = (size_t)(n0 + row) * K + kc + lc * 8;
            uint32_t so = SMEM_SWIZZLE_128B(row * 128 + lc * 16);
            *(uint4*)(sm + O_AHI + so) = *(const uint4*)(Ahi + ga);
            *(uint4*)(sm + O_ALO + so) = *(const uint4*)(Alo + ga);
            *(uint4*)(sm + O_WHI + so) = *(const uint4*)(Whi + gw);
            *(uint4*)(sm + O_WLO + so) = *(const uint4*)(Wlo + gw);
        }
        __syncthreads();

        #pragma unroll
        for (int kk = 0; kk < 4; kk++) {
            int ks2 = kk * 32;   // 16 bf16 = 32 bytes
            uint32_t ah[4][4], al[4][4], bw[2][4];
            #pragma unroll
            for (int mf = 0; mf < 4; mf++) {
                uint32_t off = SMEM_SWIZZLE_128B((a_row + mf * 16) * 128 + ks2 + a_k2);
                ldm_x4(ah[mf], sb + O_AHI + off);
                ldm_x4(al[mf], sb + O_ALO + off);
            }
            #pragma unroll
            for (int bp = 0; bp < 2; bp++) {
                uint32_t off = SMEM_SWIZZLE_128B((b_row + bp * 16) * 128 + ks2 + b_k2);
                ldm_x4(bw[bp], sb + O_WHI + off);
            }
            #pragma unroll
            for (int mf = 0; mf < 4; mf++)
                #pragma unroll
                for (int nf = 0; nf < 4; nf++)
                    mma_bf16(acc[mf][nf], ah[mf], &bw[nf >> 1][(nf & 1) * 2]);
            #pragma unroll
            for (int mf = 0; mf < 4; mf++)
                #pragma unroll
                for (int nf = 0; nf < 4; nf++)
                    mma_bf16(acc[mf][nf], al[mf], &bw[nf >> 1][(nf & 1) * 2]);
            #pragma unroll
            for (int bp = 0; bp < 2; bp++) {
                uint32_t off = SMEM_SWIZZLE_128B((b_row + bp * 16) * 128 + ks2 + b_k2);
                ldm_x4(bw[bp], sb + O_WLO + off);
            }
            #pragma unroll
            for (int mf = 0; mf < 4; mf++)
                #pragma unroll
                for (int nf = 0; nf < 4; nf++)
                    mma_bf16(acc[mf][nf], ah[mf], &bw[nf >> 1][(nf & 1) * 2]);
        }
    }

    int er = l >> 2, ec = (l & 3) * 2;
    #pragma unroll
    for (int mf = 0; mf < 4; mf++) {
        #pragma unroll
        for (int nf = 0; nf < 4; nf++) {
            int gm = m0 + wm * 64 + mf * 16 + er;
            int gn = n0 + wn * 32 + nf * 8 + ec;
            float b0 = bias ? bias[gn] : 0.0f;
            float b1 = bias ? bias[gn + 1] : 0.0f;
            float2 v0, v1;
            v0.x = acc[mf][nf][0] + b0; v0.y = acc[mf][nf][1] + b1;
            v1.x = acc[mf][nf][2] + b0; v1.y = acc[mf][nf][3] + b1;
            *(float2*)&C[(size_t)gm * N + gn]       = v0;
            *(float2*)&C[(size_t)(gm + 8) * N + gn] = v1;
        }
    }
}

// ---------------------------------------------------------------------------
// scores[bh][m][n] = (Q_h[m,:] . K_h[n,:]) * (1/32) + mask*(-1e9)   (FFMA)
// ---------------------------------------------------------------------------
__global__ __launch_bounds__(256) void scores_kernel(
    const int* __restrict__ mask, float* __restrict__ attn_ext)
{
    float* attn = attn_ext ? attn_ext : g_attn;
    __shared__ float Qs[16][128];
    __shared__ float Ks[16][128];

    int bh = blockIdx.z, b = bh >> 4, h = bh & 15;
    int m0 = blockIdx.y * 128, n0 = blockIdx.x * 128;
    const float* Q  = g_qp + (size_t)b * SEQ * DM + h * HD;
    const float* Kp = g_kp + (size_t)b * SEQ * DM + h * HD;

    int tid = threadIdx.x;
    int tx = tid & 15, ty = tid >> 4;
    int lr = tid >> 2;
    int lk = (tid & 3) * 4;

    const float* Qp0 = Q + (size_t)(m0 + lr) * DM + lk;
    const float* Qp1 = Qp0 + (size_t)64 * DM;
    const float* Kp0 = Kp + (size_t)(n0 + lr) * DM + lk;
    const float* Kp1 = Kp0 + (size_t)64 * DM;

    float acc[8][8] = {};

    for (int k0 = 0; k0 < HD; k0 += 16) {
        float4 a0 = *(const float4*)(Qp0 + k0);
        float4 a1 = *(const float4*)(Qp1 + k0);
        float4 w0 = *(const float4*)(Kp0 + k0);
        float4 w1 = *(const float4*)(Kp1 + k0);
        __syncthreads();
        Qs[lk + 0][lr] = a0.x; Qs[lk + 1][lr] = a0.y;
        Qs[lk + 2][lr] = a0.z; Qs[lk + 3][lr] = a0.w;
        Qs[lk + 0][lr + 64] = a1.x; Qs[lk + 1][lr + 64] = a1.y;
        Qs[lk + 2][lr + 64] = a1.z; Qs[lk + 3][lr + 64] = a1.w;
        Ks[lk + 0][lr] = w0.x; Ks[lk + 1][lr] = w0.y;
        Ks[lk + 2][lr] = w0.z; Ks[lk + 3][lr] = w0.w;
        Ks[lk + 0][lr + 64] = w1.x; Ks[lk + 1][lr + 64] = w1.y;
        Ks[lk + 2][lr + 64] = w1.z; Ks[lk + 3][lr + 64] = w1.w;
        __syncthreads();
        #pragma unroll
        for (int kk = 0; kk < 16; kk++) {
            float a[8], b2[8];
            *(float4*)&a[0]  = *(const float4*)&Qs[kk][ty * 8];
            *(float4*)&a[4]  = *(const float4*)&Qs[kk][ty * 8 + 4];
            *(float4*)&b2[0] = *(const float4*)&Ks[kk][tx * 8];
            *(float4*)&b2[4] = *(const float4*)&Ks[kk][tx * 8 + 4];
            #pragma unroll
            for (int i = 0; i < 8; i++)
                #pragma unroll
                for (int j = 0; j < 8; j++)
                    acc[i][j] = fmaf(a[i], b2[j], acc[i][j]);
        }
    }

    const float scale = 0.03125f;
    #pragma unroll
    for (int i = 0; i < 8; i++) {
        int gm = m0 + ty * 8 + i;
        const int* mrow = mask + (size_t)b * SEQ * SEQ + (size_t)gm * SEQ + n0 + tx * 8;
        int4 mi0 = *(const int4*)mrow;
        int4 mi1 = *(const int4*)(mrow + 4);
        float4 v0, v1;
        v0.x = acc[i][0] * scale + (float)mi0.x * -1e9f;
        v0.y = acc[i][1] * scale + (float)mi0.y * -1e9f;
        v0.z = acc[i][2] * scale + (float)mi0.z * -1e9f;
        v0.w = acc[i][3] * scale + (float)mi0.w * -1e9f;
        v1.x = acc[i][4] * scale + (float)mi1.x * -1e9f;
        v1.y = acc[i][5] * scale + (float)mi1.y * -1e9f;
        v1.z = acc[i][6] * scale + (float)mi1.z * -1e9f;
        v1.w = acc[i][7] * scale + (float)mi1.w * -1e9f;
        float* arow = attn + ((size_t)bh * SEQ + gm) * SEQ + n0 + tx * 8;
        *(float4*)arow       = v0;
        *(float4*)(arow + 4) = v1;
    }
}

// in-place row softmax, one block per row (length 1024)
__global__ __launch_bounds__(256) void softmax_kernel(float* __restrict__ attn_ext)
{
    float* attn = attn_ext ? attn_ext : g_attn;
    float* p = attn + (size_t)blockIdx.x * SEQ;
    int tid = threadIdx.x;

    float4 x = ((const float4*)p)[tid];
    float m = fmaxf(fmaxf(x.x, x.y), fmaxf(x.z, x.w));

    __shared__ float red[8];
    #pragma unroll
    for (int o = 16; o; o >>= 1) m = fmaxf(m, __shfl_xor_sync(0xffffffffu, m, o));
    if ((tid & 31) == 0) red[tid >> 5] = m;
    __syncthreads();
    m = red[0];
    #pragma unroll
    for (int i = 1; i < 8; i++) m = fmaxf(m, red[i]);

    float4 e;
    e.x = __expf(x.x - m); e.y = __expf(x.y - m);
    e.z = __expf(x.z - m); e.w = __expf(x.w - m);
    float s = (e.x + e.y) + (e.z + e.w);

    __syncthreads();
    #pragma unroll
    for (int o = 16; o; o >>= 1) s += __shfl_xor_sync(0xffffffffu, s, o);
    if ((tid & 31) == 0) red[tid >> 5] = s;
    __syncthreads();
    s = 0.0f;
    #pragma unroll
    for (int i = 0; i < 8; i++) s += red[i];

    float inv = __frcp_rn(s);
    e.x *= inv; e.y *= inv; e.z *= inv; e.w *= inv;
    ((float4*)p)[tid] = e;
}

// ---------------------------------------------------------------------------
// ctx_h[m][n] = sum_k attn[bh][m][k] * V_h[k][n]   (FFMA)
// ---------------------------------------------------------------------------
__global__ __launch_bounds__(256) void ctx_kernel(const float* __restrict__ attn_ext)
{
    const float* attn = attn_ext ? attn_ext : g_attn;
    __shared__ float As2[32][128];
    __shared__ float Vs[32][64];

    int bh = blockIdx.y, b = bh >> 4, h = bh & 15;
    int m0 = blockIdx.x * 128;
    int tid = threadIdx.x;
    int tx = tid & 15, ty = tid >> 4;

    const float* Ab = attn + ((size_t)bh * SEQ + m0) * SEQ;
    const float* Vb = g_vp + (size_t)b * SEQ * DM + h * HD;

    int lr8 = tid >> 3;
    int lk8 = (tid & 7) * 4;
    int vrow = tid >> 4;
    int vc4 = (tid & 15) * 4;

    float acc[8][4] = {};

    for (int k0 = 0; k0 < SEQ; k0 += 32) {
        float4 av[4];
        #pragma unroll
        for (int it = 0; it < 4; it++)
            av[it] = *(const float4*)(Ab + (size_t)(lr8 + 32 * it) * SEQ + k0 + lk8);
        float4 vv0 = *(const float4*)(Vb + (size_t)(k0 + vrow) * DM + vc4);
        float4 vv1 = *(const float4*)(Vb + (size_t)(k0 + vrow + 16) * DM + vc4);
        __syncthreads();
        #pragma unroll
        for (int it = 0; it < 4; it++) {
            int r = lr8 + 32 * it;
            As2[lk8 + 0][r] = av[it].x; As2[lk8 + 1][r] = av[it].y;
            As2[lk8 + 2][r] = av[it].z; As2[lk8 + 3][r] = av[it].w;
        }
        *(float4*)&Vs[vrow][vc4]      = vv0;
        *(float4*)&Vs[vrow + 16][vc4] = vv1;
        __syncthreads();
        #pragma unroll
        for (int kk = 0; kk < 32; kk++) {
            float a[8], b2[4];
            *(float4*)&a[0]  = *(const float4*)&As2[kk][ty * 8];
            *(float4*)&a[4]  = *(const float4*)&As2[kk][ty * 8 + 4];
            *(float4*)&b2[0] = *(const float4*)&Vs[kk][tx * 4];
            #pragma unroll
            for (int i = 0; i < 8; i++)
                #pragma unroll
                for (int j = 0; j < 4; j++)
                    acc[i][j] = fmaf(a[i], b2[j], acc[i][j]);
        }
    }

    float* Cb = g_ctx + (size_t)b * SEQ * DM + h * HD;
    #pragma unroll
    for (int i = 0; i < 8; i++) {
        float4 v;
        v.x = acc[i][0]; v.y = acc[i][1]; v.z = acc[i][2]; v.w = acc[i][3];
        *(float4*)&Cb[(size_t)(m0 + ty * 8 + i) * DM + tx * 4] = v;
    }
}

// ---------------------------------------------------------------------------
extern "C" void kernel_launch(void* const* d_in, const int* in_sizes, int n_in,
                              void* d_out, int out_size)
{
    const float* q   = (const float*)d_in[0];
    const float* k   = (const float*)d_in[1];
    const float* v   = (const float*)d_in[2];
    const int*  mask = (const int*)d_in[3];
    const float* Wq  = (const float*)d_in[4];
    const float* Wk  = (const float*)d_in[5];
    const float* Wv  = (const float*)d_in[6];
    const float* Wd  = (const float*)d_in[7];
    const float* bd  = (const float*)d_in[8];
    float* out = (float*)d_out;

    const long long out_elems  = (long long)BQ * SEQ * DM;           // 4M
    const long long attn_elems = (long long)BQ * NH * SEQ * SEQ;     // 64M
    float* attn_ext = ((long long)out_size >= out_elems + attn_elems)
                          ? out + out_elems : nullptr;

    cudaFuncSetAttribute(mma_gemm, cudaFuncAttributeMaxDynamicSharedMemorySize,
                         MMA_SMEM_BYTES);

    __nv_bfloat16 *qh, *ql, *kh, *kl, *vh, *vl, *ch, *cl;
    __nv_bfloat16 *wqh, *wql, *wkh, *wkl, *wvh, *wvl, *wdh, *wdl;
    float *qp, *kp, *vp, *ctx;
    cudaGetSymbolAddress((void**)&qh, g_q_hi);  cudaGetSymbolAddress((void**)&ql, g_q_lo);
    cudaGetSymbolAddress((void**)&kh, g_k_hi);  cudaGetSymbolAddress((void**)&kl, g_k_lo);
    cudaGetSymbolAddress((void**)&vh, g_v_hi);  cudaGetSymbolAddress((void**)&vl, g_v_lo);
    cudaGetSymbolAddress((void**)&ch, g_c_hi);  cudaGetSymbolAddress((void**)&cl, g_c_lo);
    cudaGetSymbolAddress((void**)&wqh, g_wq_hi); cudaGetSymbolAddress((void**)&wql, g_wq_lo);
    cudaGetSymbolAddress((void**)&wkh, g_wk_hi); cudaGetSymbolAddress((void**)&wkl, g_wk_lo);
    cudaGetSymbolAddress((void**)&wvh, g_wv_hi); cudaGetSymbolAddress((void**)&wvl, g_wv_lo);
    cudaGetSymbolAddress((void**)&wdh, g_wd_hi); cudaGetSymbolAddress((void**)&wdl, g_wd_lo);
    cudaGetSymbolAddress((void**)&qp, g_qp);    cudaGetSymbolAddress((void**)&kp, g_kp);
    cudaGetSymbolAddress((void**)&vp, g_vp);    cudaGetSymbolAddress((void**)&ctx, g_ctx);

    const int NBIG = BQ * SEQ * DM / 4 / 256;   // 4M-elem converts
    const int NW   = DM * DM / 4 / 256;         // 1M-elem converts
    convert_split<<<NBIG, 256>>>(q, qh, ql);
    convert_split<<<NBIG, 256>>>(k, kh, kl);
    convert_split<<<NBIG, 256>>>(v, vh, vl);
    convert_split<<<NW, 256>>>(Wq, wqh, wql);
    convert_split<<<NW, 256>>>(Wk, wkh, wkl);
    convert_split<<<NW, 256>>>(Wv, wvh, wvl);
    convert_split<<<NW, 256>>>(Wd, wdh, wdl);

    dim3 gg(DM / 128, (BQ * SEQ) / 128);   // 8 x 32
    mma_gemm<<<gg, 256, MMA_SMEM_BYTES>>>(qh, ql, wqh, wql, nullptr, qp);
    mma_gemm<<<gg, 256, MMA_SMEM_BYTES>>>(kh, kl, wkh, wkl, nullptr, kp);
    mma_gemm<<<gg, 256, MMA_SMEM_BYTES>>>(vh, vl, wvh, wvl, nullptr, vp);

    dim3 gs(SEQ / 128, SEQ / 128, BQ * NH);
    scores_kernel<<<gs, 256>>>(mask, attn_ext);
    softmax_kernel<<<BQ * NH * SEQ, 256>>>(attn_ext);
    ctx_kernel<<<dim3(SEQ / 128, BQ * NH), 256>>>(attn_ext);

    convert_split<<<NBIG, 256>>>(ctx, ch, cl);
    mma_gemm<<<gg, 256, MMA_SMEM_BYTES>>>(ch, cl, wdh, wdl, bd, out);
}

// round 5
// speedup vs baseline: 2.7206x; 1.6158x over previous
#include <cuda_runtime.h>
#include <cuda_bf16.h>
#include <stdint.h>
#include <math.h>

#define BQ  4
#define SEQ 1024
#define DM  1024
#define NH  16
#define HD  64

// ---------------- scratch (no allocations allowed) ----------------
__device__ float g_attn[BQ * NH * SEQ * SEQ];  // fallback if attn not an output

__device__ __nv_bfloat16 g_q_hi[BQ * SEQ * DM],  g_q_lo[BQ * SEQ * DM];
__device__ __nv_bfloat16 g_k_hi[BQ * SEQ * DM],  g_k_lo[BQ * SEQ * DM];
__device__ __nv_bfloat16 g_v_hi[BQ * SEQ * DM],  g_v_lo[BQ * SEQ * DM];
__device__ __nv_bfloat16 g_qp_hi[BQ * SEQ * DM], g_qp_lo[BQ * SEQ * DM];
__device__ __nv_bfloat16 g_kp_hi[BQ * SEQ * DM], g_kp_lo[BQ * SEQ * DM];
__device__ __nv_bfloat16 g_vp_hi[BQ * SEQ * DM], g_vp_lo[BQ * SEQ * DM];
__device__ __nv_bfloat16 g_c_hi[BQ * SEQ * DM],  g_c_lo[BQ * SEQ * DM];
__device__ __nv_bfloat16 g_wq_hi[DM * DM], g_wq_lo[DM * DM];
__device__ __nv_bfloat16 g_wk_hi[DM * DM], g_wk_lo[DM * DM];
__device__ __nv_bfloat16 g_wv_hi[DM * DM], g_wv_lo[DM * DM];
__device__ __nv_bfloat16 g_wd_hi[DM * DM], g_wd_lo[DM * DM];

#define SWZ(o) ((o) ^ (((o) >> 3) & 0x70))

__device__ __forceinline__ uint32_t smem_u32(const void* p) {
    uint32_t a;
    asm("{ .reg .u64 t; cvta.to.shared.u64 t, %1; cvt.u32.u64 %0, t; }" : "=r"(a) : "l"(p));
    return a;
}
__device__ __forceinline__ void ldm_x4(uint32_t* r, uint32_t addr) {
    asm volatile("ldmatrix.sync.aligned.m8n8.x4.shared.b16 {%0,%1,%2,%3}, [%4];"
        : "=r"(r[0]), "=r"(r[1]), "=r"(r[2]), "=r"(r[3]) : "r"(addr));
}
__device__ __forceinline__ void ldm_x4t(uint32_t* r, uint32_t addr) {
    asm volatile("ldmatrix.sync.aligned.m8n8.x4.trans.shared.b16 {%0,%1,%2,%3}, [%4];"
        : "=r"(r[0]), "=r"(r[1]), "=r"(r[2]), "=r"(r[3]) : "r"(addr));
}
__device__ __forceinline__ void mma_bf16(float* d, const uint32_t* a, const uint32_t* b) {
    asm volatile(
        "mma.sync.aligned.m16n8k16.row.col.f32.bf16.bf16.f32 "
        "{%0,%1,%2,%3}, {%4,%5,%6,%7}, {%8,%9}, {%0,%1,%2,%3};"
        : "+f"(d[0]), "+f"(d[1]), "+f"(d[2]), "+f"(d[3])
        : "r"(a[0]), "r"(a[1]), "r"(a[2]), "r"(a[3]), "r"(b[0]), "r"(b[1]));
}
#define CP16(dst, src) asm volatile("cp.async.cg.shared.global [%0], [%1], 16;" :: "r"(dst), "l"(src))
#define CP_COMMIT()    asm volatile("cp.async.commit_group;" ::: "memory")
#define CP_WAIT0()     asm volatile("cp.async.wait_group 0;" ::: "memory")
#define CP_WAIT1()     asm volatile("cp.async.wait_group 1;" ::: "memory")

__device__ __forceinline__ uint32_t pack_bf2(float x, float y) {
    __nv_bfloat162 t(__float2bfloat16_rn(x), __float2bfloat16_rn(y));
    return *(uint32_t*)&t;
}

// ---------------------------------------------------------------------------
// fp32 -> (bf16 hi, bf16 lo) split. grid*256*4 == n.
// ---------------------------------------------------------------------------
__global__ __launch_bounds__(256) void convert_split(
    const float* __restrict__ x,
    __nv_bfloat16* __restrict__ hi, __nv_bfloat16* __restrict__ lo)
{
    int i = blockIdx.x * 256 + threadIdx.x;
    float4 v = ((const float4*)x)[i];
    __nv_bfloat16 h0 = __float2bfloat16_rn(v.x);
    __nv_bfloat16 h1 = __float2bfloat16_rn(v.y);
    __nv_bfloat16 h2 = __float2bfloat16_rn(v.z);
    __nv_bfloat16 h3 = __float2bfloat16_rn(v.w);
    __nv_bfloat16 l0 = __float2bfloat16_rn(v.x - __bfloat162float(h0));
    __nv_bfloat16 l1 = __float2bfloat16_rn(v.y - __bfloat162float(h1));
    __nv_bfloat16 l2 = __float2bfloat16_rn(v.z - __bfloat162float(h2));
    __nv_bfloat16 l3 = __float2bfloat16_rn(v.w - __bfloat162float(h3));
    __nv_bfloat162* hp = (__nv_bfloat162*)(hi + (size_t)i * 4);
    __nv_bfloat162* lp = (__nv_bfloat162*)(lo + (size_t)i * 4);
    hp[0] = __nv_bfloat162(h0, h1); hp[1] = __nv_bfloat162(h2, h3);
    lp[0] = __nv_bfloat162(l0, l1); lp[1] = __nv_bfloat162(l2, l3);
}

// ---------------------------------------------------------------------------
// mma.sync bf16 GEMM, 2-stage cp.async pipeline.
// C[m][n] = sum_k A[m][k]*W[n][k]; 3-term split.
// Output: fp32 (+bias) if Cf32, else bf16 hi/lo split.
// CTA 128x128, 8 warps (64x32), BK=64.
// ---------------------------------------------------------------------------
#define GEMM_SMEM (2 * 65536)

__global__ __launch_bounds__(256) void mma_gemm(
    const __nv_bfloat16* __restrict__ Ahi, const __nv_bfloat16* __restrict__ Alo,
    const __nv_bfloat16* __restrict__ Whi, const __nv_bfloat16* __restrict__ Wlo,
    const float* __restrict__ bias, float* __restrict__ Cf32,
    __nv_bfloat16* __restrict__ Chi, __nv_bfloat16* __restrict__ Clo)
{
    extern __shared__ char sm[];
    const int K = DM, N = DM;
    const uint32_t O_AHI = 0, O_ALO = 16384, O_WHI = 32768, O_WLO = 49152;

    int tid = threadIdx.x, w = tid >> 5, l = tid & 31;
    int m0 = blockIdx.y * 128, n0 = blockIdx.x * 128;
    int wm = w & 1, wn = w >> 1;

    uint32_t sb = smem_u32(sm);

    int a_row = wm * 64 + (l & 15);
    int a_k2  = (l >> 4) * 16;
    int b_row = wn * 32 + (l & 7) + ((l >> 4) * 8);
    int b_k2  = ((l >> 3) & 1) * 16;

    int lrow = tid >> 3;
    int lc   = tid & 7;

    float acc[4][4][4] = {};

    const int NK = K / 64;

    // stage loader
    auto load_stage = [&](int s, int kc) {
        uint32_t base = sb + (uint32_t)s * 65536;
        #pragma unroll
        for (int it = 0; it < 4; it++) {
            int row = lrow + it * 32;
            size_t ga = (size_t)(m0 + row) * K + kc * 64 + lc * 8;
            size_t gw = (size_t)(n0 + row) * K + kc * 64 + lc * 8;
            uint32_t so = SWZ(row * 128 + lc * 16);
            CP16(base + O_AHI + so, Ahi + ga);
            CP16(base + O_ALO + so, Alo + ga);
            CP16(base + O_WHI + so, Whi + gw);
            CP16(base + O_WLO + so, Wlo + gw);
        }
        CP_COMMIT();
    };

    load_stage(0, 0);

    for (int kc = 0; kc < NK; kc++) {
        if (kc + 1 < NK) { load_stage((kc + 1) & 1, kc + 1); CP_WAIT1(); }
        else             { CP_WAIT0(); }
        __syncthreads();

        uint32_t st = sb + (uint32_t)(kc & 1) * 65536;
        #pragma unroll
        for (int kk = 0; kk < 4; kk++) {
            int ks2 = kk * 32;
            uint32_t ah[4][4], al[4][4], bw[2][4];
            #pragma unroll
            for (int mf = 0; mf < 4; mf++) {
                uint32_t off = SWZ((a_row + mf * 16) * 128 + ks2 + a_k2);
                ldm_x4(ah[mf], st + O_AHI + off);
                ldm_x4(al[mf], st + O_ALO + off);
            }
            #pragma unroll
            for (int bp = 0; bp < 2; bp++) {
                uint32_t off = SWZ((b_row + bp * 16) * 128 + ks2 + b_k2);
                ldm_x4(bw[bp], st + O_WHI + off);
            }
            #pragma unroll
            for (int mf = 0; mf < 4; mf++)
                #pragma unroll
                for (int nf = 0; nf < 4; nf++)
                    mma_bf16(acc[mf][nf], ah[mf], &bw[nf >> 1][(nf & 1) * 2]);
            #pragma unroll
            for (int mf = 0; mf < 4; mf++)
                #pragma unroll
                for (int nf = 0; nf < 4; nf++)
                    mma_bf16(acc[mf][nf], al[mf], &bw[nf >> 1][(nf & 1) * 2]);
            #pragma unroll
            for (int bp = 0; bp < 2; bp++) {
                uint32_t off = SWZ((b_row + bp * 16) * 128 + ks2 + b_k2);
                ldm_x4(bw[bp], st + O_WLO + off);
            }
            #pragma unroll
            for (int mf = 0; mf < 4; mf++)
                #pragma unroll
                for (int nf = 0; nf < 4; nf++)
                    mma_bf16(acc[mf][nf], ah[mf], &bw[nf >> 1][(nf & 1) * 2]);
        }
        __syncthreads();
    }

    int er = l >> 2, ec = (l & 3) * 2;
    #pragma unroll
    for (int mf = 0; mf < 4; mf++) {
        #pragma unroll
        for (int nf = 0; nf < 4; nf++) {
            int gm = m0 + wm * 64 + mf * 16 + er;
            int gn = n0 + wn * 32 + nf * 8 + ec;
            if (Cf32) {
                float b0 = bias ? bias[gn] : 0.0f;
                float b1 = bias ? bias[gn + 1] : 0.0f;
                float2 v0, v1;
                v0.x = acc[mf][nf][0] + b0; v0.y = acc[mf][nf][1] + b1;
                v1.x = acc[mf][nf][2] + b0; v1.y = acc[mf][nf][3] + b1;
                *(float2*)&Cf32[(size_t)gm * N + gn]       = v0;
                *(float2*)&Cf32[(size_t)(gm + 8) * N + gn] = v1;
            } else {
                #pragma unroll
                for (int rr = 0; rr < 2; rr++) {
                    float vx = acc[mf][nf][rr * 2], vy = acc[mf][nf][rr * 2 + 1];
                    float hx = __bfloat162float(__float2bfloat16_rn(vx));
                    float hy = __bfloat162float(__float2bfloat16_rn(vy));
                    size_t o = (size_t)(gm + rr * 8) * N + gn;
                    *(uint32_t*)&Chi[o] = pack_bf2(vx, vy);
                    *(uint32_t*)&Clo[o] = pack_bf2(vx - hx, vy - hy);
                }
            }
        }
    }
}

// ---------------------------------------------------------------------------
// scores via mma.sync: attn_raw[bh][m][n] = (Qh[m,:].Kh[n,:])/32 + mask*-1e9
// CTA 128x128 per head; K=64 (4 chunks). 3-term split.
// ---------------------------------------------------------------------------
#define SCORES_SMEM 65536

__global__ __launch_bounds__(256) void scores_mma(
    const int* __restrict__ mask, float* __restrict__ attn)
{
    extern __shared__ char sm[];
    const uint32_t O_QH = 0, O_QL = 16384, O_KH = 32768, O_KL = 49152;

    int tid = threadIdx.x, w = tid >> 5, l = tid & 31;
    int bh = blockIdx.z, b = bh >> 4, h = bh & 15;
    int m0 = blockIdx.y * 128, n0 = blockIdx.x * 128;
    int wm = w & 1, wn = w >> 1;

    uint32_t sb = smem_u32(sm);

    const __nv_bfloat16* Qh = g_qp_hi + (size_t)b * SEQ * DM + h * HD;
    const __nv_bfloat16* Ql = g_qp_lo + (size_t)b * SEQ * DM + h * HD;
    const __nv_bfloat16* Kh = g_kp_hi + (size_t)b * SEQ * DM + h * HD;
    const __nv_bfloat16* Kl = g_kp_lo + (size_t)b * SEQ * DM + h * HD;

    #pragma unroll
    for (int it = 0; it < 4; it++) {
        int idx = tid + it * 256;          // 0..1023
        int row = idx >> 3, c = idx & 7;
        uint32_t so = SWZ(row * 128 + c * 16);
        size_t gq = (size_t)(m0 + row) * DM + c * 8;
        size_t gk = (size_t)(n0 + row) * DM + c * 8;
        *(uint4*)(sm + O_QH + so) = *(const uint4*)(Qh + gq);
        *(uint4*)(sm + O_QL + so) = *(const uint4*)(Ql + gq);
        *(uint4*)(sm + O_KH + so) = *(const uint4*)(Kh + gk);
        *(uint4*)(sm + O_KL + so) = *(const uint4*)(Kl + gk);
    }
    __syncthreads();

    int a_row = wm * 64 + (l & 15);
    int a_k2  = (l >> 4) * 16;
    int b_row = wn * 32 + (l & 7) + ((l >> 4) * 8);
    int b_k2  = ((l >> 3) & 1) * 16;

    float acc[4][4][4] = {};

    #pragma unroll
    for (int kk = 0; kk < 4; kk++) {
        int ks2 = kk * 32;
        uint32_t ah[4][4], al[4][4], bw[2][4];
        #pragma unroll
        for (int mf = 0; mf < 4; mf++) {
            uint32_t off = SWZ((a_row + mf * 16) * 128 + ks2 + a_k2);
            ldm_x4(ah[mf], sb + O_QH + off);
            ldm_x4(al[mf], sb + O_QL + off);
        }
        #pragma unroll
        for (int bp = 0; bp < 2; bp++) {
            uint32_t off = SWZ((b_row + bp * 16) * 128 + ks2 + b_k2);
            ldm_x4(bw[bp], sb + O_KH + off);
        }
        #pragma unroll
        for (int mf = 0; mf < 4; mf++)
            #pragma unroll
            for (int nf = 0; nf < 4; nf++)
                mma_bf16(acc[mf][nf], ah[mf], &bw[nf >> 1][(nf & 1) * 2]);
        #pragma unroll
        for (int mf = 0; mf < 4; mf++)
            #pragma unroll
            for (int nf = 0; nf < 4; nf++)
                mma_bf16(acc[mf][nf], al[mf], &bw[nf >> 1][(nf & 1) * 2]);
        #pragma unroll
        for (int bp = 0; bp < 2; bp++) {
            uint32_t off = SWZ((b_row + bp * 16) * 128 + ks2 + b_k2);
            ldm_x4(bw[bp], sb + O_KL + off);
        }
        #pragma unroll
        for (int mf = 0; mf < 4; mf++)
            #pragma unroll
            for (int nf = 0; nf < 4; nf++)
                mma_bf16(acc[mf][nf], ah[mf], &bw[nf >> 1][(nf & 1) * 2]);
    }

    const float scale = 0.03125f;
    int er = l >> 2, ec = (l & 3) * 2;
    #pragma unroll
    for (int mf = 0; mf < 4; mf++) {
        #pragma unroll
        for (int nf = 0; nf < 4; nf++) {
            int gm = m0 + wm * 64 + mf * 16 + er;
            int gn = n0 + wn * 32 + nf * 8 + ec;
            #pragma unroll
            for (int rr = 0; rr < 2; rr++) {
                int gmr = gm + rr * 8;
                int2 mv = *(const int2*)(mask + (size_t)b * SEQ * SEQ + (size_t)gmr * SEQ + gn);
                float2 v;
                v.x = acc[mf][nf][rr * 2]     * scale + (float)mv.x * -1e9f;
                v.y = acc[mf][nf][rr * 2 + 1] * scale + (float)mv.y * -1e9f;
                *(float2*)&attn[((size_t)bh * SEQ + gmr) * SEQ + gn] = v;
            }
        }
    }
}

// in-place row softmax, one block per row (length 1024)
__global__ __launch_bounds__(256) void softmax_kernel(float* __restrict__ attn)
{
    float* p = attn + (size_t)blockIdx.x * SEQ;
    int tid = threadIdx.x;

    float4 x = ((const float4*)p)[tid];
    float m = fmaxf(fmaxf(x.x, x.y), fmaxf(x.z, x.w));

    __shared__ float red[8];
    #pragma unroll
    for (int o = 16; o; o >>= 1) m = fmaxf(m, __shfl_xor_sync(0xffffffffu, m, o));
    if ((tid & 31) == 0) red[tid >> 5] = m;
    __syncthreads();
    m = red[0];
    #pragma unroll
    for (int i = 1; i < 8; i++) m = fmaxf(m, red[i]);

    float4 e;
    e.x = __expf(x.x - m); e.y = __expf(x.y - m);
    e.z = __expf(x.z - m); e.w = __expf(x.w - m);
    float s = (e.x + e.y) + (e.z + e.w);

    __syncthreads();
    #pragma unroll
    for (int o = 16; o; o >>= 1) s += __shfl_xor_sync(0xffffffffu, s, o);
    if ((tid & 31) == 0) red[tid >> 5] = s;
    __syncthreads();
    s = 0.0f;
    #pragma unroll
    for (int i = 0; i < 8; i++) s += red[i];

    float inv = __frcp_rn(s);
    e.x *= inv; e.y *= inv; e.z *= inv; e.w *= inv;
    ((float4*)p)[tid] = e;
}

// ---------------------------------------------------------------------------
// ctx via mma.sync: ctx[m][dh] = sum_k attn[bh][m][k] * V[k][dh]
// Reads attn fp32, converts to bf16 hi/lo in-kernel; V via ldmatrix.trans.
// CTA: 128 m-rows x 64 n per head; loop k in 128-tiles. Writes bf16 hi/lo.
// attn tiles stored as 2 subtiles of 64 cols (128B rows) per buffer.
// ---------------------------------------------------------------------------
#define CTX_SMEM 98304

__global__ __launch_bounds__(256) void ctx_mma(const float* __restrict__ attn)
{
    extern __shared__ char sm[];
    const uint32_t O_AH = 0, O_AL = 32768, O_VH = 65536, O_VL = 81920;

    int tid = threadIdx.x, w = tid >> 5, l = tid & 31;
    int bh = blockIdx.y, b = bh >> 4, h = bh & 15;
    int m0 = blockIdx.x * 128;
    int wm = w & 3, wn = w >> 2;   // warp tile 32x32

    uint32_t sb = smem_u32(sm);

    const __nv_bfloat16* Vh = g_v_hi;   // placeholder; real = vp split below
    (void)Vh;
    const __nv_bfloat16* Vhi = g_vp_hi + (size_t)b * SEQ * DM + h * HD;
    const __nv_bfloat16* Vlo = g_vp_lo + (size_t)b * SEQ * DM + h * HD;
    const float* Ab = attn + ((size_t)bh * SEQ + m0) * SEQ;

    int arow = tid >> 1;            // 0..127
    int asub = tid & 1;             // 64-col half
    const float* Arow = Ab + (size_t)arow * SEQ + asub * 64;

    float acc[2][4][4] = {};

    for (int k0 = 0; k0 < SEQ; k0 += 128) {
        __syncthreads();
        // attn fp32 -> bf16 hi/lo into smem (2 subtiles of 64 cols)
        #pragma unroll
        for (int j = 0; j < 16; j++) {
            float4 v = *(const float4*)(Arow + k0 + j * 4);
            float hx = __bfloat162float(__float2bfloat16_rn(v.x));
            float hy = __bfloat162float(__float2bfloat16_rn(v.y));
            float hz = __bfloat162float(__float2bfloat16_rn(v.z));
            float hw = __bfloat162float(__float2bfloat16_rn(v.w));
            uint2 hp, lp;
            hp.x = pack_bf2(v.x, v.y);      hp.y = pack_bf2(v.z, v.w);
            lp.x = pack_bf2(v.x - hx, v.y - hy); lp.y = pack_bf2(v.z - hz, v.w - hw);
            uint32_t so = asub * 16384u + SWZ(arow * 128 + j * 8);
            *(uint2*)(sm + O_AH + so) = hp;
            *(uint2*)(sm + O_AL + so) = lp;
        }
        // V tile [k][n]: 128 rows x 64 bf16
        #pragma unroll
        for (int it = 0; it < 4; it++) {
            int idx = tid + it * 256;
            int row = idx >> 3, c = idx & 7;
            uint32_t so = SWZ(row * 128 + c * 16);
            size_t gv = (size_t)(k0 + row) * DM + c * 8;
            *(uint4*)(sm + O_VH + so) = *(const uint4*)(Vhi + gv);
            *(uint4*)(sm + O_VL + so) = *(const uint4*)(Vlo + gv);
        }
        __syncthreads();

        #pragma unroll
        for (int kk = 0; kk < 8; kk++) {
            int kabs = kk * 16;
            int sub = kabs >> 6;
            int kin2 = (kabs & 63) * 2;
            uint32_t ah[2][4], al[2][4], bvh[2][4], bvl[2][4];
            #pragma unroll
            for (int mf = 0; mf < 2; mf++) {
                int r = wm * 32 + mf * 16 + (l & 15);
                uint32_t off = (uint32_t)sub * 16384u + SWZ(r * 128 + kin2 + (l >> 4) * 16);
                ldm_x4(ah[mf], sb + O_AH + off);
                ldm_x4(al[mf], sb + O_AL + off);
            }
            #pragma unroll
            for (int nb = 0; nb < 2; nb++) {
                int vr = kabs + (l & 15);
                int nc2 = (wn * 32 + nb * 16 + (l >> 4) * 8) * 2;
                uint32_t off = SWZ(vr * 128 + nc2);
                ldm_x4t(bvh[nb], sb + O_VH + off);
                ldm_x4t(bvl[nb], sb + O_VL + off);
            }
            #pragma unroll
            for (int mf = 0; mf < 2; mf++)
                #pragma unroll
                for (int nf = 0; nf < 4; nf++) {
                    mma_bf16(acc[mf][nf], ah[mf], &bvh[nf >> 1][(nf & 1) * 2]);
                    mma_bf16(acc[mf][nf], al[mf], &bvh[nf >> 1][(nf & 1) * 2]);
                    mma_bf16(acc[mf][nf], ah[mf], &bvl[nf >> 1][(nf & 1) * 2]);
                }
        }
    }

    __nv_bfloat16* Chi = g_c_hi + (size_t)b * SEQ * DM + h * HD;
    __nv_bfloat16* Clo = g_c_lo + (size_t)b * SEQ * DM + h * HD;
    int er = l >> 2, ec = (l & 3) * 2;
    #pragma unroll
    for (int mf = 0; mf < 2; mf++) {
        #pragma unroll
        for (int nf = 0; nf < 4; nf++) {
            int gm = m0 + wm * 32 + mf * 16 + er;
            int gn = wn * 32 + nf * 8 + ec;
            #pragma unroll
            for (int rr = 0; rr < 2; rr++) {
                float vx = acc[mf][nf][rr * 2], vy = acc[mf][nf][rr * 2 + 1];
                float hx = __bfloat162float(__float2bfloat16_rn(vx));
                float hy = __bfloat162float(__float2bfloat16_rn(vy));
                size_t o = (size_t)(gm + rr * 8) * DM + gn;
                *(uint32_t*)&Chi[o] = pack_bf2(vx, vy);
                *(uint32_t*)&Clo[o] = pack_bf2(vx - hx, vy - hy);
            }
        }
    }
}

// ---------------------------------------------------------------------------
extern "C" void kernel_launch(void* const* d_in, const int* in_sizes, int n_in,
                              void* d_out, int out_size)
{
    const float* q   = (const float*)d_in[0];
    const float* k   = (const float*)d_in[1];
    const float* v   = (const float*)d_in[2];
    const int*  mask = (const int*)d_in[3];
    const float* Wq  = (const float*)d_in[4];
    const float* Wk  = (const float*)d_in[5];
    const float* Wv  = (const float*)d_in[6];
    const float* Wd  = (const float*)d_in[7];
    const float* bd  = (const float*)d_in[8];
    float* out = (float*)d_out;

    const long long out_elems  = (long long)BQ * SEQ * DM;           // 4M
    const long long attn_elems = (long long)BQ * NH * SEQ * SEQ;     // 64M
    float* attn;
    if ((long long)out_size >= out_elems + attn_elems) {
        attn = out + out_elems;
    } else {
        cudaGetSymbolAddress((void**)&attn, g_attn);
    }

    cudaFuncSetAttribute(mma_gemm, cudaFuncAttributeMaxDynamicSharedMemorySize, GEMM_SMEM);
    cudaFuncSetAttribute(scores_mma, cudaFuncAttributeMaxDynamicSharedMemorySize, SCORES_SMEM);
    cudaFuncSetAttribute(ctx_mma, cudaFuncAttributeMaxDynamicSharedMemorySize, CTX_SMEM);

    __nv_bfloat16 *qh, *ql, *kh, *kl, *vh, *vl, *ch, *cl;
    __nv_bfloat16 *qph, *qpl, *kph, *kpl, *vph, *vpl;
    __nv_bfloat16 *wqh, *wql, *wkh, *wkl, *wvh, *wvl, *wdh, *wdl;
    cudaGetSymbolAddress((void**)&qh, g_q_hi);   cudaGetSymbolAddress((void**)&ql, g_q_lo);
    cudaGetSymbolAddress((void**)&kh, g_k_hi);   cudaGetSymbolAddress((void**)&kl, g_k_lo);
    cudaGetSymbolAddress((void**)&vh, g_v_hi);   cudaGetSymbolAddress((void**)&vl, g_v_lo);
    cudaGetSymbolAddress((void**)&ch, g_c_hi);   cudaGetSymbolAddress((void**)&cl, g_c_lo);
    cudaGetSymbolAddress((void**)&qph, g_qp_hi); cudaGetSymbolAddress((void**)&qpl, g_qp_lo);
    cudaGetSymbolAddress((void**)&kph, g_kp_hi); cudaGetSymbolAddress((void**)&kpl, g_kp_lo);
    cudaGetSymbolAddress((void**)&vph, g_vp_hi); cudaGetSymbolAddress((void**)&vpl, g_vp_lo);
    cudaGetSymbolAddress((void**)&wqh, g_wq_hi); cudaGetSymbolAddress((void**)&wql, g_wq_lo);
    cudaGetSymbolAddress((void**)&wkh, g_wk_hi); cudaGetSymbolAddress((void**)&wkl, g_wk_lo);
    cudaGetSymbolAddress((void**)&wvh, g_wv_hi); cudaGetSymbolAddress((void**)&wvl, g_wv_lo);
    cudaGetSymbolAddress((void**)&wdh, g_wd_hi); cudaGetSymbolAddress((void**)&wdl, g_wd_lo);

    const int NBIG = BQ * SEQ * DM / 4 / 256;
    const int NW   = DM * DM / 4 / 256;
    convert_split<<<NBIG, 256>>>(q, qh, ql);
    convert_split<<<NBIG, 256>>>(k, kh, kl);
    convert_split<<<NBIG, 256>>>(v, vh, vl);
    convert_split<<<NW, 256>>>(Wq, wqh, wql);
    convert_split<<<NW, 256>>>(Wk, wkh, wkl);
    convert_split<<<NW, 256>>>(Wv, wvh, wvl);
    convert_split<<<NW, 256>>>(Wd, wdh, wdl);

    dim3 gg(DM / 128, (BQ * SEQ) / 128);   // 8 x 32
    mma_gemm<<<gg, 256, GEMM_SMEM>>>(qh, ql, wqh, wql, nullptr, nullptr, qph, qpl);
    mma_gemm<<<gg, 256, GEMM_SMEM>>>(kh, kl, wkh, wkl, nullptr, nullptr, kph, kpl);
    mma_gemm<<<gg, 256, GEMM_SMEM>>>(vh, vl, wvh, wvl, nullptr, nullptr, vph, vpl);

    dim3 gs(SEQ / 128, SEQ / 128, BQ * NH);
    scores_mma<<<gs, 256, SCORES_SMEM>>>(mask, attn);
    softmax_kernel<<<BQ * NH * SEQ, 256>>>(attn);
    ctx_mma<<<dim3(SEQ / 128, BQ * NH), 256, CTX_SMEM>>>(attn);

    mma_gemm<<<gg, 256, GEMM_SMEM>>>(ch, cl, wdh, wdl, bd, out, nullptr, nullptr);
}

// round 6
// speedup vs baseline: 2.8591x; 1.0509x over previous
#include <cuda_runtime.h>
#include <cuda_bf16.h>
#include <stdint.h>
#include <math.h>

#define BQ  4
#define SEQ 1024
#define DM  1024
#define NH  16
#define HD  64

// ---------------- scratch (no allocations allowed) ----------------
__device__ float g_attn[BQ * NH * SEQ * SEQ];  // fallback if attn not an output
__device__ float g_rmax[BQ * NH * SEQ];
__device__ float g_rsum[BQ * NH * SEQ];
__device__ uint32_t g_mbits[BQ * SEQ * (SEQ / 32)];

__device__ __nv_bfloat16 g_q_hi[BQ * SEQ * DM],  g_q_lo[BQ * SEQ * DM];
__device__ __nv_bfloat16 g_k_hi[BQ * SEQ * DM],  g_k_lo[BQ * SEQ * DM];
__device__ __nv_bfloat16 g_v_hi[BQ * SEQ * DM],  g_v_lo[BQ * SEQ * DM];
__device__ __nv_bfloat16 g_qp_hi[BQ * SEQ * DM], g_qp_lo[BQ * SEQ * DM];
__device__ __nv_bfloat16 g_kp_hi[BQ * SEQ * DM], g_kp_lo[BQ * SEQ * DM];
__device__ __nv_bfloat16 g_vp_hi[BQ * SEQ * DM], g_vp_lo[BQ * SEQ * DM];
__device__ __nv_bfloat16 g_c_hi[BQ * SEQ * DM],  g_c_lo[BQ * SEQ * DM];
__device__ __nv_bfloat16 g_wq_hi[DM * DM], g_wq_lo[DM * DM];
__device__ __nv_bfloat16 g_wk_hi[DM * DM], g_wk_lo[DM * DM];
__device__ __nv_bfloat16 g_wv_hi[DM * DM], g_wv_lo[DM * DM];
__device__ __nv_bfloat16 g_wd_hi[DM * DM], g_wd_lo[DM * DM];

#define SWZ(o) ((o) ^ (((o) >> 3) & 0x70))

__device__ __forceinline__ uint32_t smem_u32(const void* p) {
    uint32_t a;
    asm("{ .reg .u64 t; cvta.to.shared.u64 t, %1; cvt.u32.u64 %0, t; }" : "=r"(a) : "l"(p));
    return a;
}
__device__ __forceinline__ void ldm_x4(uint32_t* r, uint32_t addr) {
    asm volatile("ldmatrix.sync.aligned.m8n8.x4.shared.b16 {%0,%1,%2,%3}, [%4];"
        : "=r"(r[0]), "=r"(r[1]), "=r"(r[2]), "=r"(r[3]) : "r"(addr));
}
__device__ __forceinline__ void ldm_x4t(uint32_t* r, uint32_t addr) {
    asm volatile("ldmatrix.sync.aligned.m8n8.x4.trans.shared.b16 {%0,%1,%2,%3}, [%4];"
        : "=r"(r[0]), "=r"(r[1]), "=r"(r[2]), "=r"(r[3]) : "r"(addr));
}
__device__ __forceinline__ void mma_bf16(float* d, const uint32_t* a, const uint32_t* b) {
    asm volatile(
        "mma.sync.aligned.m16n8k16.row.col.f32.bf16.bf16.f32 "
        "{%0,%1,%2,%3}, {%4,%5,%6,%7}, {%8,%9}, {%0,%1,%2,%3};"
        : "+f"(d[0]), "+f"(d[1]), "+f"(d[2]), "+f"(d[3])
        : "r"(a[0]), "r"(a[1]), "r"(a[2]), "r"(a[3]), "r"(b[0]), "r"(b[1]));
}
#define CP16(dst, src) asm volatile("cp.async.cg.shared.global [%0], [%1], 16;" :: "r"(dst), "l"(src))
#define CP_COMMIT()    asm volatile("cp.async.commit_group;" ::: "memory")
#define CP_WAIT0()     asm volatile("cp.async.wait_group 0;" ::: "memory")
#define CP_WAIT1()     asm volatile("cp.async.wait_group 1;" ::: "memory")

__device__ __forceinline__ uint32_t pack_bf2(float x, float y) {
    __nv_bfloat162 t(__float2bfloat16_rn(x), __float2bfloat16_rn(y));
    return *(uint32_t*)&t;
}

// ---------------------------------------------------------------------------
__global__ __launch_bounds__(256) void convert_split(
    const float* __restrict__ x,
    __nv_bfloat16* __restrict__ hi, __nv_bfloat16* __restrict__ lo)
{
    int i = blockIdx.x * 256 + threadIdx.x;
    float4 v = ((const float4*)x)[i];
    __nv_bfloat16 h0 = __float2bfloat16_rn(v.x);
    __nv_bfloat16 h1 = __float2bfloat16_rn(v.y);
    __nv_bfloat16 h2 = __float2bfloat16_rn(v.z);
    __nv_bfloat16 h3 = __float2bfloat16_rn(v.w);
    __nv_bfloat16 l0 = __float2bfloat16_rn(v.x - __bfloat162float(h0));
    __nv_bfloat16 l1 = __float2bfloat16_rn(v.y - __bfloat162float(h1));
    __nv_bfloat16 l2 = __float2bfloat16_rn(v.z - __bfloat162float(h2));
    __nv_bfloat16 l3 = __float2bfloat16_rn(v.w - __bfloat162float(h3));
    __nv_bfloat162* hp = (__nv_bfloat162*)(hi + (size_t)i * 4);
    __nv_bfloat162* lp = (__nv_bfloat162*)(lo + (size_t)i * 4);
    hp[0] = __nv_bfloat162(h0, h1); hp[1] = __nv_bfloat162(h2, h3);
    lp[0] = __nv_bfloat162(l0, l1); lp[1] = __nv_bfloat162(l2, l3);
}

// int32 mask -> packed bits (1 = masked)
__global__ __launch_bounds__(256) void mask_to_bits(
    const int* __restrict__ mask, uint32_t* __restrict__ bits)
{
    int w = blockIdx.x * 256 + threadIdx.x;
    const int* p = mask + (size_t)w * 32;
    uint32_t word = 0;
    #pragma unroll
    for (int j = 0; j < 8; j++) {
        int4 v = ((const int4*)p)[j];
        word |= (v.x ? 1u : 0u) << (j * 4 + 0);
        word |= (v.y ? 1u : 0u) << (j * 4 + 1);
        word |= (v.z ? 1u : 0u) << (j * 4 + 2);
        word |= (v.w ? 1u : 0u) << (j * 4 + 3);
    }
    bits[w] = word;
}

// ---------------------------------------------------------------------------
// mma.sync bf16 GEMM, 2-stage cp.async pipeline (unchanged from R5).
// ---------------------------------------------------------------------------
#define GEMM_SMEM (2 * 65536)

__global__ __launch_bounds__(256) void mma_gemm(
    const __nv_bfloat16* __restrict__ Ahi, const __nv_bfloat16* __restrict__ Alo,
    const __nv_bfloat16* __restrict__ Whi, const __nv_bfloat16* __restrict__ Wlo,
    const float* __restrict__ bias, float* __restrict__ Cf32,
    __nv_bfloat16* __restrict__ Chi, __nv_bfloat16* __restrict__ Clo)
{
    extern __shared__ char sm[];
    const int K = DM, N = DM;
    const uint32_t O_AHI = 0, O_ALO = 16384, O_WHI = 32768, O_WLO = 49152;

    int tid = threadIdx.x, w = tid >> 5, l = tid & 31;
    int m0 = blockIdx.y * 128, n0 = blockIdx.x * 128;
    int wm = w & 1, wn = w >> 1;

    uint32_t sb = smem_u32(sm);

    int a_row = wm * 64 + (l & 15);
    int a_k2  = (l >> 4) * 16;
    int b_row = wn * 32 + (l & 7) + ((l >> 4) * 8);
    int b_k2  = ((l >> 3) & 1) * 16;

    int lrow = tid >> 3;
    int lc   = tid & 7;

    float acc[4][4][4] = {};
    const int NK = K / 64;

    auto load_stage = [&](int s, int kc) {
        uint32_t base = sb + (uint32_t)s * 65536;
        #pragma unroll
        for (int it = 0; it < 4; it++) {
            int row = lrow + it * 32;
            size_t ga = (size_t)(m0 + row) * K + kc * 64 + lc * 8;
            size_t gw = (size_t)(n0 + row) * K + kc * 64 + lc * 8;
            uint32_t so = SWZ(row * 128 + lc * 16);
            CP16(base + O_AHI + so, Ahi + ga);
            CP16(base + O_ALO + so, Alo + ga);
            CP16(base + O_WHI + so, Whi + gw);
            CP16(base + O_WLO + so, Wlo + gw);
        }
        CP_COMMIT();
    };

    load_stage(0, 0);

    for (int kc = 0; kc < NK; kc++) {
        if (kc + 1 < NK) { load_stage((kc + 1) & 1, kc + 1); CP_WAIT1(); }
        else             { CP_WAIT0(); }
        __syncthreads();

        uint32_t st = sb + (uint32_t)(kc & 1) * 65536;
        #pragma unroll
        for (int kk = 0; kk < 4; kk++) {
            int ks2 = kk * 32;
            uint32_t ah[4][4], al[4][4], bw[2][4];
            #pragma unroll
            for (int mf = 0; mf < 4; mf++) {
                uint32_t off = SWZ((a_row + mf * 16) * 128 + ks2 + a_k2);
                ldm_x4(ah[mf], st + O_AHI + off);
                ldm_x4(al[mf], st + O_ALO + off);
            }
            #pragma unroll
            for (int bp = 0; bp < 2; bp++) {
                uint32_t off = SWZ((b_row + bp * 16) * 128 + ks2 + b_k2);
                ldm_x4(bw[bp], st + O_WHI + off);
            }
            #pragma unroll
            for (int mf = 0; mf < 4; mf++)
                #pragma unroll
                for (int nf = 0; nf < 4; nf++)
                    mma_bf16(acc[mf][nf], ah[mf], &bw[nf >> 1][(nf & 1) * 2]);
            #pragma unroll
            for (int mf = 0; mf < 4; mf++)
                #pragma unroll
                for (int nf = 0; nf < 4; nf++)
                    mma_bf16(acc[mf][nf], al[mf], &bw[nf >> 1][(nf & 1) * 2]);
            #pragma unroll
            for (int bp = 0; bp < 2; bp++) {
                uint32_t off = SWZ((b_row + bp * 16) * 128 + ks2 + b_k2);
                ldm_x4(bw[bp], st + O_WLO + off);
            }
            #pragma unroll
            for (int mf = 0; mf < 4; mf++)
                #pragma unroll
                for (int nf = 0; nf < 4; nf++)
                    mma_bf16(acc[mf][nf], ah[mf], &bw[nf >> 1][(nf & 1) * 2]);
        }
        __syncthreads();
    }

    int er = l >> 2, ec = (l & 3) * 2;
    #pragma unroll
    for (int mf = 0; mf < 4; mf++) {
        #pragma unroll
        for (int nf = 0; nf < 4; nf++) {
            int gm = m0 + wm * 64 + mf * 16 + er;
            int gn = n0 + wn * 32 + nf * 8 + ec;
            if (Cf32) {
                float b0 = bias ? bias[gn] : 0.0f;
                float b1 = bias ? bias[gn + 1] : 0.0f;
                float2 v0, v1;
                v0.x = acc[mf][nf][0] + b0; v0.y = acc[mf][nf][1] + b1;
                v1.x = acc[mf][nf][2] + b0; v1.y = acc[mf][nf][3] + b1;
                *(float2*)&Cf32[(size_t)gm * N + gn]       = v0;
                *(float2*)&Cf32[(size_t)(gm + 8) * N + gn] = v1;
            } else {
                #pragma unroll
                for (int rr = 0; rr < 2; rr++) {
                    float vx = acc[mf][nf][rr * 2], vy = acc[mf][nf][rr * 2 + 1];
                    float hx = __bfloat162float(__float2bfloat16_rn(vx));
                    float hy = __bfloat162float(__float2bfloat16_rn(vy));
                    size_t o = (size_t)(gm + rr * 8) * N + gn;
                    *(uint32_t*)&Chi[o] = pack_bf2(vx, vy);
                    *(uint32_t*)&Clo[o] = pack_bf2(vx - hx, vy - hy);
                }
            }
        }
    }
}

// ---------------------------------------------------------------------------
// Fused attention, pass 1: per (bh, 128-row tile), online row (max, sum)
// over all 1024 keys. 8 warps: wm=w&3 (32-row group), wn=w>>2 (64-key half).
// ---------------------------------------------------------------------------
#define P1_SMEM (65536 + 2048 + 2048)

__global__ __launch_bounds__(256) void attn_pass1()
{
    extern __shared__ char sm[];
    const uint32_t O_QH = 0, O_QL = 16384, O_KH = 32768, O_KL = 49152;
    uint32_t* sm_mb = (uint32_t*)(sm + 65536);       // 128 x 4 words
    float* sm_m = (float*)(sm + 65536 + 2048);       // 2 x 128
    float* sm_s = sm_m + 256;

    int tid = threadIdx.x, w = tid >> 5, l = tid & 31;
    int bh = blockIdx.y, b = bh >> 4, h = bh & 15;
    int m0 = blockIdx.x * 128;
    int wm = w & 3, wn = w >> 2;
    uint32_t sb = smem_u32(sm);

    const __nv_bfloat16* Qh = g_qp_hi + (size_t)b * SEQ * DM + h * HD;
    const __nv_bfloat16* Ql = g_qp_lo + (size_t)b * SEQ * DM + h * HD;
    const __nv_bfloat16* Kh = g_kp_hi + (size_t)b * SEQ * DM + h * HD;
    const __nv_bfloat16* Kl = g_kp_lo + (size_t)b * SEQ * DM + h * HD;

    // Q tile (persistent)
    #pragma unroll
    for (int it = 0; it < 4; it++) {
        int idx = tid + it * 256;
        int row = idx >> 3, c = idx & 7;
        uint32_t so = SWZ(row * 128 + c * 16);
        size_t g = (size_t)(m0 + row) * DM + c * 8;
        *(uint4*)(sm + O_QH + so) = *(const uint4*)(Qh + g);
        *(uint4*)(sm + O_QL + so) = *(const uint4*)(Ql + g);
    }

    float mrun[2][2] = {{-1e30f, -1e30f}, {-1e30f, -1e30f}};
    float srun[2][2] = {};
    const float scale = 0.03125f;
    int er = l >> 2, ec = (l & 3) * 2;

    for (int nt = 0; nt < 8; nt++) {
        __syncthreads();
        #pragma unroll
        for (int it = 0; it < 4; it++) {
            int idx = tid + it * 256;
            int row = idx >> 3, c = idx & 7;
            uint32_t so = SWZ(row * 128 + c * 16);
            size_t g = (size_t)(nt * 128 + row) * DM + c * 8;
            *(uint4*)(sm + O_KH + so) = *(const uint4*)(Kh + g);
            *(uint4*)(sm + O_KL + so) = *(const uint4*)(Kl + g);
        }
        if (tid < 128)
            *(uint4*)&sm_mb[tid * 4] =
                *(const uint4*)&g_mbits[((size_t)b * SEQ + m0 + tid) * 32 + nt * 4];
        __syncthreads();

        float acc[2][8][4] = {};
        #pragma unroll
        for (int kk = 0; kk < 4; kk++) {
            int ks2 = kk * 32;
            uint32_t ah[2][4], al[2][4], bwh[4][4], bwl[4][4];
            #pragma unroll
            for (int mf = 0; mf < 2; mf++) {
                uint32_t off = SWZ((wm * 32 + mf * 16 + (l & 15)) * 128 + ks2 + (l >> 4) * 16);
                ldm_x4(ah[mf], sb + O_QH + off);
                ldm_x4(al[mf], sb + O_QL + off);
            }
            #pragma unroll
            for (int bp = 0; bp < 4; bp++) {
                uint32_t off = SWZ((wn * 64 + bp * 16 + (l & 7) + ((l >> 4) * 8)) * 128
                                   + ks2 + ((l >> 3) & 1) * 16);
                ldm_x4(bwh[bp], sb + O_KH + off);
                ldm_x4(bwl[bp], sb + O_KL + off);
            }
            #pragma unroll
            for (int mf = 0; mf < 2; mf++)
                #pragma unroll
                for (int nf = 0; nf < 8; nf++) {
                    mma_bf16(acc[mf][nf], ah[mf], &bwh[nf >> 1][(nf & 1) * 2]);
                    mma_bf16(acc[mf][nf], al[mf], &bwh[nf >> 1][(nf & 1) * 2]);
                    mma_bf16(acc[mf][nf], ah[mf], &bwl[nf >> 1][(nf & 1) * 2]);
                }
        }

        // online stats
        #pragma unroll
        for (int mf = 0; mf < 2; mf++) {
            #pragma unroll
            for (int rr = 0; rr < 2; rr++) {
                int rl = wm * 32 + mf * 16 + rr * 8 + er;
                uint32_t w0 = sm_mb[rl * 4 + wn * 2];
                uint32_t w1 = sm_mb[rl * 4 + wn * 2 + 1];
                float v[16];
                float tmax = -1e30f;
                #pragma unroll
                for (int nf = 0; nf < 8; nf++) {
                    uint32_t word = (nf < 4) ? w0 : w1;
                    int sh = (nf & 3) * 8 + ec;
                    float m0f = ((word >> sh) & 1u) ? -1e9f : 0.0f;
                    float m1f = ((word >> (sh + 1)) & 1u) ? -1e9f : 0.0f;
                    v[nf * 2]     = acc[mf][nf][rr * 2]     * scale + m0f;
                    v[nf * 2 + 1] = acc[mf][nf][rr * 2 + 1] * scale + m1f;
                    tmax = fmaxf(tmax, fmaxf(v[nf * 2], v[nf * 2 + 1]));
                }
                tmax = fmaxf(tmax, __shfl_xor_sync(0xffffffffu, tmax, 1));
                tmax = fmaxf(tmax, __shfl_xor_sync(0xffffffffu, tmax, 2));
                float nm = fmaxf(mrun[mf][rr], tmax);
                float ts = 0.0f;
                #pragma unroll
                for (int i = 0; i < 16; i++) ts += __expf(v[i] - nm);
                ts += __shfl_xor_sync(0xffffffffu, ts, 1);
                ts += __shfl_xor_sync(0xffffffffu, ts, 2);
                srun[mf][rr] = srun[mf][rr] * __expf(mrun[mf][rr] - nm) + ts;
                mrun[mf][rr] = nm;
            }
        }
    }

    if ((l & 3) == 0) {
        #pragma unroll
        for (int mf = 0; mf < 2; mf++)
            #pragma unroll
            for (int rr = 0; rr < 2; rr++) {
                int rl = wm * 32 + mf * 16 + rr * 8 + er;
                sm_m[wn * 128 + rl] = mrun[mf][rr];
                sm_s[wn * 128 + rl] = srun[mf][rr];
            }
    }
    __syncthreads();
    if (tid < 128) {
        float ma = sm_m[tid], mb2 = sm_m[128 + tid];
        float m = fmaxf(ma, mb2);
        float s = sm_s[tid] * __expf(ma - m) + sm_s[128 + tid] * __expf(mb2 - m);
        g_rmax[(size_t)bh * SEQ + m0 + tid] = m;
        g_rsum[(size_t)bh * SEQ + m0 + tid] = s;
    }
}

// ---------------------------------------------------------------------------
// Fused attention, pass 2: recompute S, write normalized attn, accumulate
// ctx = P @ V entirely in registers (C-frag == A-frag layout identity).
// ---------------------------------------------------------------------------
#define P2_SMEM (98304 + 2048)

__global__ __launch_bounds__(256) void attn_pass2(float* __restrict__ attn)
{
    extern __shared__ char sm[];
    const uint32_t O_QH = 0, O_QL = 16384, O_KH = 32768, O_KL = 49152,
                   O_VH = 65536, O_VL = 81920;
    uint32_t* sm_mb = (uint32_t*)(sm + 98304);

    int tid = threadIdx.x, w = tid >> 5, l = tid & 31;
    int bh = blockIdx.y, b = bh >> 4, h = bh & 15;
    int m0 = blockIdx.x * 128;
    int wm = w & 3, wn = w >> 2;
    uint32_t sb = smem_u32(sm);

    const __nv_bfloat16* Qh = g_qp_hi + (size_t)b * SEQ * DM + h * HD;
    const __nv_bfloat16* Ql = g_qp_lo + (size_t)b * SEQ * DM + h * HD;
    const __nv_bfloat16* Kh = g_kp_hi + (size_t)b * SEQ * DM + h * HD;
    const __nv_bfloat16* Kl = g_kp_lo + (size_t)b * SEQ * DM + h * HD;
    const __nv_bfloat16* Vh = g_vp_hi + (size_t)b * SEQ * DM + h * HD;
    const __nv_bfloat16* Vl = g_vp_lo + (size_t)b * SEQ * DM + h * HD;

    #pragma unroll
    for (int it = 0; it < 4; it++) {
        int idx = tid + it * 256;
        int row = idx >> 3, c = idx & 7;
        uint32_t so = SWZ(row * 128 + c * 16);
        size_t g = (size_t)(m0 + row) * DM + c * 8;
        *(uint4*)(sm + O_QH + so) = *(const uint4*)(Qh + g);
        *(uint4*)(sm + O_QL + so) = *(const uint4*)(Ql + g);
    }

    int er = l >> 2, ec = (l & 3) * 2;
    const float scale = 0.03125f;

    float rmax[2][2], rinv[2][2];
    #pragma unroll
    for (int mf = 0; mf < 2; mf++)
        #pragma unroll
        for (int rr = 0; rr < 2; rr++) {
            int gm = m0 + wm * 32 + mf * 16 + rr * 8 + er;
            rmax[mf][rr] = g_rmax[(size_t)bh * SEQ + gm];
            rinv[mf][rr] = __frcp_rn(g_rsum[(size_t)bh * SEQ + gm]);
        }

    float ctx[2][8][4] = {};

    for (int nt = 0; nt < 8; nt++) {
        __syncthreads();
        #pragma unroll
        for (int it = 0; it < 4; it++) {
            int idx = tid + it * 256;
            int row = idx >> 3, c = idx & 7;
            uint32_t so = SWZ(row * 128 + c * 16);
            size_t g = (size_t)(nt * 128 + row) * DM + c * 8;
            *(uint4*)(sm + O_KH + so) = *(const uint4*)(Kh + g);
            *(uint4*)(sm + O_KL + so) = *(const uint4*)(Kl + g);
            *(uint4*)(sm + O_VH + so) = *(const uint4*)(Vh + g);
            *(uint4*)(sm + O_VL + so) = *(const uint4*)(Vl + g);
        }
        if (tid < 128)
            *(uint4*)&sm_mb[tid * 4] =
                *(const uint4*)&g_mbits[((size_t)b * SEQ + m0 + tid) * 32 + nt * 4];
        __syncthreads();

        float acc[2][8][4] = {};
        #pragma unroll
        for (int kk = 0; kk < 4; kk++) {
            int ks2 = kk * 32;
            uint32_t ah[2][4], al[2][4], bwh[4][4], bwl[4][4];
            #pragma unroll
            for (int mf = 0; mf < 2; mf++) {
                uint32_t off = SWZ((wm * 32 + mf * 16 + (l & 15)) * 128 + ks2 + (l >> 4) * 16);
                ldm_x4(ah[mf], sb + O_QH + off);
                ldm_x4(al[mf], sb + O_QL + off);
            }
            #pragma unroll
            for (int bp = 0; bp < 4; bp++) {
                uint32_t off = SWZ((wn * 64 + bp * 16 + (l & 7) + ((l >> 4) * 8)) * 128
                                   + ks2 + ((l >> 3) & 1) * 16);
                ldm_x4(bwh[bp], sb + O_KH + off);
                ldm_x4(bwl[bp], sb + O_KL + off);
            }
            #pragma unroll
            for (int mf = 0; mf < 2; mf++)
                #pragma unroll
                for (int nf = 0; nf < 8; nf++) {
                    mma_bf16(acc[mf][nf], ah[mf], &bwh[nf >> 1][(nf & 1) * 2]);
                    mma_bf16(acc[mf][nf], al[mf], &bwh[nf >> 1][(nf & 1) * 2]);
                    mma_bf16(acc[mf][nf], ah[mf], &bwl[nf >> 1][(nf & 1) * 2]);
                }
        }

        // P = exp(s - m) / sum; write attn; keep P in acc
        #pragma unroll
        for (int mf = 0; mf < 2; mf++) {
            #pragma unroll
            for (int rr = 0; rr < 2; rr++) {
                int rl = wm * 32 + mf * 16 + rr * 8 + er;
                int gm = m0 + rl;
                uint32_t w0 = sm_mb[rl * 4 + wn * 2];
                uint32_t w1 = sm_mb[rl * 4 + wn * 2 + 1];
                #pragma unroll
                for (int nf = 0; nf < 8; nf++) {
                    uint32_t word = (nf < 4) ? w0 : w1;
                    int sh = (nf & 3) * 8 + ec;
                    float m0f = ((word >> sh) & 1u) ? -1e9f : 0.0f;
                    float m1f = ((word >> (sh + 1)) & 1u) ? -1e9f : 0.0f;
                    float sv0 = acc[mf][nf][rr * 2]     * scale + m0f;
                    float sv1 = acc[mf][nf][rr * 2 + 1] * scale + m1f;
                    float2 pv;
                    pv.x = __expf(sv0 - rmax[mf][rr]) * rinv[mf][rr];
                    pv.y = __expf(sv1 - rmax[mf][rr]) * rinv[mf][rr];
                    int gn = nt * 128 + wn * 64 + nf * 8 + ec;
                    *(float2*)&attn[((size_t)bh * SEQ + gm) * SEQ + gn] = pv;
                    acc[mf][nf][rr * 2]     = pv.x;
                    acc[mf][nf][rr * 2 + 1] = pv.y;
                }
            }
        }

        // ctx += P @ V   (P frags straight from acc)
        #pragma unroll
        for (int kk = 0; kk < 4; kk++) {
            uint32_t pah[2][4], pal[2][4], bvh[4][4], bvl[4][4];
            #pragma unroll
            for (int mf = 0; mf < 2; mf++) {
                float* a0 = acc[mf][kk * 2];
                float* a1 = acc[mf][kk * 2 + 1];
                pah[mf][0] = pack_bf2(a0[0], a0[1]);
                pah[mf][1] = pack_bf2(a0[2], a0[3]);
                pah[mf][2] = pack_bf2(a1[0], a1[1]);
                pah[mf][3] = pack_bf2(a1[2], a1[3]);
                float h00 = __bfloat162float(__float2bfloat16_rn(a0[0]));
                float h01 = __bfloat162float(__float2bfloat16_rn(a0[1]));
                float h02 = __bfloat162float(__float2bfloat16_rn(a0[2]));
                float h03 = __bfloat162float(__float2bfloat16_rn(a0[3]));
                float h10 = __bfloat162float(__float2bfloat16_rn(a1[0]));
                float h11 = __bfloat162float(__float2bfloat16_rn(a1[1]));
                float h12 = __bfloat162float(__float2bfloat16_rn(a1[2]));
                float h13 = __bfloat162float(__float2bfloat16_rn(a1[3]));
                pal[mf][0] = pack_bf2(a0[0] - h00, a0[1] - h01);
                pal[mf][1] = pack_bf2(a0[2] - h02, a0[3] - h03);
                pal[mf][2] = pack_bf2(a1[0] - h10, a1[1] - h11);
                pal[mf][3] = pack_bf2(a1[2] - h12, a1[3] - h13);
            }
            #pragma unroll
            for (int nb = 0; nb < 4; nb++) {
                uint32_t off = SWZ((wn * 64 + kk * 16 + (l & 15)) * 128
                                   + (nb * 16 + (l >> 4) * 8) * 2);
                ldm_x4t(bvh[nb], sb + O_VH + off);
                ldm_x4t(bvl[nb], sb + O_VL + off);
            }
            #pragma unroll
            for (int mf = 0; mf < 2; mf++)
                #pragma unroll
                for (int nd = 0; nd < 8; nd++) {
                    mma_bf16(ctx[mf][nd], pah[mf], &bvh[nd >> 1][(nd & 1) * 2]);
                    mma_bf16(ctx[mf][nd], pal[mf], &bvh[nd >> 1][(nd & 1) * 2]);
                    mma_bf16(ctx[mf][nd], pah[mf], &bvl[nd >> 1][(nd & 1) * 2]);
                }
        }
    }

    // cross-wn reduce via smem (alias K region), write ctx bf16 hi/lo
    __syncthreads();
    float* red = (float*)(sm + O_KH);   // 128 x 64 fp32
    if (wn == 1) {
        #pragma unroll
        for (int mf = 0; mf < 2; mf++)
            #pragma unroll
            for (int nd = 0; nd < 8; nd++)
                #pragma unroll
                for (int rr = 0; rr < 2; rr++) {
                    int row = wm * 32 + mf * 16 + rr * 8 + er;
                    float2 v;
                    v.x = ctx[mf][nd][rr * 2];
                    v.y = ctx[mf][nd][rr * 2 + 1];
                    *(float2*)&red[row * 64 + nd * 8 + ec] = v;
                }
    }
    __syncthreads();
    if (wn == 0) {
        __nv_bfloat16* Chi = g_c_hi + (size_t)b * SEQ * DM + h * HD;
        __nv_bfloat16* Clo = g_c_lo + (size_t)b * SEQ * DM + h * HD;
        #pragma unroll
        for (int mf = 0; mf < 2; mf++)
            #pragma unroll
            for (int nd = 0; nd < 8; nd++)
                #pragma unroll
                for (int rr = 0; rr < 2; rr++) {
                    int row = wm * 32 + mf * 16 + rr * 8 + er;
                    int col = nd * 8 + ec;
                    float2 o = *(float2*)&red[row * 64 + col];
                    float vx = ctx[mf][nd][rr * 2] + o.x;
                    float vy = ctx[mf][nd][rr * 2 + 1] + o.y;
                    float hx = __bfloat162float(__float2bfloat16_rn(vx));
                    float hy = __bfloat162float(__float2bfloat16_rn(vy));
                    size_t off = (size_t)(m0 + row) * DM + col;
                    *(uint32_t*)&Chi[off] = pack_bf2(vx, vy);
                    *(uint32_t*)&Clo[off] = pack_bf2(vx - hx, vy - hy);
                }
    }
}

// ---------------------------------------------------------------------------
extern "C" void kernel_launch(void* const* d_in, const int* in_sizes, int n_in,
                              void* d_out, int out_size)
{
    const float* q   = (const float*)d_in[0];
    const float* k   = (const float*)d_in[1];
    const float* v   = (const float*)d_in[2];
    const int*  mask = (const int*)d_in[3];
    const float* Wq  = (const float*)d_in[4];
    const float* Wk  = (const float*)d_in[5];
    const float* Wv  = (const float*)d_in[6];
    const float* Wd  = (const float*)d_in[7];
    const float* bd  = (const float*)d_in[8];
    float* out = (float*)d_out;

    const long long out_elems  = (long long)BQ * SEQ * DM;
    const long long attn_elems = (long long)BQ * NH * SEQ * SEQ;
    float* attn;
    if ((long long)out_size >= out_elems + attn_elems) {
        attn = out + out_elems;
    } else {
        cudaGetSymbolAddress((void**)&attn, g_attn);
    }

    cudaFuncSetAttribute(mma_gemm,  cudaFuncAttributeMaxDynamicSharedMemorySize, GEMM_SMEM);
    cudaFuncSetAttribute(attn_pass1, cudaFuncAttributeMaxDynamicSharedMemorySize, P1_SMEM);
    cudaFuncSetAttribute(attn_pass2, cudaFuncAttributeMaxDynamicSharedMemorySize, P2_SMEM);

    __nv_bfloat16 *qh, *ql, *kh, *kl, *vh, *vl, *ch, *cl;
    __nv_bfloat16 *qph, *qpl, *kph, *kpl, *vph, *vpl;
    __nv_bfloat16 *wqh, *wql, *wkh, *wkl, *wvh, *wvl, *wdh, *wdl;
    uint32_t* mb;
    cudaGetSymbolAddress((void**)&qh, g_q_hi);   cudaGetSymbolAddress((void**)&ql, g_q_lo);
    cudaGetSymbolAddress((void**)&kh, g_k_hi);   cudaGetSymbolAddress((void**)&kl, g_k_lo);
    cudaGetSymbolAddress((void**)&vh, g_v_hi);   cudaGetSymbolAddress((void**)&vl, g_v_lo);
    cudaGetSymbolAddress((void**)&ch, g_c_hi);   cudaGetSymbolAddress((void**)&cl, g_c_lo);
    cudaGetSymbolAddress((void**)&qph, g_qp_hi); cudaGetSymbolAddress((void**)&qpl, g_qp_lo);
    cudaGetSymbolAddress((void**)&kph, g_kp_hi); cudaGetSymbolAddress((void**)&kpl, g_kp_lo);
    cudaGetSymbolAddress((void**)&vph, g_vp_hi); cudaGetSymbolAddress((void**)&vpl, g_vp_lo);
    cudaGetSymbolAddress((void**)&wqh, g_wq_hi); cudaGetSymbolAddress((void**)&wql, g_wq_lo);
    cudaGetSymbolAddress((void**)&wkh, g_wk_hi); cudaGetSymbolAddress((void**)&wkl, g_wk_lo);
    cudaGetSymbolAddress((void**)&wvh, g_wv_hi); cudaGetSymbolAddress((void**)&wvl, g_wv_lo);
    cudaGetSymbolAddress((void**)&wdh, g_wd_hi); cudaGetSymbolAddress((void**)&wdl, g_wd_lo);
    cudaGetSymbolAddress((void**)&mb, g_mbits);

    const int NBIG = BQ * SEQ * DM / 4 / 256;
    const int NW   = DM * DM / 4 / 256;
    convert_split<<<NBIG, 256>>>(q, qh, ql);
    convert_split<<<NBIG, 256>>>(k, kh, kl);
    convert_split<<<NBIG, 256>>>(v, vh, vl);
    convert_split<<<NW, 256>>>(Wq, wqh, wql);
    convert_split<<<NW, 256>>>(Wk, wkh, wkl);
    convert_split<<<NW, 256>>>(Wv, wvh, wvl);
    convert_split<<<NW, 256>>>(Wd, wdh, wdl);
    mask_to_bits<<<BQ * SEQ * SEQ / 32 / 256, 256>>>(mask, mb);

    dim3 gg(DM / 128, (BQ * SEQ) / 128);
    mma_gemm<<<gg, 256, GEMM_SMEM>>>(qh, ql, wqh, wql, nullptr, nullptr, qph, qpl);
    mma_gemm<<<gg, 256, GEMM_SMEM>>>(kh, kl, wkh, wkl, nullptr, nullptr, kph, kpl);
    mma_gemm<<<gg, 256, GEMM_SMEM>>>(vh, vl, wvh, wvl, nullptr, nullptr, vph, vpl);

    dim3 ga(SEQ / 128, BQ * NH);
    attn_pass1<<<ga, 256, P1_SMEM>>>();
    attn_pass2<<<ga, 256, P2_SMEM>>>(attn);

    mma_gemm<<<gg, 256, GEMM_SMEM>>>(ch, cl, wdh, wdl, bd, out, nullptr, nullptr);
}

// round 7
// speedup vs baseline: 2.8609x; 1.0006x over previous
#include <cuda_runtime.h>
#include <cuda_bf16.h>
#include <stdint.h>
#include <math.h>

#define BQ  4
#define SEQ 1024
#define DM  1024
#define NH  16
#define HD  64

// ---------------- scratch (no allocations allowed) ----------------
__device__ float g_attn[BQ * NH * SEQ * SEQ];  // fallback if attn not an output
__device__ float g_rmax[BQ * NH * SEQ];
__device__ float g_rsum[BQ * NH * SEQ];
__device__ uint32_t g_mbits[BQ * SEQ * (SEQ / 32)];

__device__ __nv_bfloat16 g_q_hi[BQ * SEQ * DM],  g_q_lo[BQ * SEQ * DM];
__device__ __nv_bfloat16 g_k_hi[BQ * SEQ * DM],  g_k_lo[BQ * SEQ * DM];
__device__ __nv_bfloat16 g_v_hi[BQ * SEQ * DM],  g_v_lo[BQ * SEQ * DM];
__device__ __nv_bfloat16 g_qp_hi[BQ * SEQ * DM], g_qp_lo[BQ * SEQ * DM];
__device__ __nv_bfloat16 g_kp_hi[BQ * SEQ * DM], g_kp_lo[BQ * SEQ * DM];
__device__ __nv_bfloat16 g_vp_hi[BQ * SEQ * DM], g_vp_lo[BQ * SEQ * DM];
__device__ __nv_bfloat16 g_c_hi[BQ * SEQ * DM],  g_c_lo[BQ * SEQ * DM];
__device__ __nv_bfloat16 g_wq_hi[DM * DM], g_wq_lo[DM * DM];
__device__ __nv_bfloat16 g_wk_hi[DM * DM], g_wk_lo[DM * DM];
__device__ __nv_bfloat16 g_wv_hi[DM * DM], g_wv_lo[DM * DM];
__device__ __nv_bfloat16 g_wd_hi[DM * DM], g_wd_lo[DM * DM];

#define SWZ(o) ((o) ^ (((o) >> 3) & 0x70))

__device__ __forceinline__ uint32_t smem_u32(const void* p) {
    uint32_t a;
    asm("{ .reg .u64 t; cvta.to.shared.u64 t, %1; cvt.u32.u64 %0, t; }" : "=r"(a) : "l"(p));
    return a;
}
__device__ __forceinline__ void ldm_x4(uint32_t* r, uint32_t addr) {
    asm volatile("ldmatrix.sync.aligned.m8n8.x4.shared.b16 {%0,%1,%2,%3}, [%4];"
        : "=r"(r[0]), "=r"(r[1]), "=r"(r[2]), "=r"(r[3]) : "r"(addr));
}
__device__ __forceinline__ void ldm_x4t(uint32_t* r, uint32_t addr) {
    asm volatile("ldmatrix.sync.aligned.m8n8.x4.trans.shared.b16 {%0,%1,%2,%3}, [%4];"
        : "=r"(r[0]), "=r"(r[1]), "=r"(r[2]), "=r"(r[3]) : "r"(addr));
}
__device__ __forceinline__ void mma_bf16(float* d, const uint32_t* a, const uint32_t* b) {
    asm volatile(
        "mma.sync.aligned.m16n8k16.row.col.f32.bf16.bf16.f32 "
        "{%0,%1,%2,%3}, {%4,%5,%6,%7}, {%8,%9}, {%0,%1,%2,%3};"
        : "+f"(d[0]), "+f"(d[1]), "+f"(d[2]), "+f"(d[3])
        : "r"(a[0]), "r"(a[1]), "r"(a[2]), "r"(a[3]), "r"(b[0]), "r"(b[1]));
}
#define CP16(dst, src) asm volatile("cp.async.cg.shared.global [%0], [%1], 16;" :: "r"(dst), "l"(src))
#define CP_COMMIT()    asm volatile("cp.async.commit_group;" ::: "memory")
#define CP_WAIT0()     asm volatile("cp.async.wait_group 0;" ::: "memory")
#define CP_WAIT1()     asm volatile("cp.async.wait_group 1;" ::: "memory")

__device__ __forceinline__ uint32_t pack_bf2(float x, float y) {
    __nv_bfloat162 t(__float2bfloat16_rn(x), __float2bfloat16_rn(y));
    return *(uint32_t*)&t;
}

// ---------------------------------------------------------------------------
__global__ __launch_bounds__(256) void convert_split(
    const float* __restrict__ x,
    __nv_bfloat16* __restrict__ hi, __nv_bfloat16* __restrict__ lo)
{
    int i = blockIdx.x * 256 + threadIdx.x;
    float4 v = ((const float4*)x)[i];
    __nv_bfloat16 h0 = __float2bfloat16_rn(v.x);
    __nv_bfloat16 h1 = __float2bfloat16_rn(v.y);
    __nv_bfloat16 h2 = __float2bfloat16_rn(v.z);
    __nv_bfloat16 h3 = __float2bfloat16_rn(v.w);
    __nv_bfloat16 l0 = __float2bfloat16_rn(v.x - __bfloat162float(h0));
    __nv_bfloat16 l1 = __float2bfloat16_rn(v.y - __bfloat162float(h1));
    __nv_bfloat16 l2 = __float2bfloat16_rn(v.z - __bfloat162float(h2));
    __nv_bfloat16 l3 = __float2bfloat16_rn(v.w - __bfloat162float(h3));
    __nv_bfloat162* hp = (__nv_bfloat162*)(hi + (size_t)i * 4);
    __nv_bfloat162* lp = (__nv_bfloat162*)(lo + (size_t)i * 4);
    hp[0] = __nv_bfloat162(h0, h1); hp[1] = __nv_bfloat162(h2, h3);
    lp[0] = __nv_bfloat162(l0, l1); lp[1] = __nv_bfloat162(l2, l3);
}

// int32 mask -> packed bits (1 = masked)
__global__ __launch_bounds__(256) void mask_to_bits(
    const int* __restrict__ mask, uint32_t* __restrict__ bits)
{
    int w = blockIdx.x * 256 + threadIdx.x;
    const int* p = mask + (size_t)w * 32;
    uint32_t word = 0;
    #pragma unroll
    for (int j = 0; j < 8; j++) {
        int4 v = ((const int4*)p)[j];
        word |= (v.x ? 1u : 0u) << (j * 4 + 0);
        word |= (v.y ? 1u : 0u) << (j * 4 + 1);
        word |= (v.z ? 1u : 0u) << (j * 4 + 2);
        word |= (v.w ? 1u : 0u) << (j * 4 + 3);
    }
    bits[w] = word;
}

// ---------------------------------------------------------------------------
// mma.sync bf16 GEMM, 2-stage cp.async pipeline (unchanged from R5).
// ---------------------------------------------------------------------------
#define GEMM_SMEM (2 * 65536)

__global__ __launch_bounds__(256) void mma_gemm(
    const __nv_bfloat16* __restrict__ Ahi, const __nv_bfloat16* __restrict__ Alo,
    const __nv_bfloat16* __restrict__ Whi, const __nv_bfloat16* __restrict__ Wlo,
    const float* __restrict__ bias, float* __restrict__ Cf32,
    __nv_bfloat16* __restrict__ Chi, __nv_bfloat16* __restrict__ Clo)
{
    extern __shared__ char sm[];
    const int K = DM, N = DM;
    const uint32_t O_AHI = 0, O_ALO = 16384, O_WHI = 32768, O_WLO = 49152;

    int tid = threadIdx.x, w = tid >> 5, l = tid & 31;
    int m0 = blockIdx.y * 128, n0 = blockIdx.x * 128;
    int wm = w & 1, wn = w >> 1;

    uint32_t sb = smem_u32(sm);

    int a_row = wm * 64 + (l & 15);
    int a_k2  = (l >> 4) * 16;
    int b_row = wn * 32 + (l & 7) + ((l >> 4) * 8);
    int b_k2  = ((l >> 3) & 1) * 16;

    int lrow = tid >> 3;
    int lc   = tid & 7;

    float acc[4][4][4] = {};
    const int NK = K / 64;

    auto load_stage = [&](int s, int kc) {
        uint32_t base = sb + (uint32_t)s * 65536;
        #pragma unroll
        for (int it = 0; it < 4; it++) {
            int row = lrow + it * 32;
            size_t ga = (size_t)(m0 + row) * K + kc * 64 + lc * 8;
            size_t gw = (size_t)(n0 + row) * K + kc * 64 + lc * 8;
            uint32_t so = SWZ(row * 128 + lc * 16);
            CP16(base + O_AHI + so, Ahi + ga);
            CP16(base + O_ALO + so, Alo + ga);
            CP16(base + O_WHI + so, Whi + gw);
            CP16(base + O_WLO + so, Wlo + gw);
        }
        CP_COMMIT();
    };

    load_stage(0, 0);

    for (int kc = 0; kc < NK; kc++) {
        if (kc + 1 < NK) { load_stage((kc + 1) & 1, kc + 1); CP_WAIT1(); }
        else             { CP_WAIT0(); }
        __syncthreads();

        uint32_t st = sb + (uint32_t)(kc & 1) * 65536;
        #pragma unroll
        for (int kk = 0; kk < 4; kk++) {
            int ks2 = kk * 32;
            uint32_t ah[4][4], al[4][4], bw[2][4];
            #pragma unroll
            for (int mf = 0; mf < 4; mf++) {
                uint32_t off = SWZ((a_row + mf * 16) * 128 + ks2 + a_k2);
                ldm_x4(ah[mf], st + O_AHI + off);
                ldm_x4(al[mf], st + O_ALO + off);
            }
            #pragma unroll
            for (int bp = 0; bp < 2; bp++) {
                uint32_t off = SWZ((b_row + bp * 16) * 128 + ks2 + b_k2);
                ldm_x4(bw[bp], st + O_WHI + off);
            }
            #pragma unroll
            for (int mf = 0; mf < 4; mf++)
                #pragma unroll
                for (int nf = 0; nf < 4; nf++)
                    mma_bf16(acc[mf][nf], ah[mf], &bw[nf >> 1][(nf & 1) * 2]);
            #pragma unroll
            for (int mf = 0; mf < 4; mf++)
                #pragma unroll
                for (int nf = 0; nf < 4; nf++)
                    mma_bf16(acc[mf][nf], al[mf], &bw[nf >> 1][(nf & 1) * 2]);
            #pragma unroll
            for (int bp = 0; bp < 2; bp++) {
                uint32_t off = SWZ((b_row + bp * 16) * 128 + ks2 + b_k2);
                ldm_x4(bw[bp], st + O_WLO + off);
            }
            #pragma unroll
            for (int mf = 0; mf < 4; mf++)
                #pragma unroll
                for (int nf = 0; nf < 4; nf++)
                    mma_bf16(acc[mf][nf], ah[mf], &bw[nf >> 1][(nf & 1) * 2]);
        }
        __syncthreads();
    }

    int er = l >> 2, ec = (l & 3) * 2;
    #pragma unroll
    for (int mf = 0; mf < 4; mf++) {
        #pragma unroll
        for (int nf = 0; nf < 4; nf++) {
            int gm = m0 + wm * 64 + mf * 16 + er;
            int gn = n0 + wn * 32 + nf * 8 + ec;
            if (Cf32) {
                float b0 = bias ? bias[gn] : 0.0f;
                float b1 = bias ? bias[gn + 1] : 0.0f;
                float2 v0, v1;
                v0.x = acc[mf][nf][0] + b0; v0.y = acc[mf][nf][1] + b1;
                v1.x = acc[mf][nf][2] + b0; v1.y = acc[mf][nf][3] + b1;
                *(float2*)&Cf32[(size_t)gm * N + gn]       = v0;
                *(float2*)&Cf32[(size_t)(gm + 8) * N + gn] = v1;
            } else {
                #pragma unroll
                for (int rr = 0; rr < 2; rr++) {
                    float vx = acc[mf][nf][rr * 2], vy = acc[mf][nf][rr * 2 + 1];
                    float hx = __bfloat162float(__float2bfloat16_rn(vx));
                    float hy = __bfloat162float(__float2bfloat16_rn(vy));
                    size_t o = (size_t)(gm + rr * 8) * N + gn;
                    *(uint32_t*)&Chi[o] = pack_bf2(vx, vy);
                    *(uint32_t*)&Clo[o] = pack_bf2(vx - hx, vy - hy);
                }
            }
        }
    }
}

// ---------------------------------------------------------------------------
// Fused attention, pass 1: per (bh, 128-row tile), online row (max, sum)
// over all 1024 keys. 8 warps: wm=w&3 (32-row group), wn=w>>2 (64-key half).
// ---------------------------------------------------------------------------
#define P1_SMEM (65536 + 2048 + 2048)

__global__ __launch_bounds__(256) void attn_pass1()
{
    extern __shared__ char sm[];
    const uint32_t O_QH = 0, O_QL = 16384, O_KH = 32768, O_KL = 49152;
    uint32_t* sm_mb = (uint32_t*)(sm + 65536);       // 128 x 4 words
    float* sm_m = (float*)(sm + 65536 + 2048);       // 2 x 128
    float* sm_s = sm_m + 256;

    int tid = threadIdx.x, w = tid >> 5, l = tid & 31;
    int bh = blockIdx.y, b = bh >> 4, h = bh & 15;
    int m0 = blockIdx.x * 128;
    int wm = w & 3, wn = w >> 2;
    uint32_t sb = smem_u32(sm);

    const __nv_bfloat16* Qh = g_qp_hi + (size_t)b * SEQ * DM + h * HD;
    const __nv_bfloat16* Ql = g_qp_lo + (size_t)b * SEQ * DM + h * HD;
    const __nv_bfloat16* Kh = g_kp_hi + (size_t)b * SEQ * DM + h * HD;
    const __nv_bfloat16* Kl = g_kp_lo + (size_t)b * SEQ * DM + h * HD;

    // Q tile (persistent)
    #pragma unroll
    for (int it = 0; it < 4; it++) {
        int idx = tid + it * 256;
        int row = idx >> 3, c = idx & 7;
        uint32_t so = SWZ(row * 128 + c * 16);
        size_t g = (size_t)(m0 + row) * DM + c * 8;
        *(uint4*)(sm + O_QH + so) = *(const uint4*)(Qh + g);
        *(uint4*)(sm + O_QL + so) = *(const uint4*)(Ql + g);
    }

    float mrun[2][2] = {{-1e30f, -1e30f}, {-1e30f, -1e30f}};
    float srun[2][2] = {};
    const float scale = 0.03125f;
    int er = l >> 2, ec = (l & 3) * 2;

    for (int nt = 0; nt < 8; nt++) {
        __syncthreads();
        #pragma unroll
        for (int it = 0; it < 4; it++) {
            int idx = tid + it * 256;
            int row = idx >> 3, c = idx & 7;
            uint32_t so = SWZ(row * 128 + c * 16);
            size_t g = (size_t)(nt * 128 + row) * DM + c * 8;
            *(uint4*)(sm + O_KH + so) = *(const uint4*)(Kh + g);
            *(uint4*)(sm + O_KL + so) = *(const uint4*)(Kl + g);
        }
        if (tid < 128)
            *(uint4*)&sm_mb[tid * 4] =
                *(const uint4*)&g_mbits[((size_t)b * SEQ + m0 + tid) * 32 + nt * 4];
        __syncthreads();

        float acc[2][8][4] = {};
        #pragma unroll
        for (int kk = 0; kk < 4; kk++) {
            int ks2 = kk * 32;
            uint32_t ah[2][4], al[2][4], bwh[4][4], bwl[4][4];
            #pragma unroll
            for (int mf = 0; mf < 2; mf++) {
                uint32_t off = SWZ((wm * 32 + mf * 16 + (l & 15)) * 128 + ks2 + (l >> 4) * 16);
                ldm_x4(ah[mf], sb + O_QH + off);
                ldm_x4(al[mf], sb + O_QL + off);
            }
            #pragma unroll
            for (int bp = 0; bp < 4; bp++) {
                uint32_t off = SWZ((wn * 64 + bp * 16 + (l & 7) + ((l >> 4) * 8)) * 128
                                   + ks2 + ((l >> 3) & 1) * 16);
                ldm_x4(bwh[bp], sb + O_KH + off);
                ldm_x4(bwl[bp], sb + O_KL + off);
            }
            #pragma unroll
            for (int mf = 0; mf < 2; mf++)
                #pragma unroll
                for (int nf = 0; nf < 8; nf++) {
                    mma_bf16(acc[mf][nf], ah[mf], &bwh[nf >> 1][(nf & 1) * 2]);
                    mma_bf16(acc[mf][nf], al[mf], &bwh[nf >> 1][(nf & 1) * 2]);
                    mma_bf16(acc[mf][nf], ah[mf], &bwl[nf >> 1][(nf & 1) * 2]);
                }
        }

        // online stats
        #pragma unroll
        for (int mf = 0; mf < 2; mf++) {
            #pragma unroll
            for (int rr = 0; rr < 2; rr++) {
                int rl = wm * 32 + mf * 16 + rr * 8 + er;
                uint32_t w0 = sm_mb[rl * 4 + wn * 2];
                uint32_t w1 = sm_mb[rl * 4 + wn * 2 + 1];
                float v[16];
                float tmax = -1e30f;
                #pragma unroll
                for (int nf = 0; nf < 8; nf++) {
                    uint32_t word = (nf < 4) ? w0 : w1;
                    int sh = (nf & 3) * 8 + ec;
                    float m0f = ((word >> sh) & 1u) ? -1e9f : 0.0f;
                    float m1f = ((word >> (sh + 1)) & 1u) ? -1e9f : 0.0f;
                    v[nf * 2]     = acc[mf][nf][rr * 2]     * scale + m0f;
                    v[nf * 2 + 1] = acc[mf][nf][rr * 2 + 1] * scale + m1f;
                    tmax = fmaxf(tmax, fmaxf(v[nf * 2], v[nf * 2 + 1]));
                }
                tmax = fmaxf(tmax, __shfl_xor_sync(0xffffffffu, tmax, 1));
                tmax = fmaxf(tmax, __shfl_xor_sync(0xffffffffu, tmax, 2));
                float nm = fmaxf(mrun[mf][rr], tmax);
                float ts = 0.0f;
                #pragma unroll
                for (int i = 0; i < 16; i++) ts += __expf(v[i] - nm);
                ts += __shfl_xor_sync(0xffffffffu, ts, 1);
                ts += __shfl_xor_sync(0xffffffffu, ts, 2);
                srun[mf][rr] = srun[mf][rr] * __expf(mrun[mf][rr] - nm) + ts;
                mrun[mf][rr] = nm;
            }
        }
    }

    if ((l & 3) == 0) {
        #pragma unroll
        for (int mf = 0; mf < 2; mf++)
            #pragma unroll
            for (int rr = 0; rr < 2; rr++) {
                int rl = wm * 32 + mf * 16 + rr * 8 + er;
                sm_m[wn * 128 + rl] = mrun[mf][rr];
                sm_s[wn * 128 + rl] = srun[mf][rr];
            }
    }
    __syncthreads();
    if (tid < 128) {
        float ma = sm_m[tid], mb2 = sm_m[128 + tid];
        float m = fmaxf(ma, mb2);
        float s = sm_s[tid] * __expf(ma - m) + sm_s[128 + tid] * __expf(mb2 - m);
        g_rmax[(size_t)bh * SEQ + m0 + tid] = m;
        g_rsum[(size_t)bh * SEQ + m0 + tid] = s;
    }
}

// ---------------------------------------------------------------------------
// Fused attention, pass 2: recompute S, write normalized attn, accumulate
// ctx = P @ V entirely in registers (C-frag == A-frag layout identity).
// ---------------------------------------------------------------------------
#define P2_SMEM (98304 + 2048)

__global__ __launch_bounds__(256) void attn_pass2(float* __restrict__ attn)
{
    extern __shared__ char sm[];
    const uint32_t O_QH = 0, O_QL = 16384, O_KH = 32768, O_KL = 49152,
                   O_VH = 65536, O_VL = 81920;
    uint32_t* sm_mb = (uint32_t*)(sm + 98304);

    int tid = threadIdx.x, w = tid >> 5, l = tid & 31;
    int bh = blockIdx.y, b = bh >> 4, h = bh & 15;
    int m0 = blockIdx.x * 128;
    int wm = w & 3, wn = w >> 2;
    uint32_t sb = smem_u32(sm);

    const __nv_bfloat16* Qh = g_qp_hi + (size_t)b * SEQ * DM + h * HD;
    const __nv_bfloat16* Ql = g_qp_lo + (size_t)b * SEQ * DM + h * HD;
    const __nv_bfloat16* Kh = g_kp_hi + (size_t)b * SEQ * DM + h * HD;
    const __nv_bfloat16* Kl = g_kp_lo + (size_t)b * SEQ * DM + h * HD;
    const __nv_bfloat16* Vh = g_vp_hi + (size_t)b * SEQ * DM + h * HD;
    const __nv_bfloat16* Vl = g_vp_lo + (size_t)b * SEQ * DM + h * HD;

    #pragma unroll
    for (int it = 0; it < 4; it++) {
        int idx = tid + it * 256;
        int row = idx >> 3, c = idx & 7;
        uint32_t so = SWZ(row * 128 + c * 16);
        size_t g = (size_t)(m0 + row) * DM + c * 8;
        *(uint4*)(sm + O_QH + so) = *(const uint4*)(Qh + g);
        *(uint4*)(sm + O_QL + so) = *(const uint4*)(Ql + g);
    }

    int er = l >> 2, ec = (l & 3) * 2;
    const float scale = 0.03125f;

    float rmax[2][2], rinv[2][2];
    #pragma unroll
    for (int mf = 0; mf < 2; mf++)
        #pragma unroll
        for (int rr = 0; rr < 2; rr++) {
            int gm = m0 + wm * 32 + mf * 16 + rr * 8 + er;
            rmax[mf][rr] = g_rmax[(size_t)bh * SEQ + gm];
            rinv[mf][rr] = __frcp_rn(g_rsum[(size_t)bh * SEQ + gm]);
        }

    float ctx[2][8][4] = {};

    for (int nt = 0; nt < 8; nt++) {
        __syncthreads();
        #pragma unroll
        for (int it = 0; it < 4; it++) {
            int idx = tid + it * 256;
            int row = idx >> 3, c = idx & 7;
            uint32_t so = SWZ(row * 128 + c * 16);
            size_t g = (size_t)(nt * 128 + row) * DM + c * 8;
            *(uint4*)(sm + O_KH + so) = *(const uint4*)(Kh + g);
            *(uint4*)(sm + O_KL + so) = *(const uint4*)(Kl + g);
            *(uint4*)(sm + O_VH + so) = *(const uint4*)(Vh + g);
            *(uint4*)(sm + O_VL + so) = *(const uint4*)(Vl + g);
        }
        if (tid < 128)
            *(uint4*)&sm_mb[tid * 4] =
                *(const uint4*)&g_mbits[((size_t)b * SEQ + m0 + tid) * 32 + nt * 4];
        __syncthreads();

        float acc[2][8][4] = {};
        #pragma unroll
        for (int kk = 0; kk < 4; kk++) {
            int ks2 = kk * 32;
            uint32_t ah[2][4], al[2][4], bwh[4][4], bwl[4][4];
            #pragma unroll
            for (int mf = 0; mf < 2; mf++) {
                uint32_t off = SWZ((wm * 32 + mf * 16 + (l & 15)) * 128 + ks2 + (l >> 4) * 16);
                ldm_x4(ah[mf], sb + O_QH + off);
                ldm_x4(al[mf], sb + O_QL + off);
            }
            #pragma unroll
            for (int bp = 0; bp < 4; bp++) {
                uint32_t off = SWZ((wn * 64 + bp * 16 + (l & 7) + ((l >> 4) * 8)) * 128
                                   + ks2 + ((l >> 3) & 1) * 16);
                ldm_x4(bwh[bp], sb + O_KH + off);
                ldm_x4(bwl[bp], sb + O_KL + off);
            }
            #pragma unroll
            for (int mf = 0; mf < 2; mf++)
                #pragma unroll
                for (int nf = 0; nf < 8; nf++) {
                    mma_bf16(acc[mf][nf], ah[mf], &bwh[nf >> 1][(nf & 1) * 2]);
                    mma_bf16(acc[mf][nf], al[mf], &bwh[nf >> 1][(nf & 1) * 2]);
                    mma_bf16(acc[mf][nf], ah[mf], &bwl[nf >> 1][(nf & 1) * 2]);
                }
        }

        // P = exp(s - m) / sum; write attn; keep P in acc
        #pragma unroll
        for (int mf = 0; mf < 2; mf++) {
            #pragma unroll
            for (int rr = 0; rr < 2; rr++) {
                int rl = wm * 32 + mf * 16 + rr * 8 + er;
                int gm = m0 + rl;
                uint32_t w0 = sm_mb[rl * 4 + wn * 2];
                uint32_t w1 = sm_mb[rl * 4 + wn * 2 + 1];
                #pragma unroll
                for (int nf = 0; nf < 8; nf++) {
                    uint32_t word = (nf < 4) ? w0 : w1;
                    int sh = (nf & 3) * 8 + ec;
                    float m0f = ((word >> sh) & 1u) ? -1e9f : 0.0f;
                    float m1f = ((word >> (sh + 1)) & 1u) ? -1e9f : 0.0f;
                    float sv0 = acc[mf][nf][rr * 2]     * scale + m0f;
                    float sv1 = acc[mf][nf][rr * 2 + 1] * scale + m1f;
                    float2 pv;
                    pv.x = __expf(sv0 - rmax[mf][rr]) * rinv[mf][rr];
                    pv.y = __expf(sv1 - rmax[mf][rr]) * rinv[mf][rr];
                    int gn = nt * 128 + wn * 64 + nf * 8 + ec;
                    *(float2*)&attn[((size_t)bh * SEQ + gm) * SEQ + gn] = pv;
                    acc[mf][nf][rr * 2]     = pv.x;
                    acc[mf][nf][rr * 2 + 1] = pv.y;
                }
            }
        }

        // ctx += P @ V   (P frags straight from acc)
        #pragma unroll
        for (int kk = 0; kk < 4; kk++) {
            uint32_t pah[2][4], pal[2][4], bvh[4][4], bvl[4][4];
            #pragma unroll
            for (int mf = 0; mf < 2; mf++) {
                float* a0 = acc[mf][kk * 2];
                float* a1 = acc[mf][kk * 2 + 1];
                pah[mf][0] = pack_bf2(a0[0], a0[1]);
                pah[mf][1] = pack_bf2(a0[2], a0[3]);
                pah[mf][2] = pack_bf2(a1[0], a1[1]);
                pah[mf][3] = pack_bf2(a1[2], a1[3]);
                float h00 = __bfloat162float(__float2bfloat16_rn(a0[0]));
                float h01 = __bfloat162float(__float2bfloat16_rn(a0[1]));
                float h02 = __bfloat162float(__float2bfloat16_rn(a0[2]));
                float h03 = __bfloat162float(__float2bfloat16_rn(a0[3]));
                float h10 = __bfloat162float(__float2bfloat16_rn(a1[0]));
                float h11 = __bfloat162float(__float2bfloat16_rn(a1[1]));
                float h12 = __bfloat162float(__float2bfloat16_rn(a1[2]));
                float h13 = __bfloat162float(__float2bfloat16_rn(a1[3]));
                pal[mf][0] = pack_bf2(a0[0] - h00, a0[1] - h01);
                pal[mf][1] = pack_bf2(a0[2] - h02, a0[3] - h03);
                pal[mf][2] = pack_bf2(a1[0] - h10, a1[1] - h11);
                pal[mf][3] = pack_bf2(a1[2] - h12, a1[3] - h13);
            }
            #pragma unroll
            for (int nb = 0; nb < 4; nb++) {
                uint32_t off = SWZ((wn * 64 + kk * 16 + (l & 15)) * 128
                                   + (nb * 16 + (l >> 4) * 8) * 2);
                ldm_x4t(bvh[nb], sb + O_VH + off);
                ldm_x4t(bvl[nb], sb + O_VL + off);
            }
            #pragma unroll
            for (int mf = 0; mf < 2; mf++)
                #pragma unroll
                for (int nd = 0; nd < 8; nd++) {
                    mma_bf16(ctx[mf][nd], pah[mf], &bvh[nd >> 1][(nd & 1) * 2]);
                    mma_bf16(ctx[mf][nd], pal[mf], &bvh[nd >> 1][(nd & 1) * 2]);
                    mma_bf16(ctx[mf][nd], pah[mf], &bvl[nd >> 1][(nd & 1) * 2]);
                }
        }
    }

    // cross-wn reduce via smem (alias K region), write ctx bf16 hi/lo
    __syncthreads();
    float* red = (float*)(sm + O_KH);   // 128 x 64 fp32
    if (wn == 1) {
        #pragma unroll
        for (int mf = 0; mf < 2; mf++)
            #pragma unroll
            for (int nd = 0; nd < 8; nd++)
                #pragma unroll
                for (int rr = 0; rr < 2; rr++) {
                    int row = wm * 32 + mf * 16 + rr * 8 + er;
                    float2 v;
                    v.x = ctx[mf][nd][rr * 2];
                    v.y = ctx[mf][nd][rr * 2 + 1];
                    *(float2*)&red[row * 64 + nd * 8 + ec] = v;
                }
    }
    __syncthreads();
    if (wn == 0) {
        __nv_bfloat16* Chi = g_c_hi + (size_t)b * SEQ * DM + h * HD;
        __nv_bfloat16* Clo = g_c_lo + (size_t)b * SEQ * DM + h * HD;
        #pragma unroll
        for (int mf = 0; mf < 2; mf++)
            #pragma unroll
            for (int nd = 0; nd < 8; nd++)
                #pragma unroll
                for (int rr = 0; rr < 2; rr++) {
                    int row = wm * 32 + mf * 16 + rr * 8 + er;
                    int col = nd * 8 + ec;
                    float2 o = *(float2*)&red[row * 64 + col];
                    float vx = ctx[mf][nd][rr * 2] + o.x;
                    float vy = ctx[mf][nd][rr * 2 + 1] + o.y;
                    float hx = __bfloat162float(__float2bfloat16_rn(vx));
                    float hy = __bfloat162float(__float2bfloat16_rn(vy));
                    size_t off = (size_t)(m0 + row) * DM + col;
                    *(uint32_t*)&Chi[off] = pack_bf2(vx, vy);
                    *(uint32_t*)&Clo[off] = pack_bf2(vx - hx, vy - hy);
                }
    }
}

// ---------------------------------------------------------------------------
extern "C" void kernel_launch(void* const* d_in, const int* in_sizes, int n_in,
                              void* d_out, int out_size)
{
    const float* q   = (const float*)d_in[0];
    const float* k   = (const float*)d_in[1];
    const float* v   = (const float*)d_in[2];
    const int*  mask = (const int*)d_in[3];
    const float* Wq  = (const float*)d_in[4];
    const float* Wk  = (const float*)d_in[5];
    const float* Wv  = (const float*)d_in[6];
    const float* Wd  = (const float*)d_in[7];
    const float* bd  = (const float*)d_in[8];
    float* out = (float*)d_out;

    const long long out_elems  = (long long)BQ * SEQ * DM;
    const long long attn_elems = (long long)BQ * NH * SEQ * SEQ;
    float* attn;
    if ((long long)out_size >= out_elems + attn_elems) {
        attn = out + out_elems;
    } else {
        cudaGetSymbolAddress((void**)&attn, g_attn);
    }

    cudaFuncSetAttribute(mma_gemm,  cudaFuncAttributeMaxDynamicSharedMemorySize, GEMM_SMEM);
    cudaFuncSetAttribute(attn_pass1, cudaFuncAttributeMaxDynamicSharedMemorySize, P1_SMEM);
    cudaFuncSetAttribute(attn_pass2, cudaFuncAttributeMaxDynamicSharedMemorySize, P2_SMEM);

    __nv_bfloat16 *qh, *ql, *kh, *kl, *vh, *vl, *ch, *cl;
    __nv_bfloat16 *qph, *qpl, *kph, *kpl, *vph, *vpl;
    __nv_bfloat16 *wqh, *wql, *wkh, *wkl, *wvh, *wvl, *wdh, *wdl;
    uint32_t* mb;
    cudaGetSymbolAddress((void**)&qh, g_q_hi);   cudaGetSymbolAddress((void**)&ql, g_q_lo);
    cudaGetSymbolAddress((void**)&kh, g_k_hi);   cudaGetSymbolAddress((void**)&kl, g_k_lo);
    cudaGetSymbolAddress((void**)&vh, g_v_hi);   cudaGetSymbolAddress((void**)&vl, g_v_lo);
    cudaGetSymbolAddress((void**)&ch, g_c_hi);   cudaGetSymbolAddress((void**)&cl, g_c_lo);
    cudaGetSymbolAddress((void**)&qph, g_qp_hi); cudaGetSymbolAddress((void**)&qpl, g_qp_lo);
    cudaGetSymbolAddress((void**)&kph, g_kp_hi); cudaGetSymbolAddress((void**)&kpl, g_kp_lo);
    cudaGetSymbolAddress((void**)&vph, g_vp_hi); cudaGetSymbolAddress((void**)&vpl, g_vp_lo);
    cudaGetSymbolAddress((void**)&wqh, g_wq_hi); cudaGetSymbolAddress((void**)&wql, g_wq_lo);
    cudaGetSymbolAddress((void**)&wkh, g_wk_hi); cudaGetSymbolAddress((void**)&wkl, g_wk_lo);
    cudaGetSymbolAddress((void**)&wvh, g_wv_hi); cudaGetSymbolAddress((void**)&wvl, g_wv_lo);
    cudaGetSymbolAddress((void**)&wdh, g_wd_hi); cudaGetSymbolAddress((void**)&wdl, g_wd_lo);
    cudaGetSymbolAddress((void**)&mb, g_mbits);

    const int NBIG = BQ * SEQ * DM / 4 / 256;
    const int NW   = DM * DM / 4 / 256;
    convert_split<<<NBIG, 256>>>(q, qh, ql);
    convert_split<<<NBIG, 256>>>(k, kh, kl);
    convert_split<<<NBIG, 256>>>(v, vh, vl);
    convert_split<<<NW, 256>>>(Wq, wqh, wql);
    convert_split<<<NW, 256>>>(Wk, wkh, wkl);
    convert_split<<<NW, 256>>>(Wv, wvh, wvl);
    convert_split<<<NW, 256>>>(Wd, wdh, wdl);
    mask_to_bits<<<BQ * SEQ * SEQ / 32 / 256, 256>>>(mask, mb);

    dim3 gg(DM / 128, (BQ * SEQ) / 128);
    mma_gemm<<<gg, 256, GEMM_SMEM>>>(qh, ql, wqh, wql, nullptr, nullptr, qph, qpl);
    mma_gemm<<<gg, 256, GEMM_SMEM>>>(kh, kl, wkh, wkl, nullptr, nullptr, kph, kpl);
    mma_gemm<<<gg, 256, GEMM_SMEM>>>(vh, vl, wvh, wvl, nullptr, nullptr, vph, vpl);

    dim3 ga(SEQ / 128, BQ * NH);
    attn_pass1<<<ga, 256, P1_SMEM>>>();
    attn_pass2<<<ga, 256, P2_SMEM>>>(attn);

    mma_gemm<<<gg, 256, GEMM_SMEM>>>(ch, cl, wdh, wdl, bd, out, nullptr, nullptr);
}

// round 8
// speedup vs baseline: 3.1595x; 1.1044x over previous
#include <cuda_runtime.h>
#include <cuda_bf16.h>
#include <stdint.h>
#include <math.h>

#define BQ  4
#define SEQ 1024
#define DM  1024
#define NH  16
#define HD  64

// ---------------- scratch (no allocations allowed) ----------------
__device__ float g_attn[BQ * NH * SEQ * SEQ];  // fallback if attn not an output
__device__ float g_rmax[BQ * NH * SEQ];
__device__ float g_rsum[BQ * NH * SEQ];
__device__ uint32_t g_mbits[BQ * SEQ * (SEQ / 32)];

__device__ __nv_bfloat16 g_q_hi[BQ * SEQ * DM],  g_q_lo[BQ * SEQ * DM];
__device__ __nv_bfloat16 g_k_hi[BQ * SEQ * DM],  g_k_lo[BQ * SEQ * DM];
__device__ __nv_bfloat16 g_v_hi[BQ * SEQ * DM],  g_v_lo[BQ * SEQ * DM];
__device__ __nv_bfloat16 g_qp_hi[BQ * SEQ * DM], g_qp_lo[BQ * SEQ * DM];
__device__ __nv_bfloat16 g_kp_hi[BQ * SEQ * DM], g_kp_lo[BQ * SEQ * DM];
__device__ __nv_bfloat16 g_vp_hi[BQ * SEQ * DM], g_vp_lo[BQ * SEQ * DM];
__device__ __nv_bfloat16 g_c_hi[BQ * SEQ * DM],  g_c_lo[BQ * SEQ * DM];
__device__ __nv_bfloat16 g_wq_hi[DM * DM], g_wq_lo[DM * DM];
__device__ __nv_bfloat16 g_wk_hi[DM * DM], g_wk_lo[DM * DM];
__device__ __nv_bfloat16 g_wv_hi[DM * DM], g_wv_lo[DM * DM];
__device__ __nv_bfloat16 g_wd_hi[DM * DM], g_wd_lo[DM * DM];

#define SWZ(o) ((o) ^ (((o) >> 3) & 0x70))

__device__ __forceinline__ uint32_t smem_u32(const void* p) {
    uint32_t a;
    asm("{ .reg .u64 t; cvta.to.shared.u64 t, %1; cvt.u32.u64 %0, t; }" : "=r"(a) : "l"(p));
    return a;
}
__device__ __forceinline__ void ldm_x4(uint32_t* r, uint32_t addr) {
    asm volatile("ldmatrix.sync.aligned.m8n8.x4.shared.b16 {%0,%1,%2,%3}, [%4];"
        : "=r"(r[0]), "=r"(r[1]), "=r"(r[2]), "=r"(r[3]) : "r"(addr));
}
__device__ __forceinline__ void ldm_x4t(uint32_t* r, uint32_t addr) {
    asm volatile("ldmatrix.sync.aligned.m8n8.x4.trans.shared.b16 {%0,%1,%2,%3}, [%4];"
        : "=r"(r[0]), "=r"(r[1]), "=r"(r[2]), "=r"(r[3]) : "r"(addr));
}
__device__ __forceinline__ void mma_bf16(float* d, const uint32_t* a, const uint32_t* b) {
    asm volatile(
        "mma.sync.aligned.m16n8k16.row.col.f32.bf16.bf16.f32 "
        "{%0,%1,%2,%3}, {%4,%5,%6,%7}, {%8,%9}, {%0,%1,%2,%3};"
        : "+f"(d[0]), "+f"(d[1]), "+f"(d[2]), "+f"(d[3])
        : "r"(a[0]), "r"(a[1]), "r"(a[2]), "r"(a[3]), "r"(b[0]), "r"(b[1]));
}
#define CP16(dst, src) asm volatile("cp.async.cg.shared.global [%0], [%1], 16;" :: "r"(dst), "l"(src))
#define CP_COMMIT()    asm volatile("cp.async.commit_group;" ::: "memory")
#define CP_WAIT0()     asm volatile("cp.async.wait_group 0;" ::: "memory")
#define CP_WAIT1()     asm volatile("cp.async.wait_group 1;" ::: "memory")

__device__ __forceinline__ uint32_t pack_bf2(float x, float y) {
    __nv_bfloat162 t(__float2bfloat16_rn(x), __float2bfloat16_rn(y));
    return *(uint32_t*)&t;
}

// ---------------------------------------------------------------------------
// converts (merged launches)
// ---------------------------------------------------------------------------
__device__ __forceinline__ void split_store(
    const float* __restrict__ x, __nv_bfloat16* hi, __nv_bfloat16* lo, int i)
{
    float4 v = ((const float4*)x)[i];
    __nv_bfloat16 h0 = __float2bfloat16_rn(v.x);
    __nv_bfloat16 h1 = __float2bfloat16_rn(v.y);
    __nv_bfloat16 h2 = __float2bfloat16_rn(v.z);
    __nv_bfloat16 h3 = __float2bfloat16_rn(v.w);
    __nv_bfloat16 l0 = __float2bfloat16_rn(v.x - __bfloat162float(h0));
    __nv_bfloat16 l1 = __float2bfloat16_rn(v.y - __bfloat162float(h1));
    __nv_bfloat16 l2 = __float2bfloat16_rn(v.z - __bfloat162float(h2));
    __nv_bfloat16 l3 = __float2bfloat16_rn(v.w - __bfloat162float(h3));
    __nv_bfloat162* hp = (__nv_bfloat162*)(hi + (size_t)i * 4);
    __nv_bfloat162* lp = (__nv_bfloat162*)(lo + (size_t)i * 4);
    hp[0] = __nv_bfloat162(h0, h1); hp[1] = __nv_bfloat162(h2, h3);
    lp[0] = __nv_bfloat162(l0, l1); lp[1] = __nv_bfloat162(l2, l3);
}

__global__ __launch_bounds__(256) void convert_qkv(
    const float* __restrict__ q, const float* __restrict__ k,
    const float* __restrict__ v)
{
    int i = blockIdx.x * 256 + threadIdx.x;
    int z = blockIdx.y;
    if (z == 0)      split_store(q, g_q_hi, g_q_lo, i);
    else if (z == 1) split_store(k, g_k_hi, g_k_lo, i);
    else             split_store(v, g_v_hi, g_v_lo, i);
}

__global__ __launch_bounds__(256) void convert_w(
    const float* __restrict__ Wq, const float* __restrict__ Wk,
    const float* __restrict__ Wv, const float* __restrict__ Wd)
{
    int i = blockIdx.x * 256 + threadIdx.x;
    int z = blockIdx.y;
    if (z == 0)      split_store(Wq, g_wq_hi, g_wq_lo, i);
    else if (z == 1) split_store(Wk, g_wk_hi, g_wk_lo, i);
    else if (z == 2) split_store(Wv, g_wv_hi, g_wv_lo, i);
    else             split_store(Wd, g_wd_hi, g_wd_lo, i);
}

__global__ __launch_bounds__(256) void mask_to_bits(
    const int* __restrict__ mask, uint32_t* __restrict__ bits)
{
    int w = blockIdx.x * 256 + threadIdx.x;
    const int* p = mask + (size_t)w * 32;
    uint32_t word = 0;
    #pragma unroll
    for (int j = 0; j < 8; j++) {
        int4 v = ((const int4*)p)[j];
        word |= (v.x ? 1u : 0u) << (j * 4 + 0);
        word |= (v.y ? 1u : 0u) << (j * 4 + 1);
        word |= (v.z ? 1u : 0u) << (j * 4 + 2);
        word |= (v.w ? 1u : 0u) << (j * 4 + 3);
    }
    bits[w] = word;
}

// ---------------------------------------------------------------------------
// shared GEMM body: C[m][n] = sum_k A[m][k]*W[n][k], 3-term bf16 split,
// 2-stage cp.async, CTA 128x128, 8 warps (64x32), BK=64.
// ---------------------------------------------------------------------------
#define GEMM_SMEM (2 * 65536)

__device__ __forceinline__ void gemm_body(
    const __nv_bfloat16* __restrict__ Ahi, const __nv_bfloat16* __restrict__ Alo,
    const __nv_bfloat16* __restrict__ Whi, const __nv_bfloat16* __restrict__ Wlo,
    const float* __restrict__ bias, float* __restrict__ Cf32,
    __nv_bfloat16* __restrict__ Chi, __nv_bfloat16* __restrict__ Clo,
    char* sm)
{
    const int K = DM, N = DM;
    const uint32_t O_AHI = 0, O_ALO = 16384, O_WHI = 32768, O_WLO = 49152;

    int tid = threadIdx.x, w = tid >> 5, l = tid & 31;
    int m0 = blockIdx.y * 128, n0 = blockIdx.x * 128;
    int wm = w & 1, wn = w >> 1;

    uint32_t sb = smem_u32(sm);

    int a_row = wm * 64 + (l & 15);
    int a_k2  = (l >> 4) * 16;
    int b_row = wn * 32 + (l & 7) + ((l >> 4) * 8);
    int b_k2  = ((l >> 3) & 1) * 16;

    int lrow = tid >> 3;
    int lc   = tid & 7;

    float acc[4][4][4] = {};
    const int NK = K / 64;

    auto load_stage = [&](int s, int kc) {
        uint32_t base = sb + (uint32_t)s * 65536;
        #pragma unroll
        for (int it = 0; it < 4; it++) {
            int row = lrow + it * 32;
            size_t ga = (size_t)(m0 + row) * K + kc * 64 + lc * 8;
            size_t gw = (size_t)(n0 + row) * K + kc * 64 + lc * 8;
            uint32_t so = SWZ(row * 128 + lc * 16);
            CP16(base + O_AHI + so, Ahi + ga);
            CP16(base + O_ALO + so, Alo + ga);
            CP16(base + O_WHI + so, Whi + gw);
            CP16(base + O_WLO + so, Wlo + gw);
        }
        CP_COMMIT();
    };

    load_stage(0, 0);

    for (int kc = 0; kc < NK; kc++) {
        if (kc + 1 < NK) { load_stage((kc + 1) & 1, kc + 1); CP_WAIT1(); }
        else             { CP_WAIT0(); }
        __syncthreads();

        uint32_t st = sb + (uint32_t)(kc & 1) * 65536;
        #pragma unroll
        for (int kk = 0; kk < 4; kk++) {
            int ks2 = kk * 32;
            uint32_t ah[4][4], al[4][4], bw[2][4];
            #pragma unroll
            for (int mf = 0; mf < 4; mf++) {
                uint32_t off = SWZ((a_row + mf * 16) * 128 + ks2 + a_k2);
                ldm_x4(ah[mf], st + O_AHI + off);
                ldm_x4(al[mf], st + O_ALO + off);
            }
            #pragma unroll
            for (int bp = 0; bp < 2; bp++) {
                uint32_t off = SWZ((b_row + bp * 16) * 128 + ks2 + b_k2);
                ldm_x4(bw[bp], st + O_WHI + off);
            }
            #pragma unroll
            for (int mf = 0; mf < 4; mf++)
                #pragma unroll
                for (int nf = 0; nf < 4; nf++)
                    mma_bf16(acc[mf][nf], ah[mf], &bw[nf >> 1][(nf & 1) * 2]);
            #pragma unroll
            for (int mf = 0; mf < 4; mf++)
                #pragma unroll
                for (int nf = 0; nf < 4; nf++)
                    mma_bf16(acc[mf][nf], al[mf], &bw[nf >> 1][(nf & 1) * 2]);
            #pragma unroll
            for (int bp = 0; bp < 2; bp++) {
                uint32_t off = SWZ((b_row + bp * 16) * 128 + ks2 + b_k2);
                ldm_x4(bw[bp], st + O_WLO + off);
            }
            #pragma unroll
            for (int mf = 0; mf < 4; mf++)
                #pragma unroll
                for (int nf = 0; nf < 4; nf++)
                    mma_bf16(acc[mf][nf], ah[mf], &bw[nf >> 1][(nf & 1) * 2]);
        }
        __syncthreads();
    }

    int er = l >> 2, ec = (l & 3) * 2;
    #pragma unroll
    for (int mf = 0; mf < 4; mf++) {
        #pragma unroll
        for (int nf = 0; nf < 4; nf++) {
            int gm = m0 + wm * 64 + mf * 16 + er;
            int gn = n0 + wn * 32 + nf * 8 + ec;
            if (Cf32) {
                float b0 = bias ? bias[gn] : 0.0f;
                float b1 = bias ? bias[gn + 1] : 0.0f;
                float2 v0, v1;
                v0.x = acc[mf][nf][0] + b0; v0.y = acc[mf][nf][1] + b1;
                v1.x = acc[mf][nf][2] + b0; v1.y = acc[mf][nf][3] + b1;
                *(float2*)&Cf32[(size_t)gm * N + gn]       = v0;
                *(float2*)&Cf32[(size_t)(gm + 8) * N + gn] = v1;
            } else {
                #pragma unroll
                for (int rr = 0; rr < 2; rr++) {
                    float vx = acc[mf][nf][rr * 2], vy = acc[mf][nf][rr * 2 + 1];
                    float hx = __bfloat162float(__float2bfloat16_rn(vx));
                    float hy = __bfloat162float(__float2bfloat16_rn(vy));
                    size_t o = (size_t)(gm + rr * 8) * N + gn;
                    *(uint32_t*)&Chi[o] = pack_bf2(vx, vy);
                    *(uint32_t*)&Clo[o] = pack_bf2(vx - hx, vy - hy);
                }
            }
        }
    }
}

__global__ __launch_bounds__(256) void qkv_gemm()
{
    extern __shared__ char sm[];
    int z = blockIdx.z;
    if (z == 0)
        gemm_body(g_q_hi, g_q_lo, g_wq_hi, g_wq_lo, nullptr, nullptr, g_qp_hi, g_qp_lo, sm);
    else if (z == 1)
        gemm_body(g_k_hi, g_k_lo, g_wk_hi, g_wk_lo, nullptr, nullptr, g_kp_hi, g_kp_lo, sm);
    else
        gemm_body(g_v_hi, g_v_lo, g_wv_hi, g_wv_lo, nullptr, nullptr, g_vp_hi, g_vp_lo, sm);
}

__global__ __launch_bounds__(256) void out_gemm(const float* __restrict__ bias,
                                                float* __restrict__ out)
{
    extern __shared__ char sm[];
    gemm_body(g_c_hi, g_c_lo, g_wd_hi, g_wd_lo, bias, out, nullptr, nullptr, sm);
}

// ---------------------------------------------------------------------------
// Fused attention, pass 1: online row (max, sum). 2-stage cp.async K tiles.
// smem: Q 32KB | K stages 2x32KB | mask 2x2KB | m/s 2KB
// ---------------------------------------------------------------------------
#define P1_SMEM (32768 + 65536 + 4096 + 2048)

__global__ __launch_bounds__(256) void attn_pass1()
{
    extern __shared__ char sm[];
    const uint32_t O_Q = 0, O_KS = 32768, O_MB = 98304, O_MS = 102400;

    int tid = threadIdx.x, w = tid >> 5, l = tid & 31;
    int bh = blockIdx.y, b = bh >> 4, h = bh & 15;
    int m0 = blockIdx.x * 128;
    int wm = w & 3, wn = w >> 2;
    uint32_t sb = smem_u32(sm);
    float* sm_m = (float*)(sm + O_MS);
    float* sm_s = sm_m + 256;

    const __nv_bfloat16* Qh = g_qp_hi + (size_t)b * SEQ * DM + h * HD;
    const __nv_bfloat16* Ql = g_qp_lo + (size_t)b * SEQ * DM + h * HD;
    const __nv_bfloat16* Kh = g_kp_hi + (size_t)b * SEQ * DM + h * HD;
    const __nv_bfloat16* Kl = g_kp_lo + (size_t)b * SEQ * DM + h * HD;

    auto load_k = [&](int nt) {
        uint32_t base = sb + O_KS + (uint32_t)(nt & 1) * 32768;
        #pragma unroll
        for (int it = 0; it < 4; it++) {
            int idx = tid + it * 256;
            int row = idx >> 3, c = idx & 7;
            uint32_t so = SWZ(row * 128 + c * 16);
            size_t g = (size_t)(nt * 128 + row) * DM + c * 8;
            CP16(base + so, Kh + g);
            CP16(base + 16384 + so, Kl + g);
        }
        if (tid < 128)
            CP16(sb + O_MB + (uint32_t)(nt & 1) * 2048 + tid * 16,
                 &g_mbits[((size_t)b * SEQ + m0 + tid) * 32 + nt * 4]);
        CP_COMMIT();
    };

    // Q tile (persistent)
    #pragma unroll
    for (int it = 0; it < 4; it++) {
        int idx = tid + it * 256;
        int row = idx >> 3, c = idx & 7;
        uint32_t so = SWZ(row * 128 + c * 16);
        size_t g = (size_t)(m0 + row) * DM + c * 8;
        *(uint4*)(sm + O_Q + so)         = *(const uint4*)(Qh + g);
        *(uint4*)(sm + O_Q + 16384 + so) = *(const uint4*)(Ql + g);
    }
    load_k(0);

    float mrun[2][2] = {{-1e30f, -1e30f}, {-1e30f, -1e30f}};
    float srun[2][2] = {};
    const float scale = 0.03125f;
    int er = l >> 2, ec = (l & 3) * 2;

    for (int nt = 0; nt < 8; nt++) {
        if (nt + 1 < 8) { load_k(nt + 1); CP_WAIT1(); }
        else            { CP_WAIT0(); }
        __syncthreads();

        uint32_t kst = sb + O_KS + (uint32_t)(nt & 1) * 32768;
        uint32_t* sm_mb = (uint32_t*)(sm + O_MB + (size_t)(nt & 1) * 2048);

        float acc[2][8][4] = {};
        #pragma unroll
        for (int kk = 0; kk < 4; kk++) {
            int ks2 = kk * 32;
            uint32_t ah[2][4], al[2][4], bwh[4][4], bwl[4][4];
            #pragma unroll
            for (int mf = 0; mf < 2; mf++) {
                uint32_t off = SWZ((wm * 32 + mf * 16 + (l & 15)) * 128 + ks2 + (l >> 4) * 16);
                ldm_x4(ah[mf], sb + O_Q + off);
                ldm_x4(al[mf], sb + O_Q + 16384 + off);
            }
            #pragma unroll
            for (int bp = 0; bp < 4; bp++) {
                uint32_t off = SWZ((wn * 64 + bp * 16 + (l & 7) + ((l >> 4) * 8)) * 128
                                   + ks2 + ((l >> 3) & 1) * 16);
                ldm_x4(bwh[bp], kst + off);
                ldm_x4(bwl[bp], kst + 16384 + off);
            }
            #pragma unroll
            for (int mf = 0; mf < 2; mf++)
                #pragma unroll
                for (int nf = 0; nf < 8; nf++) {
                    mma_bf16(acc[mf][nf], ah[mf], &bwh[nf >> 1][(nf & 1) * 2]);
                    mma_bf16(acc[mf][nf], al[mf], &bwh[nf >> 1][(nf & 1) * 2]);
                    mma_bf16(acc[mf][nf], ah[mf], &bwl[nf >> 1][(nf & 1) * 2]);
                }
        }

        #pragma unroll
        for (int mf = 0; mf < 2; mf++) {
            #pragma unroll
            for (int rr = 0; rr < 2; rr++) {
                int rl = wm * 32 + mf * 16 + rr * 8 + er;
                uint32_t w0 = sm_mb[rl * 4 + wn * 2];
                uint32_t w1 = sm_mb[rl * 4 + wn * 2 + 1];
                float v[16];
                float tmax = -1e30f;
                #pragma unroll
                for (int nf = 0; nf < 8; nf++) {
                    uint32_t word = (nf < 4) ? w0 : w1;
                    int sh = (nf & 3) * 8 + ec;
                    float m0f = ((word >> sh) & 1u) ? -1e9f : 0.0f;
                    float m1f = ((word >> (sh + 1)) & 1u) ? -1e9f : 0.0f;
                    v[nf * 2]     = acc[mf][nf][rr * 2]     * scale + m0f;
                    v[nf * 2 + 1] = acc[mf][nf][rr * 2 + 1] * scale + m1f;
                    tmax = fmaxf(tmax, fmaxf(v[nf * 2], v[nf * 2 + 1]));
                }
                tmax = fmaxf(tmax, __shfl_xor_sync(0xffffffffu, tmax, 1));
                tmax = fmaxf(tmax, __shfl_xor_sync(0xffffffffu, tmax, 2));
                float nm = fmaxf(mrun[mf][rr], tmax);
                float ts = 0.0f;
                #pragma unroll
                for (int i = 0; i < 16; i++) ts += __expf(v[i] - nm);
                ts += __shfl_xor_sync(0xffffffffu, ts, 1);
                ts += __shfl_xor_sync(0xffffffffu, ts, 2);
                srun[mf][rr] = srun[mf][rr] * __expf(mrun[mf][rr] - nm) + ts;
                mrun[mf][rr] = nm;
            }
        }
        __syncthreads();
    }

    if ((l & 3) == 0) {
        #pragma unroll
        for (int mf = 0; mf < 2; mf++)
            #pragma unroll
            for (int rr = 0; rr < 2; rr++) {
                int rl = wm * 32 + mf * 16 + rr * 8 + er;
                sm_m[wn * 128 + rl] = mrun[mf][rr];
                sm_s[wn * 128 + rl] = srun[mf][rr];
            }
    }
    __syncthreads();
    if (tid < 128) {
        float ma = sm_m[tid], mb2 = sm_m[128 + tid];
        float m = fmaxf(ma, mb2);
        float s = sm_s[tid] * __expf(ma - m) + sm_s[128 + tid] * __expf(mb2 - m);
        g_rmax[(size_t)bh * SEQ + m0 + tid] = m;
        g_rsum[(size_t)bh * SEQ + m0 + tid] = s;
    }
}

// ---------------------------------------------------------------------------
// Fused attention, pass 2: recompute S, write normalized attn, ctx = P@V.
// 2-stage cp.async K+V tiles.
// smem: Q 32KB | KV stages 2x64KB | mask 2x2KB
// ---------------------------------------------------------------------------
#define P2_SMEM (32768 + 131072 + 4096)

__global__ __launch_bounds__(256) void attn_pass2(float* __restrict__ attn)
{
    extern __shared__ char sm[];
    const uint32_t O_Q = 0, O_KV = 32768, O_MB = 163840;

    int tid = threadIdx.x, w = tid >> 5, l = tid & 31;
    int bh = blockIdx.y, b = bh >> 4, h = bh & 15;
    int m0 = blockIdx.x * 128;
    int wm = w & 3, wn = w >> 2;
    uint32_t sb = smem_u32(sm);

    const __nv_bfloat16* Qh = g_qp_hi + (size_t)b * SEQ * DM + h * HD;
    const __nv_bfloat16* Ql = g_qp_lo + (size_t)b * SEQ * DM + h * HD;
    const __nv_bfloat16* Kh = g_kp_hi + (size_t)b * SEQ * DM + h * HD;
    const __nv_bfloat16* Kl = g_kp_lo + (size_t)b * SEQ * DM + h * HD;
    const __nv_bfloat16* Vh = g_vp_hi + (size_t)b * SEQ * DM + h * HD;
    const __nv_bfloat16* Vl = g_vp_lo + (size_t)b * SEQ * DM + h * HD;

    auto load_kv = [&](int nt) {
        uint32_t base = sb + O_KV + (uint32_t)(nt & 1) * 65536;
        #pragma unroll
        for (int it = 0; it < 4; it++) {
            int idx = tid + it * 256;
            int row = idx >> 3, c = idx & 7;
            uint32_t so = SWZ(row * 128 + c * 16);
            size_t g = (size_t)(nt * 128 + row) * DM + c * 8;
            CP16(base + so,         Kh + g);
            CP16(base + 16384 + so, Kl + g);
            CP16(base + 32768 + so, Vh + g);
            CP16(base + 49152 + so, Vl + g);
        }
        if (tid < 128)
            CP16(sb + O_MB + (uint32_t)(nt & 1) * 2048 + tid * 16,
                 &g_mbits[((size_t)b * SEQ + m0 + tid) * 32 + nt * 4]);
        CP_COMMIT();
    };

    #pragma unroll
    for (int it = 0; it < 4; it++) {
        int idx = tid + it * 256;
        int row = idx >> 3, c = idx & 7;
        uint32_t so = SWZ(row * 128 + c * 16);
        size_t g = (size_t)(m0 + row) * DM + c * 8;
        *(uint4*)(sm + O_Q + so)         = *(const uint4*)(Qh + g);
        *(uint4*)(sm + O_Q + 16384 + so) = *(const uint4*)(Ql + g);
    }
    load_kv(0);

    int er = l >> 2, ec = (l & 3) * 2;
    const float scale = 0.03125f;

    float rmax[2][2], rinv[2][2];
    #pragma unroll
    for (int mf = 0; mf < 2; mf++)
        #pragma unroll
        for (int rr = 0; rr < 2; rr++) {
            int gm = m0 + wm * 32 + mf * 16 + rr * 8 + er;
            rmax[mf][rr] = g_rmax[(size_t)bh * SEQ + gm];
            rinv[mf][rr] = __frcp_rn(g_rsum[(size_t)bh * SEQ + gm]);
        }

    float ctx[2][8][4] = {};

    for (int nt = 0; nt < 8; nt++) {
        if (nt + 1 < 8) { load_kv(nt + 1); CP_WAIT1(); }
        else            { CP_WAIT0(); }
        __syncthreads();

        uint32_t kst = sb + O_KV + (uint32_t)(nt & 1) * 65536;
        uint32_t* sm_mb = (uint32_t*)(sm + O_MB + (size_t)(nt & 1) * 2048);

        float acc[2][8][4] = {};
        #pragma unroll
        for (int kk = 0; kk < 4; kk++) {
            int ks2 = kk * 32;
            uint32_t ah[2][4], al[2][4], bwh[4][4], bwl[4][4];
            #pragma unroll
            for (int mf = 0; mf < 2; mf++) {
                uint32_t off = SWZ((wm * 32 + mf * 16 + (l & 15)) * 128 + ks2 + (l >> 4) * 16);
                ldm_x4(ah[mf], sb + O_Q + off);
                ldm_x4(al[mf], sb + O_Q + 16384 + off);
            }
            #pragma unroll
            for (int bp = 0; bp < 4; bp++) {
                uint32_t off = SWZ((wn * 64 + bp * 16 + (l & 7) + ((l >> 4) * 8)) * 128
                                   + ks2 + ((l >> 3) & 1) * 16);
                ldm_x4(bwh[bp], kst + off);
                ldm_x4(bwl[bp], kst + 16384 + off);
            }
            #pragma unroll
            for (int mf = 0; mf < 2; mf++)
                #pragma unroll
                for (int nf = 0; nf < 8; nf++) {
                    mma_bf16(acc[mf][nf], ah[mf], &bwh[nf >> 1][(nf & 1) * 2]);
                    mma_bf16(acc[mf][nf], al[mf], &bwh[nf >> 1][(nf & 1) * 2]);
                    mma_bf16(acc[mf][nf], ah[mf], &bwl[nf >> 1][(nf & 1) * 2]);
                }
        }

        // P = exp(s - m) * rinv; write attn; keep P in acc
        #pragma unroll
        for (int mf = 0; mf < 2; mf++) {
            #pragma unroll
            for (int rr = 0; rr < 2; rr++) {
                int rl = wm * 32 + mf * 16 + rr * 8 + er;
                int gm = m0 + rl;
                uint32_t w0 = sm_mb[rl * 4 + wn * 2];
                uint32_t w1 = sm_mb[rl * 4 + wn * 2 + 1];
                #pragma unroll
                for (int nf = 0; nf < 8; nf++) {
                    uint32_t word = (nf < 4) ? w0 : w1;
                    int sh = (nf & 3) * 8 + ec;
                    float m0f = ((word >> sh) & 1u) ? -1e9f : 0.0f;
                    float m1f = ((word >> (sh + 1)) & 1u) ? -1e9f : 0.0f;
                    float sv0 = acc[mf][nf][rr * 2]     * scale + m0f;
                    float sv1 = acc[mf][nf][rr * 2 + 1] * scale + m1f;
                    float2 pv;
                    pv.x = __expf(sv0 - rmax[mf][rr]) * rinv[mf][rr];
                    pv.y = __expf(sv1 - rmax[mf][rr]) * rinv[mf][rr];
                    int gn = nt * 128 + wn * 64 + nf * 8 + ec;
                    *(float2*)&attn[((size_t)bh * SEQ + gm) * SEQ + gn] = pv;
                    acc[mf][nf][rr * 2]     = pv.x;
                    acc[mf][nf][rr * 2 + 1] = pv.y;
                }
            }
        }

        // ctx += P @ V
        #pragma unroll
        for (int kk = 0; kk < 4; kk++) {
            uint32_t pah[2][4], pal[2][4], bvh[4][4], bvl[4][4];
            #pragma unroll
            for (int mf = 0; mf < 2; mf++) {
                float* a0 = acc[mf][kk * 2];
                float* a1 = acc[mf][kk * 2 + 1];
                pah[mf][0] = pack_bf2(a0[0], a0[1]);
                pah[mf][1] = pack_bf2(a0[2], a0[3]);
                pah[mf][2] = pack_bf2(a1[0], a1[1]);
                pah[mf][3] = pack_bf2(a1[2], a1[3]);
                float h00 = __bfloat162float(__float2bfloat16_rn(a0[0]));
                float h01 = __bfloat162float(__float2bfloat16_rn(a0[1]));
                float h02 = __bfloat162float(__float2bfloat16_rn(a0[2]));
                float h03 = __bfloat162float(__float2bfloat16_rn(a0[3]));
                float h10 = __bfloat162float(__float2bfloat16_rn(a1[0]));
                float h11 = __bfloat162float(__float2bfloat16_rn(a1[1]));
                float h12 = __bfloat162float(__float2bfloat16_rn(a1[2]));
                float h13 = __bfloat162float(__float2bfloat16_rn(a1[3]));
                pal[mf][0] = pack_bf2(a0[0] - h00, a0[1] - h01);
                pal[mf][1] = pack_bf2(a0[2] - h02, a0[3] - h03);
                pal[mf][2] = pack_bf2(a1[0] - h10, a1[1] - h11);
                pal[mf][3] = pack_bf2(a1[2] - h12, a1[3] - h13);
            }
            #pragma unroll
            for (int nb = 0; nb < 4; nb++) {
                uint32_t off = SWZ((wn * 64 + kk * 16 + (l & 15)) * 128
                                   + (nb * 16 + (l >> 4) * 8) * 2);
                ldm_x4t(bvh[nb], kst + 32768 + off);
                ldm_x4t(bvl[nb], kst + 49152 + off);
            }
            #pragma unroll
            for (int mf = 0; mf < 2; mf++)
                #pragma unroll
                for (int nd = 0; nd < 8; nd++) {
                    mma_bf16(ctx[mf][nd], pah[mf], &bvh[nd >> 1][(nd & 1) * 2]);
                    mma_bf16(ctx[mf][nd], pal[mf], &bvh[nd >> 1][(nd & 1) * 2]);
                    mma_bf16(ctx[mf][nd], pah[mf], &bvl[nd >> 1][(nd & 1) * 2]);
                }
        }
        __syncthreads();
    }

    // cross-wn reduce via smem (alias KV stage 0), write ctx bf16 hi/lo
    __syncthreads();
    float* red = (float*)(sm + O_KV);   // 128 x 64 fp32 = 32KB
    if (wn == 1) {
        #pragma unroll
        for (int mf = 0; mf < 2; mf++)
            #pragma unroll
            for (int nd = 0; nd < 8; nd++)
                #pragma unroll
                for (int rr = 0; rr < 2; rr++) {
                    int row = wm * 32 + mf * 16 + rr * 8 + er;
                    float2 v;
                    v.x = ctx[mf][nd][rr * 2];
                    v.y = ctx[mf][nd][rr * 2 + 1];
                    *(float2*)&red[row * 64 + nd * 8 + ec] = v;
                }
    }
    __syncthreads();
    if (wn == 0) {
        __nv_bfloat16* Chi = g_c_hi + (size_t)b * SEQ * DM + h * HD;
        __nv_bfloat16* Clo = g_c_lo + (size_t)b * SEQ * DM + h * HD;
        #pragma unroll
        for (int mf = 0; mf < 2; mf++)
            #pragma unroll
            for (int nd = 0; nd < 8; nd++)
                #pragma unroll
                for (int rr = 0; rr < 2; rr++) {
                    int row = wm * 32 + mf * 16 + rr * 8 + er;
                    int col = nd * 8 + ec;
                    float2 o = *(float2*)&red[row * 64 + col];
                    float vx = ctx[mf][nd][rr * 2] + o.x;
                    float vy = ctx[mf][nd][rr * 2 + 1] + o.y;
                    float hx = __bfloat162float(__float2bfloat16_rn(vx));
                    float hy = __bfloat162float(__float2bfloat16_rn(vy));
                    size_t off = (size_t)(m0 + row) * DM + col;
                    *(uint32_t*)&Chi[off] = pack_bf2(vx, vy);
                    *(uint32_t*)&Clo[off] = pack_bf2(vx - hx, vy - hy);
                }
    }
}

// ---------------------------------------------------------------------------
extern "C" void kernel_launch(void* const* d_in, const int* in_sizes, int n_in,
                              void* d_out, int out_size)
{
    const float* q   = (const float*)d_in[0];
    const float* k   = (const float*)d_in[1];
    const float* v   = (const float*)d_in[2];
    const int*  mask = (const int*)d_in[3];
    const float* Wq  = (const float*)d_in[4];
    const float* Wk  = (const float*)d_in[5];
    const float* Wv  = (const float*)d_in[6];
    const float* Wd  = (const float*)d_in[7];
    const float* bd  = (const float*)d_in[8];
    float* out = (float*)d_out;

    const long long out_elems  = (long long)BQ * SEQ * DM;
    const long long attn_elems = (long long)BQ * NH * SEQ * SEQ;
    float* attn;
    if ((long long)out_size >= out_elems + attn_elems) {
        attn = out + out_elems;
    } else {
        cudaGetSymbolAddress((void**)&attn, g_attn);
    }

    cudaFuncSetAttribute(qkv_gemm,   cudaFuncAttributeMaxDynamicSharedMemorySize, GEMM_SMEM);
    cudaFuncSetAttribute(out_gemm,   cudaFuncAttributeMaxDynamicSharedMemorySize, GEMM_SMEM);
    cudaFuncSetAttribute(attn_pass1, cudaFuncAttributeMaxDynamicSharedMemorySize, P1_SMEM);
    cudaFuncSetAttribute(attn_pass2, cudaFuncAttributeMaxDynamicSharedMemorySize, P2_SMEM);

    uint32_t* mb;
    cudaGetSymbolAddress((void**)&mb, g_mbits);

    const int NBIG = BQ * SEQ * DM / 4 / 256;   // 4096 blocks
    const int NW   = DM * DM / 4 / 256;         // 1024 blocks
    convert_qkv<<<dim3(NBIG, 3), 256>>>(q, k, v);
    convert_w<<<dim3(NW, 4), 256>>>(Wq, Wk, Wv, Wd);
    mask_to_bits<<<BQ * SEQ * SEQ / 32 / 256, 256>>>(mask, mb);

    qkv_gemm<<<dim3(DM / 128, (BQ * SEQ) / 128, 3), 256, GEMM_SMEM>>>();

    dim3 ga(SEQ / 128, BQ * NH);
    attn_pass1<<<ga, 256, P1_SMEM>>>();
    attn_pass2<<<ga, 256, P2_SMEM>>>(attn);

    out_gemm<<<dim3(DM / 128, (BQ * SEQ) / 128), 256, GEMM_SMEM>>>(bd, out);
}

// round 9
// speedup vs baseline: 3.1811x; 1.0068x over previous
#include <cuda_runtime.h>
#include <cuda_bf16.h>
#include <stdint.h>
#include <math.h>

#define BQ  4
#define SEQ 1024
#define DM  1024
#define NH  16
#define HD  64

// ---------------- scratch (no allocations allowed) ----------------
__device__ float g_attn[BQ * NH * SEQ * SEQ];  // fallback if attn not an output
__device__ float g_rmax[BQ * NH * SEQ];
__device__ float g_rsum[BQ * NH * SEQ];
__device__ uint32_t g_mbits[BQ * SEQ * (SEQ / 32)];

__device__ __nv_bfloat16 g_q_hi[BQ * SEQ * DM],  g_q_lo[BQ * SEQ * DM];
__device__ __nv_bfloat16 g_k_hi[BQ * SEQ * DM],  g_k_lo[BQ * SEQ * DM];
__device__ __nv_bfloat16 g_v_hi[BQ * SEQ * DM],  g_v_lo[BQ * SEQ * DM];
__device__ __nv_bfloat16 g_qp_hi[BQ * SEQ * DM], g_qp_lo[BQ * SEQ * DM];
__device__ __nv_bfloat16 g_kp_hi[BQ * SEQ * DM], g_kp_lo[BQ * SEQ * DM];
__device__ __nv_bfloat16 g_vp_hi[BQ * SEQ * DM], g_vp_lo[BQ * SEQ * DM];
__device__ __nv_bfloat16 g_c_hi[BQ * SEQ * DM],  g_c_lo[BQ * SEQ * DM];
__device__ __nv_bfloat16 g_wq_hi[DM * DM], g_wq_lo[DM * DM];
__device__ __nv_bfloat16 g_wk_hi[DM * DM], g_wk_lo[DM * DM];
__device__ __nv_bfloat16 g_wv_hi[DM * DM], g_wv_lo[DM * DM];
__device__ __nv_bfloat16 g_wd_hi[DM * DM], g_wd_lo[DM * DM];

#define SWZ(o)   ((o) ^ (((o) >> 3) & 0x70))              // 128B rows
#define SWZ32(o) ((o) ^ ((((o) >> 7) & 3) << 4))          // 64B rows

__device__ __forceinline__ uint32_t smem_u32(const void* p) {
    uint32_t a;
    asm("{ .reg .u64 t; cvta.to.shared.u64 t, %1; cvt.u32.u64 %0, t; }" : "=r"(a) : "l"(p));
    return a;
}
__device__ __forceinline__ void ldm_x4(uint32_t* r, uint32_t addr) {
    asm volatile("ldmatrix.sync.aligned.m8n8.x4.shared.b16 {%0,%1,%2,%3}, [%4];"
        : "=r"(r[0]), "=r"(r[1]), "=r"(r[2]), "=r"(r[3]) : "r"(addr));
}
__device__ __forceinline__ void ldm_x4t(uint32_t* r, uint32_t addr) {
    asm volatile("ldmatrix.sync.aligned.m8n8.x4.trans.shared.b16 {%0,%1,%2,%3}, [%4];"
        : "=r"(r[0]), "=r"(r[1]), "=r"(r[2]), "=r"(r[3]) : "r"(addr));
}
__device__ __forceinline__ void mma_bf16(float* d, const uint32_t* a, const uint32_t* b) {
    asm volatile(
        "mma.sync.aligned.m16n8k16.row.col.f32.bf16.bf16.f32 "
        "{%0,%1,%2,%3}, {%4,%5,%6,%7}, {%8,%9}, {%0,%1,%2,%3};"
        : "+f"(d[0]), "+f"(d[1]), "+f"(d[2]), "+f"(d[3])
        : "r"(a[0]), "r"(a[1]), "r"(a[2]), "r"(a[3]), "r"(b[0]), "r"(b[1]));
}
#define CP16(dst, src) asm volatile("cp.async.cg.shared.global [%0], [%1], 16;" :: "r"(dst), "l"(src))
#define CP_COMMIT()    asm volatile("cp.async.commit_group;" ::: "memory")
#define CP_WAIT0()     asm volatile("cp.async.wait_group 0;" ::: "memory")
#define CP_WAIT1()     asm volatile("cp.async.wait_group 1;" ::: "memory")
#define CP_WAIT2()     asm volatile("cp.async.wait_group 2;" ::: "memory")

__device__ __forceinline__ uint32_t pack_bf2(float x, float y) {
    __nv_bfloat162 t(__float2bfloat16_rn(x), __float2bfloat16_rn(y));
    return *(uint32_t*)&t;
}

// ---------------------------------------------------------------------------
// prep: all converts + mask bit-packing in ONE launch.
// blocks [0,12288): q/k/v splits; [12288,16384): weights; [16384,16896): mask
// ---------------------------------------------------------------------------
__device__ __forceinline__ void split_store(
    const float* __restrict__ x, __nv_bfloat16* hi, __nv_bfloat16* lo, int i)
{
    float4 v = ((const float4*)x)[i];
    __nv_bfloat16 h0 = __float2bfloat16_rn(v.x);
    __nv_bfloat16 h1 = __float2bfloat16_rn(v.y);
    __nv_bfloat16 h2 = __float2bfloat16_rn(v.z);
    __nv_bfloat16 h3 = __float2bfloat16_rn(v.w);
    __nv_bfloat16 l0 = __float2bfloat16_rn(v.x - __bfloat162float(h0));
    __nv_bfloat16 l1 = __float2bfloat16_rn(v.y - __bfloat162float(h1));
    __nv_bfloat16 l2 = __float2bfloat16_rn(v.z - __bfloat162float(h2));
    __nv_bfloat16 l3 = __float2bfloat16_rn(v.w - __bfloat162float(h3));
    __nv_bfloat162* hp = (__nv_bfloat162*)(hi + (size_t)i * 4);
    __nv_bfloat162* lp = (__nv_bfloat162*)(lo + (size_t)i * 4);
    hp[0] = __nv_bfloat162(h0, h1); hp[1] = __nv_bfloat162(h2, h3);
    lp[0] = __nv_bfloat162(l0, l1); lp[1] = __nv_bfloat162(l2, l3);
}

__global__ __launch_bounds__(256) void prep(
    const float* __restrict__ q, const float* __restrict__ k,
    const float* __restrict__ v,
    const float* __restrict__ Wq, const float* __restrict__ Wk,
    const float* __restrict__ Wv, const float* __restrict__ Wd,
    const int* __restrict__ mask, uint32_t* __restrict__ bits)
{
    int bid = blockIdx.x;
    if (bid < 12288) {
        int z = bid >> 12;
        int i = (bid & 4095) * 256 + threadIdx.x;
        if (z == 0)      split_store(q, g_q_hi, g_q_lo, i);
        else if (z == 1) split_store(k, g_k_hi, g_k_lo, i);
        else             split_store(v, g_v_hi, g_v_lo, i);
    } else if (bid < 16384) {
        int r = bid - 12288;
        int z = r >> 10;
        int i = (r & 1023) * 256 + threadIdx.x;
        if (z == 0)      split_store(Wq, g_wq_hi, g_wq_lo, i);
        else if (z == 1) split_store(Wk, g_wk_hi, g_wk_lo, i);
        else if (z == 2) split_store(Wv, g_wv_hi, g_wv_lo, i);
        else             split_store(Wd, g_wd_hi, g_wd_lo, i);
    } else {
        int wdx = (bid - 16384) * 256 + threadIdx.x;
        const int* p = mask + (size_t)wdx * 32;
        uint32_t word = 0;
        #pragma unroll
        for (int j = 0; j < 8; j++) {
            int4 mv = ((const int4*)p)[j];
            word |= (mv.x ? 1u : 0u) << (j * 4 + 0);
            word |= (mv.y ? 1u : 0u) << (j * 4 + 1);
            word |= (mv.z ? 1u : 0u) << (j * 4 + 2);
            word |= (mv.w ? 1u : 0u) << (j * 4 + 3);
        }
        bits[wdx] = word;
    }
}

// ---------------------------------------------------------------------------
// GEMM body: C[m][n] = sum_k A[m][k]*W[n][k], 3-term bf16 split.
// BK=32 (64B rows, SWZ32), 3-stage cp.async, CTA 128x128, 8 warps (64x32),
// 2 CTAs/SM via __launch_bounds__(256,2).
// ---------------------------------------------------------------------------
#define GEMM_SMEM (3 * 32768)

__device__ __forceinline__ void gemm_body(
    const __nv_bfloat16* __restrict__ Ahi, const __nv_bfloat16* __restrict__ Alo,
    const __nv_bfloat16* __restrict__ Whi, const __nv_bfloat16* __restrict__ Wlo,
    const float* __restrict__ bias, float* __restrict__ Cf32,
    __nv_bfloat16* __restrict__ Chi, __nv_bfloat16* __restrict__ Clo,
    char* sm)
{
    const int K = DM, N = DM;

    int tid = threadIdx.x, w = tid >> 5, l = tid & 31;
    int m0 = blockIdx.y * 128, n0 = blockIdx.x * 128;
    int wm = w & 1, wn = w >> 1;

    uint32_t sb = smem_u32(sm);

    int a_row = wm * 64 + (l & 15);
    int a_cb  = (l >> 4) * 16;
    int b_row = wn * 32 + (l & 7) + ((l >> 4) * 8);
    int b_cb  = ((l >> 3) & 1) * 16;

    float acc[4][4][4] = {};
    const int NK = K / 32;   // 32

    auto load_stage = [&](int s, int kc) {
        uint32_t base = sb + (uint32_t)s * 32768;
        #pragma unroll
        for (int it = 0; it < 2; it++) {
            int idx = tid + it * 256;
            int row = idx >> 2, c = idx & 3;
            size_t ga = (size_t)(m0 + row) * K + kc * 32 + c * 8;
            size_t gw = (size_t)(n0 + row) * K + kc * 32 + c * 8;
            uint32_t so = SWZ32(row * 64 + c * 16);
            CP16(base +     0 + so, Ahi + ga);
            CP16(base +  8192 + so, Alo + ga);
            CP16(base + 16384 + so, Whi + gw);
            CP16(base + 24576 + so, Wlo + gw);
        }
        CP_COMMIT();
    };

    load_stage(0, 0);
    load_stage(1, 1);

    for (int kc = 0; kc < NK; kc++) {
        __syncthreads();                       // prev compute done before overwrite
        if (kc + 2 < NK) { load_stage((kc + 2) % 3, kc + 2); CP_WAIT2(); }
        else if (kc + 1 < NK) { CP_WAIT1(); }
        else { CP_WAIT0(); }
        __syncthreads();                       // stage kc visible to all

        uint32_t st = sb + (uint32_t)(kc % 3) * 32768;
        #pragma unroll
        for (int kk = 0; kk < 2; kk++) {
            int ks2 = kk * 32;
            uint32_t ah[4][4], al[4][4], bw[2][4];
            #pragma unroll
            for (int mf = 0; mf < 4; mf++) {
                uint32_t off = SWZ32((a_row + mf * 16) * 64 + ks2 + a_cb);
                ldm_x4(ah[mf], st + 0 + off);
                ldm_x4(al[mf], st + 8192 + off);
            }
            #pragma unroll
            for (int bp = 0; bp < 2; bp++) {
                uint32_t off = SWZ32((b_row + bp * 16) * 64 + ks2 + b_cb);
                ldm_x4(bw[bp], st + 16384 + off);
            }
            #pragma unroll
            for (int mf = 0; mf < 4; mf++)
                #pragma unroll
                for (int nf = 0; nf < 4; nf++)
                    mma_bf16(acc[mf][nf], ah[mf], &bw[nf >> 1][(nf & 1) * 2]);
            #pragma unroll
            for (int mf = 0; mf < 4; mf++)
                #pragma unroll
                for (int nf = 0; nf < 4; nf++)
                    mma_bf16(acc[mf][nf], al[mf], &bw[nf >> 1][(nf & 1) * 2]);
            #pragma unroll
            for (int bp = 0; bp < 2; bp++) {
                uint32_t off = SWZ32((b_row + bp * 16) * 64 + ks2 + b_cb);
                ldm_x4(bw[bp], st + 24576 + off);
            }
            #pragma unroll
            for (int mf = 0; mf < 4; mf++)
                #pragma unroll
                for (int nf = 0; nf < 4; nf++)
                    mma_bf16(acc[mf][nf], ah[mf], &bw[nf >> 1][(nf & 1) * 2]);
        }
    }

    int er = l >> 2, ec = (l & 3) * 2;
    #pragma unroll
    for (int mf = 0; mf < 4; mf++) {
        #pragma unroll
        for (int nf = 0; nf < 4; nf++) {
            int gm = m0 + wm * 64 + mf * 16 + er;
            int gn = n0 + wn * 32 + nf * 8 + ec;
            if (Cf32) {
                float b0 = bias ? bias[gn] : 0.0f;
                float b1 = bias ? bias[gn + 1] : 0.0f;
                float2 v0, v1;
                v0.x = acc[mf][nf][0] + b0; v0.y = acc[mf][nf][1] + b1;
                v1.x = acc[mf][nf][2] + b0; v1.y = acc[mf][nf][3] + b1;
                *(float2*)&Cf32[(size_t)gm * N + gn]       = v0;
                *(float2*)&Cf32[(size_t)(gm + 8) * N + gn] = v1;
            } else {
                #pragma unroll
                for (int rr = 0; rr < 2; rr++) {
                    float vx = acc[mf][nf][rr * 2], vy = acc[mf][nf][rr * 2 + 1];
                    float hx = __bfloat162float(__float2bfloat16_rn(vx));
                    float hy = __bfloat162float(__float2bfloat16_rn(vy));
                    size_t o = (size_t)(gm + rr * 8) * N + gn;
                    *(uint32_t*)&Chi[o] = pack_bf2(vx, vy);
                    *(uint32_t*)&Clo[o] = pack_bf2(vx - hx, vy - hy);
                }
            }
        }
    }
}

__global__ __launch_bounds__(256, 2) void qkv_gemm()
{
    extern __shared__ char sm[];
    int z = blockIdx.z;
    if (z == 0)
        gemm_body(g_q_hi, g_q_lo, g_wq_hi, g_wq_lo, nullptr, nullptr, g_qp_hi, g_qp_lo, sm);
    else if (z == 1)
        gemm_body(g_k_hi, g_k_lo, g_wk_hi, g_wk_lo, nullptr, nullptr, g_kp_hi, g_kp_lo, sm);
    else
        gemm_body(g_v_hi, g_v_lo, g_wv_hi, g_wv_lo, nullptr, nullptr, g_vp_hi, g_vp_lo, sm);
}

__global__ __launch_bounds__(256, 2) void out_gemm(const float* __restrict__ bias,
                                                   float* __restrict__ out)
{
    extern __shared__ char sm[];
    gemm_body(g_c_hi, g_c_lo, g_wd_hi, g_wd_lo, bias, out, nullptr, nullptr, sm);
}

// ---------------------------------------------------------------------------
// Fused attention, pass 1: online row (max, sum). 2-stage cp.async K tiles.
// smem: Q 32KB | K stages 2x32KB | mask 2x2KB | m/s 2KB ; 2 CTAs/SM.
// ---------------------------------------------------------------------------
#define P1_SMEM (32768 + 65536 + 4096 + 2048)

__global__ __launch_bounds__(256, 2) void attn_pass1()
{
    extern __shared__ char sm[];
    const uint32_t O_Q = 0, O_KS = 32768, O_MB = 98304, O_MS = 102400;

    int tid = threadIdx.x, w = tid >> 5, l = tid & 31;
    int bh = blockIdx.y, b = bh >> 4, h = bh & 15;
    int m0 = blockIdx.x * 128;
    int wm = w & 3, wn = w >> 2;
    uint32_t sb = smem_u32(sm);
    float* sm_m = (float*)(sm + O_MS);
    float* sm_s = sm_m + 256;

    const __nv_bfloat16* Qh = g_qp_hi + (size_t)b * SEQ * DM + h * HD;
    const __nv_bfloat16* Ql = g_qp_lo + (size_t)b * SEQ * DM + h * HD;
    const __nv_bfloat16* Kh = g_kp_hi + (size_t)b * SEQ * DM + h * HD;
    const __nv_bfloat16* Kl = g_kp_lo + (size_t)b * SEQ * DM + h * HD;

    auto load_k = [&](int nt) {
        uint32_t base = sb + O_KS + (uint32_t)(nt & 1) * 32768;
        #pragma unroll
        for (int it = 0; it < 4; it++) {
            int idx = tid + it * 256;
            int row = idx >> 3, c = idx & 7;
            uint32_t so = SWZ(row * 128 + c * 16);
            size_t g = (size_t)(nt * 128 + row) * DM + c * 8;
            CP16(base + so, Kh + g);
            CP16(base + 16384 + so, Kl + g);
        }
        if (tid < 128)
            CP16(sb + O_MB + (uint32_t)(nt & 1) * 2048 + tid * 16,
                 &g_mbits[((size_t)b * SEQ + m0 + tid) * 32 + nt * 4]);
        CP_COMMIT();
    };

    #pragma unroll
    for (int it = 0; it < 4; it++) {
        int idx = tid + it * 256;
        int row = idx >> 3, c = idx & 7;
        uint32_t so = SWZ(row * 128 + c * 16);
        size_t g = (size_t)(m0 + row) * DM + c * 8;
        *(uint4*)(sm + O_Q + so)         = *(const uint4*)(Qh + g);
        *(uint4*)(sm + O_Q + 16384 + so) = *(const uint4*)(Ql + g);
    }
    load_k(0);

    float mrun[2][2] = {{-1e30f, -1e30f}, {-1e30f, -1e30f}};
    float srun[2][2] = {};
    const float scale = 0.03125f;
    int er = l >> 2, ec = (l & 3) * 2;

    for (int nt = 0; nt < 8; nt++) {
        if (nt + 1 < 8) { load_k(nt + 1); CP_WAIT1(); }
        else            { CP_WAIT0(); }
        __syncthreads();

        uint32_t kst = sb + O_KS + (uint32_t)(nt & 1) * 32768;
        uint32_t* sm_mb = (uint32_t*)(sm + O_MB + (size_t)(nt & 1) * 2048);

        float acc[2][8][4] = {};
        #pragma unroll
        for (int kk = 0; kk < 4; kk++) {
            int ks2 = kk * 32;
            uint32_t ah[2][4], al[2][4], bwh[4][4], bwl[4][4];
            #pragma unroll
            for (int mf = 0; mf < 2; mf++) {
                uint32_t off = SWZ((wm * 32 + mf * 16 + (l & 15)) * 128 + ks2 + (l >> 4) * 16);
                ldm_x4(ah[mf], sb + O_Q + off);
                ldm_x4(al[mf], sb + O_Q + 16384 + off);
            }
            #pragma unroll
            for (int bp = 0; bp < 4; bp++) {
                uint32_t off = SWZ((wn * 64 + bp * 16 + (l & 7) + ((l >> 4) * 8)) * 128
                                   + ks2 + ((l >> 3) & 1) * 16);
                ldm_x4(bwh[bp], kst + off);
                ldm_x4(bwl[bp], kst + 16384 + off);
            }
            #pragma unroll
            for (int mf = 0; mf < 2; mf++)
                #pragma unroll
                for (int nf = 0; nf < 8; nf++) {
                    mma_bf16(acc[mf][nf], ah[mf], &bwh[nf >> 1][(nf & 1) * 2]);
                    mma_bf16(acc[mf][nf], al[mf], &bwh[nf >> 1][(nf & 1) * 2]);
                    mma_bf16(acc[mf][nf], ah[mf], &bwl[nf >> 1][(nf & 1) * 2]);
                }
        }

        #pragma unroll
        for (int mf = 0; mf < 2; mf++) {
            #pragma unroll
            for (int rr = 0; rr < 2; rr++) {
                int rl = wm * 32 + mf * 16 + rr * 8 + er;
                uint32_t w0 = sm_mb[rl * 4 + wn * 2];
                uint32_t w1 = sm_mb[rl * 4 + wn * 2 + 1];
                float v[16];
                float tmax = -1e30f;
                #pragma unroll
                for (int nf = 0; nf < 8; nf++) {
                    uint32_t word = (nf < 4) ? w0 : w1;
                    int sh = (nf & 3) * 8 + ec;
                    float m0f = ((word >> sh) & 1u) ? -1e9f : 0.0f;
                    float m1f = ((word >> (sh + 1)) & 1u) ? -1e9f : 0.0f;
                    v[nf * 2]     = acc[mf][nf][rr * 2]     * scale + m0f;
                    v[nf * 2 + 1] = acc[mf][nf][rr * 2 + 1] * scale + m1f;
                    tmax = fmaxf(tmax, fmaxf(v[nf * 2], v[nf * 2 + 1]));
                }
                tmax = fmaxf(tmax, __shfl_xor_sync(0xffffffffu, tmax, 1));
                tmax = fmaxf(tmax, __shfl_xor_sync(0xffffffffu, tmax, 2));
                float nm = fmaxf(mrun[mf][rr], tmax);
                float ts = 0.0f;
                #pragma unroll
                for (int i = 0; i < 16; i++) ts += __expf(v[i] - nm);
                ts += __shfl_xor_sync(0xffffffffu, ts, 1);
                ts += __shfl_xor_sync(0xffffffffu, ts, 2);
                srun[mf][rr] = srun[mf][rr] * __expf(mrun[mf][rr] - nm) + ts;
                mrun[mf][rr] = nm;
            }
        }
        __syncthreads();
    }

    if ((l & 3) == 0) {
        #pragma unroll
        for (int mf = 0; mf < 2; mf++)
            #pragma unroll
            for (int rr = 0; rr < 2; rr++) {
                int rl = wm * 32 + mf * 16 + rr * 8 + er;
                sm_m[wn * 128 + rl] = mrun[mf][rr];
                sm_s[wn * 128 + rl] = srun[mf][rr];
            }
    }
    __syncthreads();
    if (tid < 128) {
        float ma = sm_m[tid], mb2 = sm_m[128 + tid];
        float m = fmaxf(ma, mb2);
        float s = sm_s[tid] * __expf(ma - m) + sm_s[128 + tid] * __expf(mb2 - m);
        g_rmax[(size_t)bh * SEQ + m0 + tid] = m;
        g_rsum[(size_t)bh * SEQ + m0 + tid] = s;
    }
}

// ---------------------------------------------------------------------------
// Fused attention, pass 2 (unchanged from R8).
// ---------------------------------------------------------------------------
#define P2_SMEM (32768 + 131072 + 4096)

__global__ __launch_bounds__(256) void attn_pass2(float* __restrict__ attn)
{
    extern __shared__ char sm[];
    const uint32_t O_Q = 0, O_KV = 32768, O_MB = 163840;

    int tid = threadIdx.x, w = tid >> 5, l = tid & 31;
    int bh = blockIdx.y, b = bh >> 4, h = bh & 15;
    int m0 = blockIdx.x * 128;
    int wm = w & 3, wn = w >> 2;
    uint32_t sb = smem_u32(sm);

    const __nv_bfloat16* Qh = g_qp_hi + (size_t)b * SEQ * DM + h * HD;
    const __nv_bfloat16* Ql = g_qp_lo + (size_t)b * SEQ * DM + h * HD;
    const __nv_bfloat16* Kh = g_kp_hi + (size_t)b * SEQ * DM + h * HD;
    const __nv_bfloat16* Kl = g_kp_lo + (size_t)b * SEQ * DM + h * HD;
    const __nv_bfloat16* Vh = g_vp_hi + (size_t)b * SEQ * DM + h * HD;
    const __nv_bfloat16* Vl = g_vp_lo + (size_t)b * SEQ * DM + h * HD;

    auto load_kv = [&](int nt) {
        uint32_t base = sb + O_KV + (uint32_t)(nt & 1) * 65536;
        #pragma unroll
        for (int it = 0; it < 4; it++) {
            int idx = tid + it * 256;
            int row = idx >> 3, c = idx & 7;
            uint32_t so = SWZ(row * 128 + c * 16);
            size_t g = (size_t)(nt * 128 + row) * DM + c * 8;
            CP16(base + so,         Kh + g);
            CP16(base + 16384 + so, Kl + g);
            CP16(base + 32768 + so, Vh + g);
            CP16(base + 49152 + so, Vl + g);
        }
        if (tid < 128)
            CP16(sb + O_MB + (uint32_t)(nt & 1) * 2048 + tid * 16,
                 &g_mbits[((size_t)b * SEQ + m0 + tid) * 32 + nt * 4]);
        CP_COMMIT();
    };

    #pragma unroll
    for (int it = 0; it < 4; it++) {
        int idx = tid + it * 256;
        int row = idx >> 3, c = idx & 7;
        uint32_t so = SWZ(row * 128 + c * 16);
        size_t g = (size_t)(m0 + row) * DM + c * 8;
        *(uint4*)(sm + O_Q + so)         = *(const uint4*)(Qh + g);
        *(uint4*)(sm + O_Q + 16384 + so) = *(const uint4*)(Ql + g);
    }
    load_kv(0);

    int er = l >> 2, ec = (l & 3) * 2;
    const float scale = 0.03125f;

    float rmax[2][2], rinv[2][2];
    #pragma unroll
    for (int mf = 0; mf < 2; mf++)
        #pragma unroll
        for (int rr = 0; rr < 2; rr++) {
            int gm = m0 + wm * 32 + mf * 16 + rr * 8 + er;
            rmax[mf][rr] = g_rmax[(size_t)bh * SEQ + gm];
            rinv[mf][rr] = __frcp_rn(g_rsum[(size_t)bh * SEQ + gm]);
        }

    float ctx[2][8][4] = {};

    for (int nt = 0; nt < 8; nt++) {
        if (nt + 1 < 8) { load_kv(nt + 1); CP_WAIT1(); }
        else            { CP_WAIT0(); }
        __syncthreads();

        uint32_t kst = sb + O_KV + (uint32_t)(nt & 1) * 65536;
        uint32_t* sm_mb = (uint32_t*)(sm + O_MB + (size_t)(nt & 1) * 2048);

        float acc[2][8][4] = {};
        #pragma unroll
        for (int kk = 0; kk < 4; kk++) {
            int ks2 = kk * 32;
            uint32_t ah[2][4], al[2][4], bwh[4][4], bwl[4][4];
            #pragma unroll
            for (int mf = 0; mf < 2; mf++) {
                uint32_t off = SWZ((wm * 32 + mf * 16 + (l & 15)) * 128 + ks2 + (l >> 4) * 16);
                ldm_x4(ah[mf], sb + O_Q + off);
                ldm_x4(al[mf], sb + O_Q + 16384 + off);
            }
            #pragma unroll
            for (int bp = 0; bp < 4; bp++) {
                uint32_t off = SWZ((wn * 64 + bp * 16 + (l & 7) + ((l >> 4) * 8)) * 128
                                   + ks2 + ((l >> 3) & 1) * 16);
                ldm_x4(bwh[bp], kst + off);
                ldm_x4(bwl[bp], kst + 16384 + off);
            }
            #pragma unroll
            for (int mf = 0; mf < 2; mf++)
                #pragma unroll
                for (int nf = 0; nf < 8; nf++) {
                    mma_bf16(acc[mf][nf], ah[mf], &bwh[nf >> 1][(nf & 1) * 2]);
                    mma_bf16(acc[mf][nf], al[mf], &bwh[nf >> 1][(nf & 1) * 2]);
                    mma_bf16(acc[mf][nf], ah[mf], &bwl[nf >> 1][(nf & 1) * 2]);
                }
        }

        #pragma unroll
        for (int mf = 0; mf < 2; mf++) {
            #pragma unroll
            for (int rr = 0; rr < 2; rr++) {
                int rl = wm * 32 + mf * 16 + rr * 8 + er;
                int gm = m0 + rl;
                uint32_t w0 = sm_mb[rl * 4 + wn * 2];
                uint32_t w1 = sm_mb[rl * 4 + wn * 2 + 1];
                #pragma unroll
                for (int nf = 0; nf < 8; nf++) {
                    uint32_t word = (nf < 4) ? w0 : w1;
                    int sh = (nf & 3) * 8 + ec;
                    float m0f = ((word >> sh) & 1u) ? -1e9f : 0.0f;
                    float m1f = ((word >> (sh + 1)) & 1u) ? -1e9f : 0.0f;
                    float sv0 = acc[mf][nf][rr * 2]     * scale + m0f;
                    float sv1 = acc[mf][nf][rr * 2 + 1] * scale + m1f;
                    float2 pv;
                    pv.x = __expf(sv0 - rmax[mf][rr]) * rinv[mf][rr];
                    pv.y = __expf(sv1 - rmax[mf][rr]) * rinv[mf][rr];
                    int gn = nt * 128 + wn * 64 + nf * 8 + ec;
                    *(float2*)&attn[((size_t)bh * SEQ + gm) * SEQ + gn] = pv;
                    acc[mf][nf][rr * 2]     = pv.x;
                    acc[mf][nf][rr * 2 + 1] = pv.y;
                }
            }
        }

        #pragma unroll
        for (int kk = 0; kk < 4; kk++) {
            uint32_t pah[2][4], pal[2][4], bvh[4][4], bvl[4][4];
            #pragma unroll
            for (int mf = 0; mf < 2; mf++) {
                float* a0 = acc[mf][kk * 2];
                float* a1 = acc[mf][kk * 2 + 1];
                pah[mf][0] = pack_bf2(a0[0], a0[1]);
                pah[mf][1] = pack_bf2(a0[2], a0[3]);
                pah[mf][2] = pack_bf2(a1[0], a1[1]);
                pah[mf][3] = pack_bf2(a1[2], a1[3]);
                float h00 = __bfloat162float(__float2bfloat16_rn(a0[0]));
                float h01 = __bfloat162float(__float2bfloat16_rn(a0[1]));
                float h02 = __bfloat162float(__float2bfloat16_rn(a0[2]));
                float h03 = __bfloat162float(__float2bfloat16_rn(a0[3]));
                float h10 = __bfloat162float(__float2bfloat16_rn(a1[0]));
                float h11 = __bfloat162float(__float2bfloat16_rn(a1[1]));
                float h12 = __bfloat162float(__float2bfloat16_rn(a1[2]));
                float h13 = __bfloat162float(__float2bfloat16_rn(a1[3]));
                pal[mf][0] = pack_bf2(a0[0] - h00, a0[1] - h01);
                pal[mf][1] = pack_bf2(a0[2] - h02, a0[3] - h03);
                pal[mf][2] = pack_bf2(a1[0] - h10, a1[1] - h11);
                pal[mf][3] = pack_bf2(a1[2] - h12, a1[3] - h13);
            }
            #pragma unroll
            for (int nb = 0; nb < 4; nb++) {
                uint32_t off = SWZ((wn * 64 + kk * 16 + (l & 15)) * 128
                                   + (nb * 16 + (l >> 4) * 8) * 2);
                ldm_x4t(bvh[nb], kst + 32768 + off);
                ldm_x4t(bvl[nb], kst + 49152 + off);
            }
            #pragma unroll
            for (int mf = 0; mf < 2; mf++)
                #pragma unroll
                for (int nd = 0; nd < 8; nd++) {
                    mma_bf16(ctx[mf][nd], pah[mf], &bvh[nd >> 1][(nd & 1) * 2]);
                    mma_bf16(ctx[mf][nd], pal[mf], &bvh[nd >> 1][(nd & 1) * 2]);
                    mma_bf16(ctx[mf][nd], pah[mf], &bvl[nd >> 1][(nd & 1) * 2]);
                }
        }
        __syncthreads();
    }

    __syncthreads();
    float* red = (float*)(sm + O_KV);
    if (wn == 1) {
        #pragma unroll
        for (int mf = 0; mf < 2; mf++)
            #pragma unroll
            for (int nd = 0; nd < 8; nd++)
                #pragma unroll
                for (int rr = 0; rr < 2; rr++) {
                    int row = wm * 32 + mf * 16 + rr * 8 + er;
                    float2 v;
                    v.x = ctx[mf][nd][rr * 2];
                    v.y = ctx[mf][nd][rr * 2 + 1];
                    *(float2*)&red[row * 64 + nd * 8 + ec] = v;
                }
    }
    __syncthreads();
    if (wn == 0) {
        __nv_bfloat16* Chi = g_c_hi + (size_t)b * SEQ * DM + h * HD;
        __nv_bfloat16* Clo = g_c_lo + (size_t)b * SEQ * DM + h * HD;
        #pragma unroll
        for (int mf = 0; mf < 2; mf++)
            #pragma unroll
            for (int nd = 0; nd < 8; nd++)
                #pragma unroll
                for (int rr = 0; rr < 2; rr++) {
                    int row = wm * 32 + mf * 16 + rr * 8 + er;
                    int col = nd * 8 + ec;
                    float2 o = *(float2*)&red[row * 64 + col];
                    float vx = ctx[mf][nd][rr * 2] + o.x;
                    float vy = ctx[mf][nd][rr * 2 + 1] + o.y;
                    float hx = __bfloat162float(__float2bfloat16_rn(vx));
                    float hy = __bfloat162float(__float2bfloat16_rn(vy));
                    size_t off = (size_t)(m0 + row) * DM + col;
                    *(uint32_t*)&Chi[off] = pack_bf2(vx, vy);
                    *(uint32_t*)&Clo[off] = pack_bf2(vx - hx, vy - hy);
                }
    }
}

// ---------------------------------------------------------------------------
extern "C" void kernel_launch(void* const* d_in, const int* in_sizes, int n_in,
                              void* d_out, int out_size)
{
    const float* q   = (const float*)d_in[0];
    const float* k   = (const float*)d_in[1];
    const float* v   = (const float*)d_in[2];
    const int*  mask = (const int*)d_in[3];
    const float* Wq  = (const float*)d_in[4];
    const float* Wk  = (const float*)d_in[5];
    const float* Wv  = (const float*)d_in[6];
    const float* Wd  = (const float*)d_in[7];
    const float* bd  = (const float*)d_in[8];
    float* out = (float*)d_out;

    const long long out_elems  = (long long)BQ * SEQ * DM;
    const long long attn_elems = (long long)BQ * NH * SEQ * SEQ;
    float* attn;
    if ((long long)out_size >= out_elems + attn_elems) {
        attn = out + out_elems;
    } else {
        cudaGetSymbolAddress((void**)&attn, g_attn);
    }

    cudaFuncSetAttribute(qkv_gemm,   cudaFuncAttributeMaxDynamicSharedMemorySize, GEMM_SMEM);
    cudaFuncSetAttribute(out_gemm,   cudaFuncAttributeMaxDynamicSharedMemorySize, GEMM_SMEM);
    cudaFuncSetAttribute(attn_pass1, cudaFuncAttributeMaxDynamicSharedMemorySize, P1_SMEM);
    cudaFuncSetAttribute(attn_pass2, cudaFuncAttributeMaxDynamicSharedMemorySize, P2_SMEM);

    uint32_t* mb;
    cudaGetSymbolAddress((void**)&mb, g_mbits);

    // 12288 qkv-convert + 4096 w-convert + 512 mask blocks
    prep<<<16896, 256>>>(q, k, v, Wq, Wk, Wv, Wd, mask, mb);

    qkv_gemm<<<dim3(DM / 128, (BQ * SEQ) / 128, 3), 256, GEMM_SMEM>>>();

    dim3 ga(SEQ / 128, BQ * NH);
    attn_pass1<<<ga, 256, P1_SMEM>>>();
    attn_pass2<<<ga, 256, P2_SMEM>>>(attn);

    out_gemm<<<dim3(DM / 128, (BQ * SEQ) / 128), 256, GEMM_SMEM>>>(bd, out);
}

// round 10
// speedup vs baseline: 3.2389x; 1.0182x over previous
#include <cuda_runtime.h>
#include <cuda_bf16.h>
#include <stdint.h>
#include <math.h>

#define BQ  4
#define SEQ 1024
#define DM  1024
#define NH  16
#define HD  64

// ---------------- scratch (no allocations allowed) ----------------
__device__ float g_attn[BQ * NH * SEQ * SEQ];  // fallback if attn not an output
__device__ float g_rmax[BQ * NH * SEQ];
__device__ float g_rsum[BQ * NH * SEQ];
__device__ uint32_t g_mbits[BQ * SEQ * (SEQ / 32)];

__device__ __nv_bfloat16 g_q_hi[BQ * SEQ * DM],  g_q_lo[BQ * SEQ * DM];
__device__ __nv_bfloat16 g_k_hi[BQ * SEQ * DM],  g_k_lo[BQ * SEQ * DM];
__device__ __nv_bfloat16 g_v_hi[BQ * SEQ * DM],  g_v_lo[BQ * SEQ * DM];
__device__ __nv_bfloat16 g_qp_hi[BQ * SEQ * DM], g_qp_lo[BQ * SEQ * DM];
__device__ __nv_bfloat16 g_kp_hi[BQ * SEQ * DM], g_kp_lo[BQ * SEQ * DM];
__device__ __nv_bfloat16 g_vp_hi[BQ * SEQ * DM], g_vp_lo[BQ * SEQ * DM];
__device__ __nv_bfloat16 g_c_hi[BQ * SEQ * DM],  g_c_lo[BQ * SEQ * DM];
__device__ __nv_bfloat16 g_wq_hi[DM * DM], g_wq_lo[DM * DM];
__device__ __nv_bfloat16 g_wk_hi[DM * DM], g_wk_lo[DM * DM];
__device__ __nv_bfloat16 g_wv_hi[DM * DM], g_wv_lo[DM * DM];
__device__ __nv_bfloat16 g_wd_hi[DM * DM], g_wd_lo[DM * DM];

#define SWZ(o)   ((o) ^ (((o) >> 3) & 0x70))              // 128B rows
#define SWZ32(o) ((o) ^ ((((o) >> 7) & 3) << 4))          // 64B rows

__device__ __forceinline__ uint32_t smem_u32(const void* p) {
    uint32_t a;
    asm("{ .reg .u64 t; cvta.to.shared.u64 t, %1; cvt.u32.u64 %0, t; }" : "=r"(a) : "l"(p));
    return a;
}
__device__ __forceinline__ void ldm_x4(uint32_t* r, uint32_t addr) {
    asm volatile("ldmatrix.sync.aligned.m8n8.x4.shared.b16 {%0,%1,%2,%3}, [%4];"
        : "=r"(r[0]), "=r"(r[1]), "=r"(r[2]), "=r"(r[3]) : "r"(addr));
}
__device__ __forceinline__ void ldm_x4t(uint32_t* r, uint32_t addr) {
    asm volatile("ldmatrix.sync.aligned.m8n8.x4.trans.shared.b16 {%0,%1,%2,%3}, [%4];"
        : "=r"(r[0]), "=r"(r[1]), "=r"(r[2]), "=r"(r[3]) : "r"(addr));
}
__device__ __forceinline__ void mma_bf16(float* d, const uint32_t* a, const uint32_t* b) {
    asm volatile(
        "mma.sync.aligned.m16n8k16.row.col.f32.bf16.bf16.f32 "
        "{%0,%1,%2,%3}, {%4,%5,%6,%7}, {%8,%9}, {%0,%1,%2,%3};"
        : "+f"(d[0]), "+f"(d[1]), "+f"(d[2]), "+f"(d[3])
        : "r"(a[0]), "r"(a[1]), "r"(a[2]), "r"(a[3]), "r"(b[0]), "r"(b[1]));
}
#define CP16(dst, src) asm volatile("cp.async.cg.shared.global [%0], [%1], 16;" :: "r"(dst), "l"(src))
#define CP_COMMIT()    asm volatile("cp.async.commit_group;" ::: "memory")
#define CP_WAIT0()     asm volatile("cp.async.wait_group 0;" ::: "memory")
#define CP_WAIT1()     asm volatile("cp.async.wait_group 1;" ::: "memory")
#define CP_WAIT2()     asm volatile("cp.async.wait_group 2;" ::: "memory")

__device__ __forceinline__ uint32_t pack_bf2(float x, float y) {
    __nv_bfloat162 t(__float2bfloat16_rn(x), __float2bfloat16_rn(y));
    return *(uint32_t*)&t;
}

// ---------------------------------------------------------------------------
// prep: all converts + mask bit-packing in ONE launch.
// ---------------------------------------------------------------------------
__device__ __forceinline__ void split_store(
    const float* __restrict__ x, __nv_bfloat16* hi, __nv_bfloat16* lo, int i)
{
    float4 v = ((const float4*)x)[i];
    __nv_bfloat16 h0 = __float2bfloat16_rn(v.x);
    __nv_bfloat16 h1 = __float2bfloat16_rn(v.y);
    __nv_bfloat16 h2 = __float2bfloat16_rn(v.z);
    __nv_bfloat16 h3 = __float2bfloat16_rn(v.w);
    __nv_bfloat16 l0 = __float2bfloat16_rn(v.x - __bfloat162float(h0));
    __nv_bfloat16 l1 = __float2bfloat16_rn(v.y - __bfloat162float(h1));
    __nv_bfloat16 l2 = __float2bfloat16_rn(v.z - __bfloat162float(h2));
    __nv_bfloat16 l3 = __float2bfloat16_rn(v.w - __bfloat162float(h3));
    __nv_bfloat162* hp = (__nv_bfloat162*)(hi + (size_t)i * 4);
    __nv_bfloat162* lp = (__nv_bfloat162*)(lo + (size_t)i * 4);
    hp[0] = __nv_bfloat162(h0, h1); hp[1] = __nv_bfloat162(h2, h3);
    lp[0] = __nv_bfloat162(l0, l1); lp[1] = __nv_bfloat162(l2, l3);
}

__global__ __launch_bounds__(256) void prep(
    const float* __restrict__ q, const float* __restrict__ k,
    const float* __restrict__ v,
    const float* __restrict__ Wq, const float* __restrict__ Wk,
    const float* __restrict__ Wv, const float* __restrict__ Wd,
    const int* __restrict__ mask, uint32_t* __restrict__ bits)
{
    int bid = blockIdx.x;
    if (bid < 12288) {
        int z = bid >> 12;
        int i = (bid & 4095) * 256 + threadIdx.x;
        if (z == 0)      split_store(q, g_q_hi, g_q_lo, i);
        else if (z == 1) split_store(k, g_k_hi, g_k_lo, i);
        else             split_store(v, g_v_hi, g_v_lo, i);
    } else if (bid < 16384) {
        int r = bid - 12288;
        int z = r >> 10;
        int i = (r & 1023) * 256 + threadIdx.x;
        if (z == 0)      split_store(Wq, g_wq_hi, g_wq_lo, i);
        else if (z == 1) split_store(Wk, g_wk_hi, g_wk_lo, i);
        else if (z == 2) split_store(Wv, g_wv_hi, g_wv_lo, i);
        else             split_store(Wd, g_wd_hi, g_wd_lo, i);
    } else {
        int wdx = (bid - 16384) * 256 + threadIdx.x;
        const int* p = mask + (size_t)wdx * 32;
        uint32_t word = 0;
        #pragma unroll
        for (int j = 0; j < 8; j++) {
            int4 mv = ((const int4*)p)[j];
            word |= (mv.x ? 1u : 0u) << (j * 4 + 0);
            word |= (mv.y ? 1u : 0u) << (j * 4 + 1);
            word |= (mv.z ? 1u : 0u) << (j * 4 + 2);
            word |= (mv.w ? 1u : 0u) << (j * 4 + 3);
        }
        bits[wdx] = word;
    }
}

// ---------------------------------------------------------------------------
// GEMM body (unchanged from R9): BK=32, 3-stage cp.async, 2 CTAs/SM.
// ---------------------------------------------------------------------------
#define GEMM_SMEM (3 * 32768)

__device__ __forceinline__ void gemm_body(
    const __nv_bfloat16* __restrict__ Ahi, const __nv_bfloat16* __restrict__ Alo,
    const __nv_bfloat16* __restrict__ Whi, const __nv_bfloat16* __restrict__ Wlo,
    const float* __restrict__ bias, float* __restrict__ Cf32,
    __nv_bfloat16* __restrict__ Chi, __nv_bfloat16* __restrict__ Clo,
    char* sm)
{
    const int K = DM, N = DM;

    int tid = threadIdx.x, w = tid >> 5, l = tid & 31;
    int m0 = blockIdx.y * 128, n0 = blockIdx.x * 128;
    int wm = w & 1, wn = w >> 1;

    uint32_t sb = smem_u32(sm);

    int a_row = wm * 64 + (l & 15);
    int a_cb  = (l >> 4) * 16;
    int b_row = wn * 32 + (l & 7) + ((l >> 4) * 8);
    int b_cb  = ((l >> 3) & 1) * 16;

    float acc[4][4][4] = {};
    const int NK = K / 32;

    auto load_stage = [&](int s, int kc) {
        uint32_t base = sb + (uint32_t)s * 32768;
        #pragma unroll
        for (int it = 0; it < 2; it++) {
            int idx = tid + it * 256;
            int row = idx >> 2, c = idx & 3;
            size_t ga = (size_t)(m0 + row) * K + kc * 32 + c * 8;
            size_t gw = (size_t)(n0 + row) * K + kc * 32 + c * 8;
            uint32_t so = SWZ32(row * 64 + c * 16);
            CP16(base +     0 + so, Ahi + ga);
            CP16(base +  8192 + so, Alo + ga);
            CP16(base + 16384 + so, Whi + gw);
            CP16(base + 24576 + so, Wlo + gw);
        }
        CP_COMMIT();
    };

    load_stage(0, 0);
    load_stage(1, 1);

    for (int kc = 0; kc < NK; kc++) {
        __syncthreads();
        if (kc + 2 < NK) { load_stage((kc + 2) % 3, kc + 2); CP_WAIT2(); }
        else if (kc + 1 < NK) { CP_WAIT1(); }
        else { CP_WAIT0(); }
        __syncthreads();

        uint32_t st = sb + (uint32_t)(kc % 3) * 32768;
        #pragma unroll
        for (int kk = 0; kk < 2; kk++) {
            int ks2 = kk * 32;
            uint32_t ah[4][4], al[4][4], bw[2][4];
            #pragma unroll
            for (int mf = 0; mf < 4; mf++) {
                uint32_t off = SWZ32((a_row + mf * 16) * 64 + ks2 + a_cb);
                ldm_x4(ah[mf], st + 0 + off);
                ldm_x4(al[mf], st + 8192 + off);
            }
            #pragma unroll
            for (int bp = 0; bp < 2; bp++) {
                uint32_t off = SWZ32((b_row + bp * 16) * 64 + ks2 + b_cb);
                ldm_x4(bw[bp], st + 16384 + off);
            }
            #pragma unroll
            for (int mf = 0; mf < 4; mf++)
                #pragma unroll
                for (int nf = 0; nf < 4; nf++)
                    mma_bf16(acc[mf][nf], ah[mf], &bw[nf >> 1][(nf & 1) * 2]);
            #pragma unroll
            for (int mf = 0; mf < 4; mf++)
                #pragma unroll
                for (int nf = 0; nf < 4; nf++)
                    mma_bf16(acc[mf][nf], al[mf], &bw[nf >> 1][(nf & 1) * 2]);
            #pragma unroll
            for (int bp = 0; bp < 2; bp++) {
                uint32_t off = SWZ32((b_row + bp * 16) * 64 + ks2 + b_cb);
                ldm_x4(bw[bp], st + 24576 + off);
            }
            #pragma unroll
            for (int mf = 0; mf < 4; mf++)
                #pragma unroll
                for (int nf = 0; nf < 4; nf++)
                    mma_bf16(acc[mf][nf], ah[mf], &bw[nf >> 1][(nf & 1) * 2]);
        }
    }

    int er = l >> 2, ec = (l & 3) * 2;
    #pragma unroll
    for (int mf = 0; mf < 4; mf++) {
        #pragma unroll
        for (int nf = 0; nf < 4; nf++) {
            int gm = m0 + wm * 64 + mf * 16 + er;
            int gn = n0 + wn * 32 + nf * 8 + ec;
            if (Cf32) {
                float b0 = bias ? bias[gn] : 0.0f;
                float b1 = bias ? bias[gn + 1] : 0.0f;
                float2 v0, v1;
                v0.x = acc[mf][nf][0] + b0; v0.y = acc[mf][nf][1] + b1;
                v1.x = acc[mf][nf][2] + b0; v1.y = acc[mf][nf][3] + b1;
                *(float2*)&Cf32[(size_t)gm * N + gn]       = v0;
                *(float2*)&Cf32[(size_t)(gm + 8) * N + gn] = v1;
            } else {
                #pragma unroll
                for (int rr = 0; rr < 2; rr++) {
                    float vx = acc[mf][nf][rr * 2], vy = acc[mf][nf][rr * 2 + 1];
                    float hx = __bfloat162float(__float2bfloat16_rn(vx));
                    float hy = __bfloat162float(__float2bfloat16_rn(vy));
                    size_t o = (size_t)(gm + rr * 8) * N + gn;
                    *(uint32_t*)&Chi[o] = pack_bf2(vx, vy);
                    *(uint32_t*)&Clo[o] = pack_bf2(vx - hx, vy - hy);
                }
            }
        }
    }
}

__global__ __launch_bounds__(256, 2) void qkv_gemm()
{
    extern __shared__ char sm[];
    int z = blockIdx.z;
    if (z == 0)
        gemm_body(g_q_hi, g_q_lo, g_wq_hi, g_wq_lo, nullptr, nullptr, g_qp_hi, g_qp_lo, sm);
    else if (z == 1)
        gemm_body(g_k_hi, g_k_lo, g_wk_hi, g_wk_lo, nullptr, nullptr, g_kp_hi, g_kp_lo, sm);
    else
        gemm_body(g_v_hi, g_v_lo, g_wv_hi, g_wv_lo, nullptr, nullptr, g_vp_hi, g_vp_lo, sm);
}

__global__ __launch_bounds__(256, 2) void out_gemm(const float* __restrict__ bias,
                                                   float* __restrict__ out)
{
    extern __shared__ char sm[];
    gemm_body(g_c_hi, g_c_lo, g_wd_hi, g_wd_lo, bias, out, nullptr, nullptr, sm);
}

// ---------------------------------------------------------------------------
// Fused attention, pass 1: 512 threads / 16 warps, warp tile 16 rows x 64 keys.
// wm = w&7 (16-row group), wn = w>>3 (64-key half). 2-stage cp.async K tiles.
// ---------------------------------------------------------------------------
#define P1_SMEM (32768 + 65536 + 4096 + 2048)

__global__ __launch_bounds__(512) void attn_pass1()
{
    extern __shared__ char sm[];
    const uint32_t O_Q = 0, O_KS = 32768, O_MB = 98304, O_MS = 102400;

    int tid = threadIdx.x, w = tid >> 5, l = tid & 31;
    int bh = blockIdx.y, b = bh >> 4, h = bh & 15;
    int m0 = blockIdx.x * 128;
    int wm = w & 7, wn = w >> 3;
    uint32_t sb = smem_u32(sm);
    float* sm_m = (float*)(sm + O_MS);
    float* sm_s = sm_m + 256;

    const __nv_bfloat16* Qh = g_qp_hi + (size_t)b * SEQ * DM + h * HD;
    const __nv_bfloat16* Ql = g_qp_lo + (size_t)b * SEQ * DM + h * HD;
    const __nv_bfloat16* Kh = g_kp_hi + (size_t)b * SEQ * DM + h * HD;
    const __nv_bfloat16* Kl = g_kp_lo + (size_t)b * SEQ * DM + h * HD;

    auto load_k = [&](int nt) {
        uint32_t base = sb + O_KS + (uint32_t)(nt & 1) * 32768;
        #pragma unroll
        for (int it = 0; it < 2; it++) {
            int idx = tid + it * 512;
            int row = idx >> 3, c = idx & 7;
            uint32_t so = SWZ(row * 128 + c * 16);
            size_t g = (size_t)(nt * 128 + row) * DM + c * 8;
            CP16(base + so, Kh + g);
            CP16(base + 16384 + so, Kl + g);
        }
        if (tid < 128)
            CP16(sb + O_MB + (uint32_t)(nt & 1) * 2048 + tid * 16,
                 &g_mbits[((size_t)b * SEQ + m0 + tid) * 32 + nt * 4]);
        CP_COMMIT();
    };

    #pragma unroll
    for (int it = 0; it < 2; it++) {
        int idx = tid + it * 512;
        int row = idx >> 3, c = idx & 7;
        uint32_t so = SWZ(row * 128 + c * 16);
        size_t g = (size_t)(m0 + row) * DM + c * 8;
        *(uint4*)(sm + O_Q + so)         = *(const uint4*)(Qh + g);
        *(uint4*)(sm + O_Q + 16384 + so) = *(const uint4*)(Ql + g);
    }
    load_k(0);

    float mrun[2] = {-1e30f, -1e30f};
    float srun[2] = {};
    const float scale = 0.03125f;
    int er = l >> 2, ec = (l & 3) * 2;

    for (int nt = 0; nt < 8; nt++) {
        if (nt + 1 < 8) { load_k(nt + 1); CP_WAIT1(); }
        else            { CP_WAIT0(); }
        __syncthreads();

        uint32_t kst = sb + O_KS + (uint32_t)(nt & 1) * 32768;
        uint32_t* sm_mb = (uint32_t*)(sm + O_MB + (size_t)(nt & 1) * 2048);

        float acc[8][4] = {};
        #pragma unroll
        for (int kk = 0; kk < 4; kk++) {
            int ks2 = kk * 32;
            uint32_t ah[4], al[4], bwh[4][4], bwl[4][4];
            {
                uint32_t off = SWZ((wm * 16 + (l & 15)) * 128 + ks2 + (l >> 4) * 16);
                ldm_x4(ah, sb + O_Q + off);
                ldm_x4(al, sb + O_Q + 16384 + off);
            }
            #pragma unroll
            for (int bp = 0; bp < 4; bp++) {
                uint32_t off = SWZ((wn * 64 + bp * 16 + (l & 7) + ((l >> 4) * 8)) * 128
                                   + ks2 + ((l >> 3) & 1) * 16);
                ldm_x4(bwh[bp], kst + off);
                ldm_x4(bwl[bp], kst + 16384 + off);
            }
            #pragma unroll
            for (int nf = 0; nf < 8; nf++) {
                mma_bf16(acc[nf], ah, &bwh[nf >> 1][(nf & 1) * 2]);
                mma_bf16(acc[nf], al, &bwh[nf >> 1][(nf & 1) * 2]);
                mma_bf16(acc[nf], ah, &bwl[nf >> 1][(nf & 1) * 2]);
            }
        }

        #pragma unroll
        for (int rr = 0; rr < 2; rr++) {
            int rl = wm * 16 + rr * 8 + er;
            uint32_t w0 = sm_mb[rl * 4 + wn * 2];
            uint32_t w1 = sm_mb[rl * 4 + wn * 2 + 1];
            float v[16];
            float tmax = -1e30f;
            #pragma unroll
            for (int nf = 0; nf < 8; nf++) {
                uint32_t word = (nf < 4) ? w0 : w1;
                int sh = (nf & 3) * 8 + ec;
                float m0f = ((word >> sh) & 1u) ? -1e9f : 0.0f;
                float m1f = ((word >> (sh + 1)) & 1u) ? -1e9f : 0.0f;
                v[nf * 2]     = acc[nf][rr * 2]     * scale + m0f;
                v[nf * 2 + 1] = acc[nf][rr * 2 + 1] * scale + m1f;
                tmax = fmaxf(tmax, fmaxf(v[nf * 2], v[nf * 2 + 1]));
            }
            tmax = fmaxf(tmax, __shfl_xor_sync(0xffffffffu, tmax, 1));
            tmax = fmaxf(tmax, __shfl_xor_sync(0xffffffffu, tmax, 2));
            float nm = fmaxf(mrun[rr], tmax);
            float ts = 0.0f;
            #pragma unroll
            for (int i = 0; i < 16; i++) ts += __expf(v[i] - nm);
            ts += __shfl_xor_sync(0xffffffffu, ts, 1);
            ts += __shfl_xor_sync(0xffffffffu, ts, 2);
            srun[rr] = srun[rr] * __expf(mrun[rr] - nm) + ts;
            mrun[rr] = nm;
        }
        __syncthreads();
    }

    if ((l & 3) == 0) {
        #pragma unroll
        for (int rr = 0; rr < 2; rr++) {
            int rl = wm * 16 + rr * 8 + er;
            sm_m[wn * 128 + rl] = mrun[rr];
            sm_s[wn * 128 + rl] = srun[rr];
        }
    }
    __syncthreads();
    if (tid < 128) {
        float ma = sm_m[tid], mb2 = sm_m[128 + tid];
        float m = fmaxf(ma, mb2);
        float s = sm_s[tid] * __expf(ma - m) + sm_s[128 + tid] * __expf(mb2 - m);
        g_rmax[(size_t)bh * SEQ + m0 + tid] = m;
        g_rsum[(size_t)bh * SEQ + m0 + tid] = s;
    }
}

// ---------------------------------------------------------------------------
// Fused attention, pass 2: 512 threads / 16 warps, warp tile 16 rows.
// Recompute S, write normalized attn, ctx = P@V in registers.
// ---------------------------------------------------------------------------
#define P2_SMEM (32768 + 131072 + 4096)

__global__ __launch_bounds__(512) void attn_pass2(float* __restrict__ attn)
{
    extern __shared__ char sm[];
    const uint32_t O_Q = 0, O_KV = 32768, O_MB = 163840;

    int tid = threadIdx.x, w = tid >> 5, l = tid & 31;
    int bh = blockIdx.y, b = bh >> 4, h = bh & 15;
    int m0 = blockIdx.x * 128;
    int wm = w & 7, wn = w >> 3;
    uint32_t sb = smem_u32(sm);

    const __nv_bfloat16* Qh = g_qp_hi + (size_t)b * SEQ * DM + h * HD;
    const __nv_bfloat16* Ql = g_qp_lo + (size_t)b * SEQ * DM + h * HD;
    const __nv_bfloat16* Kh = g_kp_hi + (size_t)b * SEQ * DM + h * HD;
    const __nv_bfloat16* Kl = g_kp_lo + (size_t)b * SEQ * DM + h * HD;
    const __nv_bfloat16* Vh = g_vp_hi + (size_t)b * SEQ * DM + h * HD;
    const __nv_bfloat16* Vl = g_vp_lo + (size_t)b * SEQ * DM + h * HD;

    auto load_kv = [&](int nt) {
        uint32_t base = sb + O_KV + (uint32_t)(nt & 1) * 65536;
        #pragma unroll
        for (int it = 0; it < 2; it++) {
            int idx = tid + it * 512;
            int row = idx >> 3, c = idx & 7;
            uint32_t so = SWZ(row * 128 + c * 16);
            size_t g = (size_t)(nt * 128 + row) * DM + c * 8;
            CP16(base + so,         Kh + g);
            CP16(base + 16384 + so, Kl + g);
            CP16(base + 32768 + so, Vh + g);
            CP16(base + 49152 + so, Vl + g);
        }
        if (tid < 128)
            CP16(sb + O_MB + (uint32_t)(nt & 1) * 2048 + tid * 16,
                 &g_mbits[((size_t)b * SEQ + m0 + tid) * 32 + nt * 4]);
        CP_COMMIT();
    };

    #pragma unroll
    for (int it = 0; it < 2; it++) {
        int idx = tid + it * 512;
        int row = idx >> 3, c = idx & 7;
        uint32_t so = SWZ(row * 128 + c * 16);
        size_t g = (size_t)(m0 + row) * DM + c * 8;
        *(uint4*)(sm + O_Q + so)         = *(const uint4*)(Qh + g);
        *(uint4*)(sm + O_Q + 16384 + so) = *(const uint4*)(Ql + g);
    }
    load_kv(0);

    int er = l >> 2, ec = (l & 3) * 2;
    const float scale = 0.03125f;

    float rmax[2], rinv[2];
    #pragma unroll
    for (int rr = 0; rr < 2; rr++) {
        int gm = m0 + wm * 16 + rr * 8 + er;
        rmax[rr] = g_rmax[(size_t)bh * SEQ + gm];
        rinv[rr] = __frcp_rn(g_rsum[(size_t)bh * SEQ + gm]);
    }

    float ctx[8][4] = {};

    for (int nt = 0; nt < 8; nt++) {
        if (nt + 1 < 8) { load_kv(nt + 1); CP_WAIT1(); }
        else            { CP_WAIT0(); }
        __syncthreads();

        uint32_t kst = sb + O_KV + (uint32_t)(nt & 1) * 65536;
        uint32_t* sm_mb = (uint32_t*)(sm + O_MB + (size_t)(nt & 1) * 2048);

        float acc[8][4] = {};
        #pragma unroll
        for (int kk = 0; kk < 4; kk++) {
            int ks2 = kk * 32;
            uint32_t ah[4], al[4], bwh[4][4], bwl[4][4];
            {
                uint32_t off = SWZ((wm * 16 + (l & 15)) * 128 + ks2 + (l >> 4) * 16);
                ldm_x4(ah, sb + O_Q + off);
                ldm_x4(al, sb + O_Q + 16384 + off);
            }
            #pragma unroll
            for (int bp = 0; bp < 4; bp++) {
                uint32_t off = SWZ((wn * 64 + bp * 16 + (l & 7) + ((l >> 4) * 8)) * 128
                                   + ks2 + ((l >> 3) & 1) * 16);
                ldm_x4(bwh[bp], kst + off);
                ldm_x4(bwl[bp], kst + 16384 + off);
            }
            #pragma unroll
            for (int nf = 0; nf < 8; nf++) {
                mma_bf16(acc[nf], ah, &bwh[nf >> 1][(nf & 1) * 2]);
                mma_bf16(acc[nf], al, &bwh[nf >> 1][(nf & 1) * 2]);
                mma_bf16(acc[nf], ah, &bwl[nf >> 1][(nf & 1) * 2]);
            }
        }

        // P = exp(s - m) * rinv; write attn; keep P in acc
        #pragma unroll
        for (int rr = 0; rr < 2; rr++) {
            int rl = wm * 16 + rr * 8 + er;
            int gm = m0 + rl;
            uint32_t w0 = sm_mb[rl * 4 + wn * 2];
            uint32_t w1 = sm_mb[rl * 4 + wn * 2 + 1];
            #pragma unroll
            for (int nf = 0; nf < 8; nf++) {
                uint32_t word = (nf < 4) ? w0 : w1;
                int sh = (nf & 3) * 8 + ec;
                float m0f = ((word >> sh) & 1u) ? -1e9f : 0.0f;
                float m1f = ((word >> (sh + 1)) & 1u) ? -1e9f : 0.0f;
                float sv0 = acc[nf][rr * 2]     * scale + m0f;
                float sv1 = acc[nf][rr * 2 + 1] * scale + m1f;
                float2 pv;
                pv.x = __expf(sv0 - rmax[rr]) * rinv[rr];
                pv.y = __expf(sv1 - rmax[rr]) * rinv[rr];
                int gn = nt * 128 + wn * 64 + nf * 8 + ec;
                *(float2*)&attn[((size_t)bh * SEQ + gm) * SEQ + gn] = pv;
                acc[nf][rr * 2]     = pv.x;
                acc[nf][rr * 2 + 1] = pv.y;
            }
        }

        // ctx += P @ V
        #pragma unroll
        for (int kk = 0; kk < 4; kk++) {
            uint32_t pah[4], pal[4], bvh[4][4], bvl[4][4];
            {
                float* a0 = acc[kk * 2];
                float* a1 = acc[kk * 2 + 1];
                pah[0] = pack_bf2(a0[0], a0[1]);
                pah[1] = pack_bf2(a0[2], a0[3]);
                pah[2] = pack_bf2(a1[0], a1[1]);
                pah[3] = pack_bf2(a1[2], a1[3]);
                float h00 = __bfloat162float(__float2bfloat16_rn(a0[0]));
                float h01 = __bfloat162float(__float2bfloat16_rn(a0[1]));
                float h02 = __bfloat162float(__float2bfloat16_rn(a0[2]));
                float h03 = __bfloat162float(__float2bfloat16_rn(a0[3]));
                float h10 = __bfloat162float(__float2bfloat16_rn(a1[0]));
                float h11 = __bfloat162float(__float2bfloat16_rn(a1[1]));
                float h12 = __bfloat162float(__float2bfloat16_rn(a1[2]));
                float h13 = __bfloat162float(__float2bfloat16_rn(a1[3]));
                pal[0] = pack_bf2(a0[0] - h00, a0[1] - h01);
                pal[1] = pack_bf2(a0[2] - h02, a0[3] - h03);
                pal[2] = pack_bf2(a1[0] - h10, a1[1] - h11);
                pal[3] = pack_bf2(a1[2] - h12, a1[3] - h13);
            }
            #pragma unroll
            for (int nb = 0; nb < 4; nb++) {
                uint32_t off = SWZ((wn * 64 + kk * 16 + (l & 15)) * 128
                                   + (nb * 16 + (l >> 4) * 8) * 2);
                ldm_x4t(bvh[nb], kst + 32768 + off);
                ldm_x4t(bvl[nb], kst + 49152 + off);
            }
            #pragma unroll
            for (int nd = 0; nd < 8; nd++) {
                mma_bf16(ctx[nd], pah, &bvh[nd >> 1][(nd & 1) * 2]);
                mma_bf16(ctx[nd], pal, &bvh[nd >> 1][(nd & 1) * 2]);
                mma_bf16(ctx[nd], pah, &bvl[nd >> 1][(nd & 1) * 2]);
            }
        }
        __syncthreads();
    }

    // cross-wn reduce via smem (alias KV stage 0), write ctx bf16 hi/lo
    __syncthreads();
    float* red = (float*)(sm + O_KV);   // 128 x 64 fp32 = 32KB
    if (wn == 1) {
        #pragma unroll
        for (int nd = 0; nd < 8; nd++)
            #pragma unroll
            for (int rr = 0; rr < 2; rr++) {
                int row = wm * 16 + rr * 8 + er;
                float2 v;
                v.x = ctx[nd][rr * 2];
                v.y = ctx[nd][rr * 2 + 1];
                *(float2*)&red[row * 64 + nd * 8 + ec] = v;
            }
    }
    __syncthreads();
    if (wn == 0) {
        __nv_bfloat16* Chi = g_c_hi + (size_t)b * SEQ * DM + h * HD;
        __nv_bfloat16* Clo = g_c_lo + (size_t)b * SEQ * DM + h * HD;
        #pragma unroll
        for (int nd = 0; nd < 8; nd++)
            #pragma unroll
            for (int rr = 0; rr < 2; rr++) {
                int row = wm * 16 + rr * 8 + er;
                int col = nd * 8 + ec;
                float2 o = *(float2*)&red[row * 64 + col];
                float vx = ctx[nd][rr * 2] + o.x;
                float vy = ctx[nd][rr * 2 + 1] + o.y;
                float hx = __bfloat162float(__float2bfloat16_rn(vx));
                float hy = __bfloat162float(__float2bfloat16_rn(vy));
                size_t off = (size_t)(m0 + row) * DM + col;
                *(uint32_t*)&Chi[off] = pack_bf2(vx, vy);
                *(uint32_t*)&Clo[off] = pack_bf2(vx - hx, vy - hy);
            }
    }
}

// ---------------------------------------------------------------------------
extern "C" void kernel_launch(void* const* d_in, const int* in_sizes, int n_in,
                              void* d_out, int out_size)
{
    const float* q   = (const float*)d_in[0];
    const float* k   = (const float*)d_in[1];
    const float* v   = (const float*)d_in[2];
    const int*  mask = (const int*)d_in[3];
    const float* Wq  = (const float*)d_in[4];
    const float* Wk  = (const float*)d_in[5];
    const float* Wv  = (const float*)d_in[6];
    const float* Wd  = (const float*)d_in[7];
    const float* bd  = (const float*)d_in[8];
    float* out = (float*)d_out;

    const long long out_elems  = (long long)BQ * SEQ * DM;
    const long long attn_elems = (long long)BQ * NH * SEQ * SEQ;
    float* attn;
    if ((long long)out_size >= out_elems + attn_elems) {
        attn = out + out_elems;
    } else {
        cudaGetSymbolAddress((void**)&attn, g_attn);
    }

    cudaFuncSetAttribute(qkv_gemm,   cudaFuncAttributeMaxDynamicSharedMemorySize, GEMM_SMEM);
    cudaFuncSetAttribute(out_gemm,   cudaFuncAttributeMaxDynamicSharedMemorySize, GEMM_SMEM);
    cudaFuncSetAttribute(attn_pass1, cudaFuncAttributeMaxDynamicSharedMemorySize, P1_SMEM);
    cudaFuncSetAttribute(attn_pass2, cudaFuncAttributeMaxDynamicSharedMemorySize, P2_SMEM);

    uint32_t* mb;
    cudaGetSymbolAddress((void**)&mb, g_mbits);

    prep<<<16896, 256>>>(q, k, v, Wq, Wk, Wv, Wd, mask, mb);

    qkv_gemm<<<dim3(DM / 128, (BQ * SEQ) / 128, 3), 256, GEMM_SMEM>>>();

    dim3 ga(SEQ / 128, BQ * NH);
    attn_pass1<<<ga, 512, P1_SMEM>>>();
    attn_pass2<<<ga, 512, P2_SMEM>>>(attn);

    out_gemm<<<dim3(DM / 128, (BQ * SEQ) / 128), 256, GEMM_SMEM>>>(bd, out);
}